// round 1
// baseline (speedup 1.0000x reference)
#include <cuda_runtime.h>

// ---------------------------------------------------------------------------
// Problem constants
// ---------------------------------------------------------------------------
constexpr int SEQ    = 2048;
constexpr int HIDN   = 2560;
constexpr int NHEAD  = 40;
constexpr int NOPE_D = 64;
constexpr int ROPE_D = 32;
constexpr int QK_D   = NOPE_D + ROPE_D;    // 96
constexpr int V_D    = 64;
constexpr int Q_RANK = 768;
constexpr int KV_RANK= 256;
constexpr int CKV_D  = KV_RANK + ROPE_D;   // 288
constexpr int KV_D   = NOPE_D + V_D;       // 128 per head
constexpr int NTOK   = 2 * SEQ;            // 4096
constexpr float SCALE = 0.10206207261596577f; // 96^-0.5

// ---------------------------------------------------------------------------
// Scratch (static device allocations — allowed; cudaMalloc is not)
// ---------------------------------------------------------------------------
__device__ float g_qa  [NTOK * Q_RANK];           // 12.6 MB
__device__ float g_q   [NTOK * NHEAD * QK_D];     // 62.9 MB
__device__ float g_ckv [NTOK * CKV_D];            //  4.7 MB
__device__ float g_kvn [NTOK * KV_RANK];          //  4.2 MB
__device__ float g_kv  [NTOK * NHEAD * KV_D];     // 83.9 MB
__device__ float g_krot[NTOK * ROPE_D];           //  0.5 MB
__device__ float g_attn[NTOK * NHEAD * V_D];      // 41.9 MB

// ---------------------------------------------------------------------------
// SGEMM: C[M,N] = A[M,K] @ B[K,N], row-major fp32.
// BM=BN=128, BK=16, 256 threads, 8x8 micro-tile. M%128==0, K%16==0 assumed.
// N may be any multiple of 4 (bounds-checked).
// ---------------------------------------------------------------------------
__global__ __launch_bounds__(256, 2)
void sgemm_kernel(const float* __restrict__ A, const float* __restrict__ B,
                  float* __restrict__ C, int M, int N, int K)
{
    __shared__ float As[16][132];   // transposed A tile, padded
    __shared__ float Bs[16][128];

    const int tid = threadIdx.x;
    const int tx  = tid & 15;        // 0..15 -> 8 cols each
    const int ty  = tid >> 4;        // 0..15 -> 8 rows each
    const int row0 = blockIdx.y * 128;
    const int col0 = blockIdx.x * 128;

    // load mapping
    const int a_r = tid >> 2;               // 0..63
    const int a_c = (tid & 3) << 2;         // 0,4,8,12
    const int b_r = tid >> 5;               // 0..7
    const int b_c = (tid & 31) << 2;        // 0..124
    const bool bp = (col0 + b_c) < N;

    float acc[8][8];
#pragma unroll
    for (int i = 0; i < 8; i++)
#pragma unroll
        for (int j = 0; j < 8; j++) acc[i][j] = 0.f;

    for (int k0 = 0; k0 < K; k0 += 16) {
        float4 a0 = *(const float4*)&A[(size_t)(row0 + a_r)      * K + k0 + a_c];
        float4 a1 = *(const float4*)&A[(size_t)(row0 + a_r + 64) * K + k0 + a_c];
        float4 b0 = make_float4(0.f, 0.f, 0.f, 0.f);
        float4 b1 = make_float4(0.f, 0.f, 0.f, 0.f);
        if (bp) {
            b0 = *(const float4*)&B[(size_t)(k0 + b_r)     * N + col0 + b_c];
            b1 = *(const float4*)&B[(size_t)(k0 + b_r + 8) * N + col0 + b_c];
        }
        As[a_c + 0][a_r] = a0.x; As[a_c + 1][a_r] = a0.y;
        As[a_c + 2][a_r] = a0.z; As[a_c + 3][a_r] = a0.w;
        As[a_c + 0][a_r + 64] = a1.x; As[a_c + 1][a_r + 64] = a1.y;
        As[a_c + 2][a_r + 64] = a1.z; As[a_c + 3][a_r + 64] = a1.w;
        *(float4*)&Bs[b_r][b_c]     = b0;
        *(float4*)&Bs[b_r + 8][b_c] = b1;
        __syncthreads();

#pragma unroll
        for (int kk = 0; kk < 16; kk++) {
            float a[8], b[8];
            *(float4*)&a[0] = *(float4*)&As[kk][ty * 8];
            *(float4*)&a[4] = *(float4*)&As[kk][ty * 8 + 4];
            *(float4*)&b[0] = *(float4*)&Bs[kk][tx * 8];
            *(float4*)&b[4] = *(float4*)&Bs[kk][tx * 8 + 4];
#pragma unroll
            for (int i = 0; i < 8; i++)
#pragma unroll
                for (int j = 0; j < 8; j++)
                    acc[i][j] = fmaf(a[i], b[j], acc[i][j]);
        }
        __syncthreads();
    }

#pragma unroll
    for (int i = 0; i < 8; i++) {
        const int r = row0 + ty * 8 + i;
#pragma unroll
        for (int j = 0; j < 8; j += 4) {
            const int c = col0 + tx * 8 + j;
            if (c < N)
                *(float4*)&C[(size_t)r * N + c] =
                    make_float4(acc[i][j], acc[i][j+1], acc[i][j+2], acc[i][j+3]);
        }
    }
}

// ---------------------------------------------------------------------------
// RMSNorm: one block per row.
// ---------------------------------------------------------------------------
__global__ void rmsnorm_kernel(const float* __restrict__ in, const float* __restrict__ w,
                               float* __restrict__ out, int dim, int istride, int ostride)
{
    const int row = blockIdx.x;
    const float* x = in + (size_t)row * istride;
    float ss = 0.f;
    for (int i = threadIdx.x; i < dim; i += blockDim.x) { float v = x[i]; ss += v * v; }
#pragma unroll
    for (int o = 16; o > 0; o >>= 1) ss += __shfl_xor_sync(0xffffffffu, ss, o);
    __shared__ float sh[8];
    __shared__ float s_inv;
    const int w32 = threadIdx.x >> 5;
    if ((threadIdx.x & 31) == 0) sh[w32] = ss;
    __syncthreads();
    if (threadIdx.x == 0) {
        float t = 0.f;
        const int nw = blockDim.x >> 5;
        for (int i = 0; i < nw; i++) t += sh[i];
        s_inv = rsqrtf(t / (float)dim + 1e-5f);
    }
    __syncthreads();
    const float inv = s_inv;
    for (int i = threadIdx.x; i < dim; i += blockDim.x)
        out[(size_t)row * ostride + i] = x[i] * inv * w[i];
}

// ---------------------------------------------------------------------------
// RoPE: per-token, rotates q (in-place, 40 heads) and k_rot (ckv tail -> krot)
// ---------------------------------------------------------------------------
__global__ void rope_kernel(float* __restrict__ q, const float* __restrict__ ckv,
                            float* __restrict__ krot,
                            const float* __restrict__ cosb, const float* __restrict__ sinb)
{
    const int token = blockIdx.x;
    const int s = token & (SEQ - 1);
    for (int i = threadIdx.x; i < (NHEAD + 1) * 32; i += blockDim.x) {
        const int h = i >> 5;
        const int d = i & 31;
        const float c  = cosb[s * ROPE_D + d];
        const float sn = sinb[s * ROPE_D + d];
        if (h < NHEAD) {
            float* base = q + (size_t)token * (NHEAD * QK_D) + h * QK_D + NOPE_D;
            const float x  = base[d];
            const float pr = (d < 16) ? -base[d + 16] : base[d - 16];
            __syncwarp();
            base[d] = x * c + pr * sn;
        } else {
            const float* kb = ckv + (size_t)token * CKV_D + KV_RANK;
            const float x  = kb[d];
            const float pr = (d < 16) ? -kb[d + 16] : kb[d - 16];
            krot[(size_t)token * ROPE_D + d] = x * c + pr * sn;
        }
    }
}

// ---------------------------------------------------------------------------
// Flash attention (fp32, causal). grid = (SEQ/64, B*NHEAD), 256 threads.
// BQ=BK=64. Q/K stored transposed [d][row] in smem, P transposed [kcol][qrow],
// so compute loads are all float4.
// ---------------------------------------------------------------------------
constexpr int AP = 68;   // padded row length (multiple of 4)
constexpr int ATTN_SMEM = (QK_D * AP * 2 + 64 * AP * 2) * (int)sizeof(float); // 87040 B

__global__ __launch_bounds__(256, 2)
void attn_kernel(const float* __restrict__ q, const float* __restrict__ kv,
                 const float* __restrict__ krot, float* __restrict__ out)
{
    extern __shared__ float sm[];
    float* Qs = sm;                  // [QK_D][AP]
    float* Ks = Qs + QK_D * AP;      // [QK_D][AP]
    float* Vs = Ks + QK_D * AP;      // [64][AP]
    float* Ps = Vs + 64 * AP;        // [64][AP]

    const int bh = blockIdx.y;
    const int b  = bh / NHEAD;
    const int h  = bh % NHEAD;
    const int qt = blockIdx.x;
    const int q0 = qt * 64;
    const int tid = threadIdx.x;
    const int tx  = tid & 15;   // 4 value-cols / k-cols
    const int ty  = tid >> 4;   // 4 q-rows
    const size_t tok0 = (size_t)b * SEQ;

    // load Q tile transposed
    for (int i = tid; i < 64 * QK_D; i += 256) {
        const int r = i / QK_D, d = i - r * QK_D;
        Qs[d * AP + r] = q[(tok0 + q0 + r) * (NHEAD * QK_D) + h * QK_D + d];
    }

    float m[4], l[4], acc[4][4];
#pragma unroll
    for (int i = 0; i < 4; i++) {
        m[i] = -1e30f; l[i] = 0.f;
#pragma unroll
        for (int j = 0; j < 4; j++) acc[i][j] = 0.f;
    }

    for (int kt = 0; kt <= qt; kt++) {
        const int k0 = kt * 64;
        __syncthreads();   // Q visible (iter 0) / previous PV done before K,V overwrite
        for (int i = tid; i < 64 * QK_D; i += 256) {
            const int r = i / QK_D, d = i - r * QK_D;
            const float v = (d < 64)
                ? kv[(tok0 + k0 + r) * (NHEAD * KV_D) + h * KV_D + d]
                : krot[(tok0 + k0 + r) * ROPE_D + (d - 64)];
            Ks[d * AP + r] = v;
        }
        for (int i = tid; i < 64 * 64; i += 256) {
            const int r = i >> 6, d = i & 63;
            Vs[r * AP + d] = kv[(tok0 + k0 + r) * (NHEAD * KV_D) + h * KV_D + 64 + d];
        }
        __syncthreads();

        float s[4][4];
#pragma unroll
        for (int i = 0; i < 4; i++)
#pragma unroll
            for (int j = 0; j < 4; j++) s[i][j] = 0.f;

#pragma unroll 4
        for (int kk = 0; kk < QK_D; kk++) {
            float qv[4], kvv[4];
            *(float4*)qv  = *(float4*)&Qs[kk * AP + ty * 4];
            *(float4*)kvv = *(float4*)&Ks[kk * AP + tx * 4];
#pragma unroll
            for (int i = 0; i < 4; i++)
#pragma unroll
                for (int j = 0; j < 4; j++)
                    s[i][j] = fmaf(qv[i], kvv[j], s[i][j]);
        }

        // scale + causal mask
        if (kt == qt) {
#pragma unroll
            for (int i = 0; i < 4; i++)
#pragma unroll
                for (int j = 0; j < 4; j++)
                    s[i][j] = (k0 + tx * 4 + j > q0 + ty * 4 + i) ? -1e30f : s[i][j] * SCALE;
        } else {
#pragma unroll
            for (int i = 0; i < 4; i++)
#pragma unroll
                for (int j = 0; j < 4; j++) s[i][j] *= SCALE;
        }

        // online softmax per q-row (16 tx-threads per row, same warp half)
#pragma unroll
        for (int i = 0; i < 4; i++) {
            float tm = fmaxf(fmaxf(s[i][0], s[i][1]), fmaxf(s[i][2], s[i][3]));
#pragma unroll
            for (int o = 8; o > 0; o >>= 1)
                tm = fmaxf(tm, __shfl_xor_sync(0xffffffffu, tm, o, 16));
            const float mn = fmaxf(m[i], tm);
            const float alpha = __expf(m[i] - mn);
            float rs = 0.f;
#pragma unroll
            for (int j = 0; j < 4; j++) { s[i][j] = __expf(s[i][j] - mn); rs += s[i][j]; }
#pragma unroll
            for (int o = 8; o > 0; o >>= 1)
                rs += __shfl_xor_sync(0xffffffffu, rs, o, 16);
            l[i] = l[i] * alpha + rs;
            m[i] = mn;
#pragma unroll
            for (int j = 0; j < 4; j++) acc[i][j] *= alpha;
        }

        // write P transposed: Ps[kcol][qrow]
#pragma unroll
        for (int j = 0; j < 4; j++)
            *(float4*)&Ps[(tx * 4 + j) * AP + ty * 4] =
                make_float4(s[0][j], s[1][j], s[2][j], s[3][j]);
        __syncthreads();

        // acc += P @ V
#pragma unroll 4
        for (int kk = 0; kk < 64; kk++) {
            float pv[4], vv[4];
            *(float4*)pv = *(float4*)&Ps[kk * AP + ty * 4];
            *(float4*)vv = *(float4*)&Vs[kk * AP + tx * 4];
#pragma unroll
            for (int i = 0; i < 4; i++)
#pragma unroll
                for (int j = 0; j < 4; j++)
                    acc[i][j] = fmaf(pv[i], vv[j], acc[i][j]);
        }
    }

#pragma unroll
    for (int i = 0; i < 4; i++) {
        const float inv = 1.f / l[i];
        const size_t o = (tok0 + q0 + ty * 4 + i) * (size_t)(NHEAD * V_D) + h * V_D + tx * 4;
        *(float4*)&out[o] =
            make_float4(acc[i][0] * inv, acc[i][1] * inv, acc[i][2] * inv, acc[i][3] * inv);
    }
}

// ---------------------------------------------------------------------------
// Launch
// ---------------------------------------------------------------------------
extern "C" void kernel_launch(void* const* d_in, const int* in_sizes, int n_in,
                              void* d_out, int out_size)
{
    const float* hidden = (const float*)d_in[0];
    const float* cosb   = (const float*)d_in[1];
    const float* sinb   = (const float*)d_in[2];
    const float* wq_a   = (const float*)d_in[3];
    const float* q_ln   = (const float*)d_in[4];
    const float* wq_b   = (const float*)d_in[5];
    const float* wkv_a  = (const float*)d_in[6];
    const float* kv_ln  = (const float*)d_in[7];
    const float* wkv_b  = (const float*)d_in[8];
    const float* wo     = (const float*)d_in[9];
    float* out = (float*)d_out;

    float *qa, *qq, *ckv, *kvn, *kvb, *krot, *attn;
    cudaGetSymbolAddress((void**)&qa,   g_qa);
    cudaGetSymbolAddress((void**)&qq,   g_q);
    cudaGetSymbolAddress((void**)&ckv,  g_ckv);
    cudaGetSymbolAddress((void**)&kvn,  g_kvn);
    cudaGetSymbolAddress((void**)&kvb,  g_kv);
    cudaGetSymbolAddress((void**)&krot, g_krot);
    cudaGetSymbolAddress((void**)&attn, g_attn);

    const dim3 blk(256);
    const int mt = NTOK / 128;   // 32 row-tiles

    // q_a = hidden @ wq_a
    sgemm_kernel<<<dim3(Q_RANK / 128, mt), blk>>>(hidden, wq_a, qa, NTOK, Q_RANK, HIDN);
    // ckv = hidden @ wkv_a  (N=288, bounds-checked)
    sgemm_kernel<<<dim3((CKV_D + 127) / 128, mt), blk>>>(hidden, wkv_a, ckv, NTOK, CKV_D, HIDN);
    // rmsnorm q_a (in-place)
    rmsnorm_kernel<<<NTOK, 256>>>(qa, q_ln, qa, Q_RANK, Q_RANK, Q_RANK);
    // rmsnorm ckv[:,:256] -> kvn
    rmsnorm_kernel<<<NTOK, 256>>>(ckv, kv_ln, kvn, KV_RANK, CKV_D, KV_RANK);
    // q = q_a_norm @ wq_b
    sgemm_kernel<<<dim3(NHEAD * QK_D / 128, mt), blk>>>(qa, wq_b, qq, NTOK, NHEAD * QK_D, Q_RANK);
    // kv = kvn @ wkv_b
    sgemm_kernel<<<dim3(NHEAD * KV_D / 128, mt), blk>>>(kvn, wkv_b, kvb, NTOK, NHEAD * KV_D, KV_RANK);
    // RoPE (q in-place, krot from ckv tail)
    rope_kernel<<<NTOK, 256>>>(qq, ckv, krot, cosb, sinb);
    // flash attention
    cudaFuncSetAttribute(attn_kernel, cudaFuncAttributeMaxDynamicSharedMemorySize, ATTN_SMEM);
    attn_kernel<<<dim3(SEQ / 64, 2 * NHEAD), blk, ATTN_SMEM>>>(qq, kvb, krot, attn);
    // out = attn @ wo
    sgemm_kernel<<<dim3(HIDN / 128, mt), blk>>>(attn, wo, out, NTOK, HIDN, HIDN);
}

// round 3
// speedup vs baseline: 1.3516x; 1.3516x over previous
#include <cuda_runtime.h>
#include <cuda_bf16.h>
#include <cstdint>

// ---------------------------------------------------------------------------
// Problem constants
// ---------------------------------------------------------------------------
constexpr int SEQ    = 2048;
constexpr int HIDN   = 2560;
constexpr int NHEAD  = 40;
constexpr int NOPE_D = 64;
constexpr int ROPE_D = 32;
constexpr int QK_D   = NOPE_D + ROPE_D;    // 96
constexpr int V_D    = 64;
constexpr int Q_RANK = 768;
constexpr int KV_RANK= 256;
constexpr int CKV_D  = KV_RANK + ROPE_D;   // 288
constexpr int KV_D   = NOPE_D + V_D;       // 128 per head
constexpr int NTOK   = 2 * SEQ;            // 4096
constexpr float SCALE = 0.10206207261596577f; // 96^-0.5

// ---------------------------------------------------------------------------
// Scratch (static device arrays — no dynamic allocation)
// ---------------------------------------------------------------------------
__device__ float g_qa  [NTOK * Q_RANK];
__device__ float g_q   [NTOK * NHEAD * QK_D];
__device__ float g_ckv [NTOK * CKV_D];
__device__ float g_kvn [NTOK * KV_RANK];
__device__ float g_kv  [NTOK * NHEAD * KV_D];
__device__ float g_krot[NTOK * ROPE_D];
__device__ float g_attn[NTOK * NHEAD * V_D];

// ---------------------------------------------------------------------------
// Warp-MMA helpers (target-portable PTX: ldmatrix + mma.sync, sm_80+)
// ---------------------------------------------------------------------------
__device__ __forceinline__ uint32_t smem_u32(const void* p) {
    uint32_t a;
    asm("{ .reg .u64 t; cvta.to.shared.u64 t, %1; cvt.u32.u64 %0, t; }"
        : "=r"(a) : "l"(p));
    return a;
}

__device__ __forceinline__ void ldmatrix_x4(uint32_t& r0, uint32_t& r1,
                                            uint32_t& r2, uint32_t& r3, uint32_t addr) {
    asm volatile("ldmatrix.sync.aligned.m8n8.x4.shared.b16 {%0,%1,%2,%3}, [%4];"
                 : "=r"(r0), "=r"(r1), "=r"(r2), "=r"(r3) : "r"(addr));
}

__device__ __forceinline__ void mma_bf16(float* c, const uint32_t* a, const uint32_t* b) {
    asm volatile(
        "mma.sync.aligned.m16n8k16.row.col.f32.bf16.bf16.f32 "
        "{%0,%1,%2,%3}, {%4,%5,%6,%7}, {%8,%9}, {%0,%1,%2,%3};"
        : "+f"(c[0]), "+f"(c[1]), "+f"(c[2]), "+f"(c[3])
        : "r"(a[0]), "r"(a[1]), "r"(a[2]), "r"(a[3]), "r"(b[0]), "r"(b[1]));
}

__device__ __forceinline__ uint32_t pack2(__nv_bfloat16 a, __nv_bfloat16 b) {
    return ((uint32_t)__bfloat16_as_ushort(b) << 16) | (uint32_t)__bfloat16_as_ushort(a);
}
__device__ __forceinline__ void split1(float x, __nv_bfloat16& h, __nv_bfloat16& l) {
    h = __float2bfloat16(x);
    l = __float2bfloat16(x - __bfloat162float(h));
}

// ---------------------------------------------------------------------------
// Tensor-core GEMM via mma.sync (bf16 hi/lo split, fp32 accumulate).
// C[M,N] = A[M,K] @ B[K,N], fp32 in/out.
// Block tile 128x64, BK=32, 256 threads (8 warps, 4x2), warp tile 32x32.
// Requires M%128==0, K%32==0, N%4==0.
// ---------------------------------------------------------------------------
constexpr int TG_AST   = 40;                 // A smem stride (bf16), padded
constexpr int TG_ATILE = 128 * TG_AST;       // bf16 elems
constexpr int TG_BTILE = 64 * TG_AST;
constexpr int TG_STAGE = 2 * TG_ATILE + 2 * TG_BTILE;   // Ah,Al,Bh,Bl
constexpr int TG_SMEM  = 2 * TG_STAGE * (int)sizeof(__nv_bfloat16);  // 61440 B

__global__ __launch_bounds__(256, 2)
void tgemm_kernel(const float* __restrict__ A, const float* __restrict__ B,
                  float* __restrict__ C, int M, int N, int K)
{
    extern __shared__ __nv_bfloat16 smb[];
    const uint32_t smbase = smem_u32(smb);

    const int tid  = threadIdx.x;
    const int warp = tid >> 5;
    const int lane = tid & 31;
    const int wr   = warp >> 1;          // 0..3 (m)
    const int wc   = warp & 1;           // 0..1 (n)
    const int row0 = blockIdx.y * 128;
    const int col0 = blockIdx.x * 64;

    // per-thread load indices
    const int am  = tid >> 1;                    // with i-loop: covers 128 rows x 8 f4
    const int bk  = tid >> 4;                    // 0..15 (with i: 0..31)
    const int bn4 = (tid & 15) * 4;

    float4 areg[4];
    float4 breg[2];

    auto load_tile = [&](int k0) {
#pragma unroll
        for (int i = 0; i < 4; i++) {
            const int s = tid + i * 256;         // 0..1023
            const int m = s >> 3;                // 0..127
            const int k4 = (s & 7) * 4;
            areg[i] = *(const float4*)&A[(size_t)(row0 + m) * K + k0 + k4];
        }
#pragma unroll
        for (int i = 0; i < 2; i++) {
            const int s = tid + i * 256;         // 0..511
            const int k = s >> 4;                // 0..31
            const int n4 = (s & 15) * 4;
            if (col0 + n4 < N)                   // N%4==0 -> all 4 in-bounds
                breg[i] = *(const float4*)&B[(size_t)(k0 + k) * N + col0 + n4];
            else
                breg[i] = make_float4(0.f, 0.f, 0.f, 0.f);
        }
    };

    auto store_stage = [&](int st) {
        __nv_bfloat16* Ah = smb + st * TG_STAGE;
        __nv_bfloat16* Al = Ah + TG_ATILE;
        __nv_bfloat16* Bh = Al + TG_ATILE;
        __nv_bfloat16* Bl = Bh + TG_BTILE;
#pragma unroll
        for (int i = 0; i < 4; i++) {
            const int s = tid + i * 256;
            const int m = s >> 3;
            const int k4 = (s & 7) * 4;
            __nv_bfloat16 h0, h1, h2, h3, l0, l1, l2, l3;
            split1(areg[i].x, h0, l0); split1(areg[i].y, h1, l1);
            split1(areg[i].z, h2, l2); split1(areg[i].w, h3, l3);
            *(uint2*)&Ah[m * TG_AST + k4] = make_uint2(pack2(h0, h1), pack2(h2, h3));
            *(uint2*)&Al[m * TG_AST + k4] = make_uint2(pack2(l0, l1), pack2(l2, l3));
        }
#pragma unroll
        for (int i = 0; i < 2; i++) {
            const int s = tid + i * 256;
            const int k = s >> 4;
            const int n4 = (s & 15) * 4;
            const float v[4] = { breg[i].x, breg[i].y, breg[i].z, breg[i].w };
#pragma unroll
            for (int j = 0; j < 4; j++) {
                __nv_bfloat16 h, l;
                split1(v[j], h, l);
                Bh[(n4 + j) * TG_AST + k] = h;
                Bl[(n4 + j) * TG_AST + k] = l;
            }
        }
    };

    float acc[2][4][4];
#pragma unroll
    for (int mf = 0; mf < 2; mf++)
#pragma unroll
        for (int nf = 0; nf < 4; nf++)
#pragma unroll
            for (int r = 0; r < 4; r++) acc[mf][nf][r] = 0.f;

    // ldmatrix lane-address components
    const int a_row = (lane & 15);               // row within 16
    const int a_col = (lane >> 4) * 8;           // 0 or 8
    const int b_row = (lane >> 4) * 8 + (lane & 7);  // n within 16
    const int b_col = ((lane >> 3) & 1) * 8;     // 0 or 8

    auto compute_stage = [&](int st) {
        const uint32_t Ah = smbase + (st * TG_STAGE) * 2;
        const uint32_t Al = Ah + TG_ATILE * 2;
        const uint32_t Bh = Al + TG_ATILE * 2;
        const uint32_t Bl = Bh + TG_BTILE * 2;
#pragma unroll
        for (int ks = 0; ks < 32; ks += 16) {
            uint32_t ah[2][4], al[2][4], bh[4][2], bl[4][2];
#pragma unroll
            for (int mf = 0; mf < 2; mf++) {
                const uint32_t off =
                    ((wr * 32 + mf * 16 + a_row) * TG_AST + ks + a_col) * 2;
                ldmatrix_x4(ah[mf][0], ah[mf][1], ah[mf][2], ah[mf][3], Ah + off);
                ldmatrix_x4(al[mf][0], al[mf][1], al[mf][2], al[mf][3], Al + off);
            }
#pragma unroll
            for (int np = 0; np < 2; np++) {
                const uint32_t off =
                    ((wc * 32 + np * 16 + b_row) * TG_AST + ks + b_col) * 2;
                ldmatrix_x4(bh[np*2][0], bh[np*2][1], bh[np*2+1][0], bh[np*2+1][1], Bh + off);
                ldmatrix_x4(bl[np*2][0], bl[np*2][1], bl[np*2+1][0], bl[np*2+1][1], Bl + off);
            }
#pragma unroll
            for (int mf = 0; mf < 2; mf++)
#pragma unroll
                for (int nf = 0; nf < 4; nf++) {
                    mma_bf16(acc[mf][nf], ah[mf], bh[nf]);
                    mma_bf16(acc[mf][nf], ah[mf], bl[nf]);
                    mma_bf16(acc[mf][nf], al[mf], bh[nf]);
                }
        }
    };

    const int nch = K >> 5;
    load_tile(0);
    store_stage(0);
    __syncthreads();
    for (int ch = 0; ch < nch; ch++) {
        if (ch + 1 < nch) load_tile((ch + 1) << 5);
        compute_stage(ch & 1);
        if (ch + 1 < nch) {
            store_stage((ch + 1) & 1);
            __syncthreads();
        }
    }

    // epilogue
#pragma unroll
    for (int mf = 0; mf < 2; mf++) {
        const int r0 = row0 + wr * 32 + mf * 16 + (lane >> 2);
#pragma unroll
        for (int nf = 0; nf < 4; nf++) {
            const int c = col0 + wc * 32 + nf * 8 + (lane & 3) * 2;
            if (c < N) {
                *(float2*)&C[(size_t)r0 * N + c] =
                    make_float2(acc[mf][nf][0], acc[mf][nf][1]);
                *(float2*)&C[(size_t)(r0 + 8) * N + c] =
                    make_float2(acc[mf][nf][2], acc[mf][nf][3]);
            }
        }
    }
}

// ---------------------------------------------------------------------------
// RMSNorm: one block per row.
// ---------------------------------------------------------------------------
__global__ void rmsnorm_kernel(const float* __restrict__ in, const float* __restrict__ w,
                               float* __restrict__ out, int dim, int istride, int ostride)
{
    const int row = blockIdx.x;
    const float* x = in + (size_t)row * istride;
    float ss = 0.f;
    for (int i = threadIdx.x; i < dim; i += blockDim.x) { float v = x[i]; ss += v * v; }
#pragma unroll
    for (int o = 16; o > 0; o >>= 1) ss += __shfl_xor_sync(0xffffffffu, ss, o);
    __shared__ float sh[8];
    __shared__ float s_inv;
    const int w32 = threadIdx.x >> 5;
    if ((threadIdx.x & 31) == 0) sh[w32] = ss;
    __syncthreads();
    if (threadIdx.x == 0) {
        float t = 0.f;
        const int nw = blockDim.x >> 5;
        for (int i = 0; i < nw; i++) t += sh[i];
        s_inv = rsqrtf(t / (float)dim + 1e-5f);
    }
    __syncthreads();
    const float inv = s_inv;
    for (int i = threadIdx.x; i < dim; i += blockDim.x)
        out[(size_t)row * ostride + i] = x[i] * inv * w[i];
}

// ---------------------------------------------------------------------------
// RoPE: per-token, rotates q (in-place, 40 heads) and k_rot (ckv tail -> krot)
// ---------------------------------------------------------------------------
__global__ void rope_kernel(float* __restrict__ q, const float* __restrict__ ckv,
                            float* __restrict__ krot,
                            const float* __restrict__ cosb, const float* __restrict__ sinb)
{
    const int token = blockIdx.x;
    const int s = token & (SEQ - 1);
    for (int i = threadIdx.x; i < (NHEAD + 1) * 32; i += blockDim.x) {
        const int h = i >> 5;
        const int d = i & 31;
        const float c  = cosb[s * ROPE_D + d];
        const float sn = sinb[s * ROPE_D + d];
        if (h < NHEAD) {
            float* base = q + (size_t)token * (NHEAD * QK_D) + h * QK_D + NOPE_D;
            const float x  = base[d];
            const float pr = (d < 16) ? -base[d + 16] : base[d - 16];
            __syncwarp();
            base[d] = x * c + pr * sn;
        } else {
            const float* kb = ckv + (size_t)token * CKV_D + KV_RANK;
            const float x  = kb[d];
            const float pr = (d < 16) ? -kb[d + 16] : kb[d - 16];
            krot[(size_t)token * ROPE_D + d] = x * c + pr * sn;
        }
    }
}

// ---------------------------------------------------------------------------
// Flash attention (fp32, causal). grid = (SEQ/64, B*NHEAD), 256 threads.
// ---------------------------------------------------------------------------
constexpr int AP = 68;
constexpr int ATTN_SMEM = (QK_D * AP * 2 + 64 * AP * 2) * (int)sizeof(float);

__global__ __launch_bounds__(256, 2)
void attn_kernel(const float* __restrict__ q, const float* __restrict__ kv,
                 const float* __restrict__ krot, float* __restrict__ out)
{
    extern __shared__ float smf[];
    float* Qs = smf;
    float* Ks = Qs + QK_D * AP;
    float* Vs = Ks + QK_D * AP;
    float* Ps = Vs + 64 * AP;

    const int bh = blockIdx.y;
    const int b  = bh / NHEAD;
    const int h  = bh % NHEAD;
    const int qt = blockIdx.x;
    const int q0 = qt * 64;
    const int tid = threadIdx.x;
    const int tx  = tid & 15;
    const int ty  = tid >> 4;
    const size_t tok0 = (size_t)b * SEQ;

    for (int i = tid; i < 64 * QK_D; i += 256) {
        const int r = i / QK_D, d = i - r * QK_D;
        Qs[d * AP + r] = q[(tok0 + q0 + r) * (NHEAD * QK_D) + h * QK_D + d];
    }

    float m[4], l[4], acc[4][4];
#pragma unroll
    for (int i = 0; i < 4; i++) {
        m[i] = -1e30f; l[i] = 0.f;
#pragma unroll
        for (int j = 0; j < 4; j++) acc[i][j] = 0.f;
    }

    for (int kt = 0; kt <= qt; kt++) {
        const int k0 = kt * 64;
        __syncthreads();
        for (int i = tid; i < 64 * QK_D; i += 256) {
            const int r = i / QK_D, d = i - r * QK_D;
            const float v = (d < 64)
                ? kv[(tok0 + k0 + r) * (NHEAD * KV_D) + h * KV_D + d]
                : krot[(tok0 + k0 + r) * ROPE_D + (d - 64)];
            Ks[d * AP + r] = v;
        }
        for (int i = tid; i < 64 * 64; i += 256) {
            const int r = i >> 6, d = i & 63;
            Vs[r * AP + d] = kv[(tok0 + k0 + r) * (NHEAD * KV_D) + h * KV_D + 64 + d];
        }
        __syncthreads();

        float s[4][4];
#pragma unroll
        for (int i = 0; i < 4; i++)
#pragma unroll
            for (int j = 0; j < 4; j++) s[i][j] = 0.f;

#pragma unroll 4
        for (int kk = 0; kk < QK_D; kk++) {
            float qv[4], kvv[4];
            *(float4*)qv  = *(float4*)&Qs[kk * AP + ty * 4];
            *(float4*)kvv = *(float4*)&Ks[kk * AP + tx * 4];
#pragma unroll
            for (int i = 0; i < 4; i++)
#pragma unroll
                for (int j = 0; j < 4; j++)
                    s[i][j] = fmaf(qv[i], kvv[j], s[i][j]);
        }

        if (kt == qt) {
#pragma unroll
            for (int i = 0; i < 4; i++)
#pragma unroll
                for (int j = 0; j < 4; j++)
                    s[i][j] = (k0 + tx * 4 + j > q0 + ty * 4 + i) ? -1e30f : s[i][j] * SCALE;
        } else {
#pragma unroll
            for (int i = 0; i < 4; i++)
#pragma unroll
                for (int j = 0; j < 4; j++) s[i][j] *= SCALE;
        }

#pragma unroll
        for (int i = 0; i < 4; i++) {
            float tm = fmaxf(fmaxf(s[i][0], s[i][1]), fmaxf(s[i][2], s[i][3]));
#pragma unroll
            for (int o = 8; o > 0; o >>= 1)
                tm = fmaxf(tm, __shfl_xor_sync(0xffffffffu, tm, o, 16));
            const float mn = fmaxf(m[i], tm);
            const float alpha = __expf(m[i] - mn);
            float rs = 0.f;
#pragma unroll
            for (int j = 0; j < 4; j++) { s[i][j] = __expf(s[i][j] - mn); rs += s[i][j]; }
#pragma unroll
            for (int o = 8; o > 0; o >>= 1)
                rs += __shfl_xor_sync(0xffffffffu, rs, o, 16);
            l[i] = l[i] * alpha + rs;
            m[i] = mn;
#pragma unroll
            for (int j = 0; j < 4; j++) acc[i][j] *= alpha;
        }

#pragma unroll
        for (int j = 0; j < 4; j++)
            *(float4*)&Ps[(tx * 4 + j) * AP + ty * 4] =
                make_float4(s[0][j], s[1][j], s[2][j], s[3][j]);
        __syncthreads();

#pragma unroll 4
        for (int kk = 0; kk < 64; kk++) {
            float pv[4], vv[4];
            *(float4*)pv = *(float4*)&Ps[kk * AP + ty * 4];
            *(float4*)vv = *(float4*)&Vs[kk * AP + tx * 4];
#pragma unroll
            for (int i = 0; i < 4; i++)
#pragma unroll
                for (int j = 0; j < 4; j++)
                    acc[i][j] = fmaf(pv[i], vv[j], acc[i][j]);
        }
    }

#pragma unroll
    for (int i = 0; i < 4; i++) {
        const float inv = 1.f / l[i];
        const size_t o = (tok0 + q0 + ty * 4 + i) * (size_t)(NHEAD * V_D) + h * V_D + tx * 4;
        *(float4*)&out[o] =
            make_float4(acc[i][0] * inv, acc[i][1] * inv, acc[i][2] * inv, acc[i][3] * inv);
    }
}

// ---------------------------------------------------------------------------
// Launch
// ---------------------------------------------------------------------------
extern "C" void kernel_launch(void* const* d_in, const int* in_sizes, int n_in,
                              void* d_out, int out_size)
{
    const float* hidden = (const float*)d_in[0];
    const float* cosb   = (const float*)d_in[1];
    const float* sinb   = (const float*)d_in[2];
    const float* wq_a   = (const float*)d_in[3];
    const float* q_ln   = (const float*)d_in[4];
    const float* wq_b   = (const float*)d_in[5];
    const float* wkv_a  = (const float*)d_in[6];
    const float* kv_ln  = (const float*)d_in[7];
    const float* wkv_b  = (const float*)d_in[8];
    const float* wo     = (const float*)d_in[9];
    float* out = (float*)d_out;

    float *qa, *qq, *ckv, *kvn, *kvb, *krot, *attn;
    cudaGetSymbolAddress((void**)&qa,   g_qa);
    cudaGetSymbolAddress((void**)&qq,   g_q);
    cudaGetSymbolAddress((void**)&ckv,  g_ckv);
    cudaGetSymbolAddress((void**)&kvn,  g_kvn);
    cudaGetSymbolAddress((void**)&kvb,  g_kv);
    cudaGetSymbolAddress((void**)&krot, g_krot);
    cudaGetSymbolAddress((void**)&attn, g_attn);

    cudaFuncSetAttribute(tgemm_kernel, cudaFuncAttributeMaxDynamicSharedMemorySize, TG_SMEM);
    cudaFuncSetAttribute(attn_kernel,  cudaFuncAttributeMaxDynamicSharedMemorySize, ATTN_SMEM);

    const dim3 blk(256);
    const int mt = NTOK / 128;   // 32 row-tiles

    // q_a = hidden @ wq_a                     [4096,2560]x[2560,768]
    tgemm_kernel<<<dim3(Q_RANK / 64, mt), blk, TG_SMEM>>>(hidden, wq_a, qa, NTOK, Q_RANK, HIDN);
    // ckv = hidden @ wkv_a                    [4096,2560]x[2560,288]
    tgemm_kernel<<<dim3((CKV_D + 63) / 64, mt), blk, TG_SMEM>>>(hidden, wkv_a, ckv, NTOK, CKV_D, HIDN);
    // rmsnorm q_a (in-place)
    rmsnorm_kernel<<<NTOK, 256>>>(qa, q_ln, qa, Q_RANK, Q_RANK, Q_RANK);
    // rmsnorm ckv[:,:256] -> kvn
    rmsnorm_kernel<<<NTOK, 256>>>(ckv, kv_ln, kvn, KV_RANK, CKV_D, KV_RANK);
    // q = q_a_norm @ wq_b                     [4096,768]x[768,3840]
    tgemm_kernel<<<dim3(NHEAD * QK_D / 64, mt), blk, TG_SMEM>>>(qa, wq_b, qq, NTOK, NHEAD * QK_D, Q_RANK);
    // kv = kvn @ wkv_b                        [4096,256]x[256,5120]
    tgemm_kernel<<<dim3(NHEAD * KV_D / 64, mt), blk, TG_SMEM>>>(kvn, wkv_b, kvb, NTOK, NHEAD * KV_D, KV_RANK);
    // RoPE (q in-place, krot from ckv tail)
    rope_kernel<<<NTOK, 256>>>(qq, ckv, krot, cosb, sinb);
    // flash attention (fp32)
    attn_kernel<<<dim3(SEQ / 64, 2 * NHEAD), blk, ATTN_SMEM>>>(qq, kvb, krot, attn);
    // out = attn @ wo                         [4096,2560]x[2560,2560]
    tgemm_kernel<<<dim3(HIDN / 64, mt), blk, TG_SMEM>>>(attn, wo, out, NTOK, HIDN, HIDN);
}

// round 4
// speedup vs baseline: 2.1921x; 1.6219x over previous
#include <cuda_runtime.h>
#include <cuda_bf16.h>
#include <cstdint>

// ---------------------------------------------------------------------------
// Problem constants
// ---------------------------------------------------------------------------
constexpr int SEQ    = 2048;
constexpr int HIDN   = 2560;
constexpr int NHEAD  = 40;
constexpr int NOPE_D = 64;
constexpr int ROPE_D = 32;
constexpr int QK_D   = NOPE_D + ROPE_D;    // 96
constexpr int V_D    = 64;
constexpr int Q_RANK = 768;
constexpr int KV_RANK= 256;
constexpr int CKV_D  = KV_RANK + ROPE_D;   // 288
constexpr int KV_D   = NOPE_D + V_D;       // 128 per head
constexpr int NTOK   = 2 * SEQ;            // 4096
constexpr float SCALE = 0.10206207261596577f; // 96^-0.5
constexpr float SC2   = SCALE * 1.4426950408889634f; // scale * log2(e)

// ---------------------------------------------------------------------------
// Scratch (static device arrays — no dynamic allocation)
// ---------------------------------------------------------------------------
__device__ float g_qa  [NTOK * Q_RANK];
__device__ float g_q   [NTOK * NHEAD * QK_D];
__device__ float g_ckv [NTOK * CKV_D];
__device__ float g_kvn [NTOK * KV_RANK];
__device__ float g_kv  [NTOK * NHEAD * KV_D];
__device__ float g_krot[NTOK * ROPE_D];
__device__ float g_attn[NTOK * NHEAD * V_D];

// ---------------------------------------------------------------------------
// Warp-MMA helpers (target-portable PTX: ldmatrix + mma.sync, sm_80+)
// ---------------------------------------------------------------------------
__device__ __forceinline__ uint32_t smem_u32(const void* p) {
    uint32_t a;
    asm("{ .reg .u64 t; cvta.to.shared.u64 t, %1; cvt.u32.u64 %0, t; }"
        : "=r"(a) : "l"(p));
    return a;
}

__device__ __forceinline__ void ldmatrix_x4(uint32_t& r0, uint32_t& r1,
                                            uint32_t& r2, uint32_t& r3, uint32_t addr) {
    asm volatile("ldmatrix.sync.aligned.m8n8.x4.shared.b16 {%0,%1,%2,%3}, [%4];"
                 : "=r"(r0), "=r"(r1), "=r"(r2), "=r"(r3) : "r"(addr));
}
__device__ __forceinline__ void ldmatrix_x4_t(uint32_t& r0, uint32_t& r1,
                                              uint32_t& r2, uint32_t& r3, uint32_t addr) {
    asm volatile("ldmatrix.sync.aligned.m8n8.x4.trans.shared.b16 {%0,%1,%2,%3}, [%4];"
                 : "=r"(r0), "=r"(r1), "=r"(r2), "=r"(r3) : "r"(addr));
}

__device__ __forceinline__ void mma_bf16(float* c, const uint32_t* a, const uint32_t* b) {
    asm volatile(
        "mma.sync.aligned.m16n8k16.row.col.f32.bf16.bf16.f32 "
        "{%0,%1,%2,%3}, {%4,%5,%6,%7}, {%8,%9}, {%0,%1,%2,%3};"
        : "+f"(c[0]), "+f"(c[1]), "+f"(c[2]), "+f"(c[3])
        : "r"(a[0]), "r"(a[1]), "r"(a[2]), "r"(a[3]), "r"(b[0]), "r"(b[1]));
}

__device__ __forceinline__ uint32_t pack2(__nv_bfloat16 a, __nv_bfloat16 b) {
    return ((uint32_t)__bfloat16_as_ushort(b) << 16) | (uint32_t)__bfloat16_as_ushort(a);
}
__device__ __forceinline__ void split1(float x, __nv_bfloat16& h, __nv_bfloat16& l) {
    h = __float2bfloat16(x);
    l = __float2bfloat16(x - __bfloat162float(h));
}

// Fast exp2 for x <= 0 (FFMA-only; avoids the MUFU throughput cliff).
// abs err ~2.4e-6 on [-0.5,0.5] reduction; underflows to ~0 below -126.
__device__ __forceinline__ float fexp2(float x) {
    x = fmaxf(x, -126.0f);
    int   ni = __float2int_rn(x);
    float f  = x - (float)ni;
    float p  = 1.3333558e-3f;
    p = fmaf(p, f, 9.6181291e-3f);
    p = fmaf(p, f, 5.5504109e-2f);
    p = fmaf(p, f, 2.4022651e-1f);
    p = fmaf(p, f, 6.9314718e-1f);
    p = fmaf(p, f, 1.0f);
    return p * __int_as_float((ni + 127) << 23);
}

// ---------------------------------------------------------------------------
// Tensor-core GEMM via mma.sync (bf16 hi/lo split, fp32 accumulate).
// Block tile 128x64, BK=32, 256 threads (8 warps, 4x2), warp tile 32x32.
// ---------------------------------------------------------------------------
constexpr int TG_AST   = 40;
constexpr int TG_ATILE = 128 * TG_AST;
constexpr int TG_BTILE = 64 * TG_AST;
constexpr int TG_STAGE = 2 * TG_ATILE + 2 * TG_BTILE;
constexpr int TG_SMEM  = 2 * TG_STAGE * (int)sizeof(__nv_bfloat16);

__global__ __launch_bounds__(256, 2)
void tgemm_kernel(const float* __restrict__ A, const float* __restrict__ B,
                  float* __restrict__ C, int M, int N, int K)
{
    extern __shared__ __nv_bfloat16 smb[];
    const uint32_t smbase = smem_u32(smb);

    const int tid  = threadIdx.x;
    const int warp = tid >> 5;
    const int lane = tid & 31;
    const int wr   = warp >> 1;
    const int wc   = warp & 1;
    const int row0 = blockIdx.y * 128;
    const int col0 = blockIdx.x * 64;

    float4 areg[4];
    float4 breg[2];

    auto load_tile = [&](int k0) {
#pragma unroll
        for (int i = 0; i < 4; i++) {
            const int s = tid + i * 256;
            const int m = s >> 3;
            const int k4 = (s & 7) * 4;
            areg[i] = *(const float4*)&A[(size_t)(row0 + m) * K + k0 + k4];
        }
#pragma unroll
        for (int i = 0; i < 2; i++) {
            const int s = tid + i * 256;
            const int k = s >> 4;
            const int n4 = (s & 15) * 4;
            if (col0 + n4 < N)
                breg[i] = *(const float4*)&B[(size_t)(k0 + k) * N + col0 + n4];
            else
                breg[i] = make_float4(0.f, 0.f, 0.f, 0.f);
        }
    };

    auto store_stage = [&](int st) {
        __nv_bfloat16* Ah = smb + st * TG_STAGE;
        __nv_bfloat16* Al = Ah + TG_ATILE;
        __nv_bfloat16* Bh = Al + TG_ATILE;
        __nv_bfloat16* Bl = Bh + TG_BTILE;
#pragma unroll
        for (int i = 0; i < 4; i++) {
            const int s = tid + i * 256;
            const int m = s >> 3;
            const int k4 = (s & 7) * 4;
            __nv_bfloat16 h0, h1, h2, h3, l0, l1, l2, l3;
            split1(areg[i].x, h0, l0); split1(areg[i].y, h1, l1);
            split1(areg[i].z, h2, l2); split1(areg[i].w, h3, l3);
            *(uint2*)&Ah[m * TG_AST + k4] = make_uint2(pack2(h0, h1), pack2(h2, h3));
            *(uint2*)&Al[m * TG_AST + k4] = make_uint2(pack2(l0, l1), pack2(l2, l3));
        }
#pragma unroll
        for (int i = 0; i < 2; i++) {
            const int s = tid + i * 256;
            const int k = s >> 4;
            const int n4 = (s & 15) * 4;
            const float v[4] = { breg[i].x, breg[i].y, breg[i].z, breg[i].w };
#pragma unroll
            for (int j = 0; j < 4; j++) {
                __nv_bfloat16 h, l;
                split1(v[j], h, l);
                Bh[(n4 + j) * TG_AST + k] = h;
                Bl[(n4 + j) * TG_AST + k] = l;
            }
        }
    };

    float acc[2][4][4];
#pragma unroll
    for (int mf = 0; mf < 2; mf++)
#pragma unroll
        for (int nf = 0; nf < 4; nf++)
#pragma unroll
            for (int r = 0; r < 4; r++) acc[mf][nf][r] = 0.f;

    const int a_row = (lane & 15);
    const int a_col = (lane >> 4) * 8;
    const int b_row = (lane >> 4) * 8 + (lane & 7);
    const int b_col = ((lane >> 3) & 1) * 8;

    auto compute_stage = [&](int st) {
        const uint32_t Ah = smbase + (st * TG_STAGE) * 2;
        const uint32_t Al = Ah + TG_ATILE * 2;
        const uint32_t Bh = Al + TG_ATILE * 2;
        const uint32_t Bl = Bh + TG_BTILE * 2;
#pragma unroll
        for (int ks = 0; ks < 32; ks += 16) {
            uint32_t ah[2][4], al[2][4], bh[4][2], bl[4][2];
#pragma unroll
            for (int mf = 0; mf < 2; mf++) {
                const uint32_t off =
                    ((wr * 32 + mf * 16 + a_row) * TG_AST + ks + a_col) * 2;
                ldmatrix_x4(ah[mf][0], ah[mf][1], ah[mf][2], ah[mf][3], Ah + off);
                ldmatrix_x4(al[mf][0], al[mf][1], al[mf][2], al[mf][3], Al + off);
            }
#pragma unroll
            for (int np = 0; np < 2; np++) {
                const uint32_t off =
                    ((wc * 32 + np * 16 + b_row) * TG_AST + ks + b_col) * 2;
                ldmatrix_x4(bh[np*2][0], bh[np*2][1], bh[np*2+1][0], bh[np*2+1][1], Bh + off);
                ldmatrix_x4(bl[np*2][0], bl[np*2][1], bl[np*2+1][0], bl[np*2+1][1], Bl + off);
            }
#pragma unroll
            for (int mf = 0; mf < 2; mf++)
#pragma unroll
                for (int nf = 0; nf < 4; nf++) {
                    mma_bf16(acc[mf][nf], ah[mf], bh[nf]);
                    mma_bf16(acc[mf][nf], ah[mf], bl[nf]);
                    mma_bf16(acc[mf][nf], al[mf], bh[nf]);
                }
        }
    };

    const int nch = K >> 5;
    load_tile(0);
    store_stage(0);
    __syncthreads();
    for (int ch = 0; ch < nch; ch++) {
        if (ch + 1 < nch) load_tile((ch + 1) << 5);
        compute_stage(ch & 1);
        if (ch + 1 < nch) {
            store_stage((ch + 1) & 1);
            __syncthreads();
        }
    }

#pragma unroll
    for (int mf = 0; mf < 2; mf++) {
        const int r0 = row0 + wr * 32 + mf * 16 + (lane >> 2);
#pragma unroll
        for (int nf = 0; nf < 4; nf++) {
            const int c = col0 + wc * 32 + nf * 8 + (lane & 3) * 2;
            if (c < N) {
                *(float2*)&C[(size_t)r0 * N + c] =
                    make_float2(acc[mf][nf][0], acc[mf][nf][1]);
                *(float2*)&C[(size_t)(r0 + 8) * N + c] =
                    make_float2(acc[mf][nf][2], acc[mf][nf][3]);
            }
        }
    }
}

// ---------------------------------------------------------------------------
// RMSNorm
// ---------------------------------------------------------------------------
__global__ void rmsnorm_kernel(const float* __restrict__ in, const float* __restrict__ w,
                               float* __restrict__ out, int dim, int istride, int ostride)
{
    const int row = blockIdx.x;
    const float* x = in + (size_t)row * istride;
    float ss = 0.f;
    for (int i = threadIdx.x; i < dim; i += blockDim.x) { float v = x[i]; ss += v * v; }
#pragma unroll
    for (int o = 16; o > 0; o >>= 1) ss += __shfl_xor_sync(0xffffffffu, ss, o);
    __shared__ float sh[8];
    __shared__ float s_inv;
    const int w32 = threadIdx.x >> 5;
    if ((threadIdx.x & 31) == 0) sh[w32] = ss;
    __syncthreads();
    if (threadIdx.x == 0) {
        float t = 0.f;
        const int nw = blockDim.x >> 5;
        for (int i = 0; i < nw; i++) t += sh[i];
        s_inv = rsqrtf(t / (float)dim + 1e-5f);
    }
    __syncthreads();
    const float inv = s_inv;
    for (int i = threadIdx.x; i < dim; i += blockDim.x)
        out[(size_t)row * ostride + i] = x[i] * inv * w[i];
}

// ---------------------------------------------------------------------------
// RoPE
// ---------------------------------------------------------------------------
__global__ void rope_kernel(float* __restrict__ q, const float* __restrict__ ckv,
                            float* __restrict__ krot,
                            const float* __restrict__ cosb, const float* __restrict__ sinb)
{
    const int token = blockIdx.x;
    const int s = token & (SEQ - 1);
    for (int i = threadIdx.x; i < (NHEAD + 1) * 32; i += blockDim.x) {
        const int h = i >> 5;
        const int d = i & 31;
        const float c  = cosb[s * ROPE_D + d];
        const float sn = sinb[s * ROPE_D + d];
        if (h < NHEAD) {
            float* base = q + (size_t)token * (NHEAD * QK_D) + h * QK_D + NOPE_D;
            const float x  = base[d];
            const float pr = (d < 16) ? -base[d + 16] : base[d - 16];
            __syncwarp();
            base[d] = x * c + pr * sn;
        } else {
            const float* kb = ckv + (size_t)token * CKV_D + KV_RANK;
            const float x  = kb[d];
            const float pr = (d < 16) ? -kb[d + 16] : kb[d - 16];
            krot[(size_t)token * ROPE_D + d] = x * c + pr * sn;
        }
    }
}

// ---------------------------------------------------------------------------
// Flash attention via mma.sync (bf16 hi/lo split, fp32 softmax+accum).
// BQ=128, BK=64. 256 threads, 8 warps x 16 q-rows each (full 64-col stripe).
// grid = (SEQ/128, B*NHEAD).
// ---------------------------------------------------------------------------
constexpr int AQ_ST   = 104;                // Q/K smem stride (bf16)
constexpr int AV_ST   = 72;                 // V smem stride
constexpr int A_QT    = 128 * AQ_ST;        // 13312
constexpr int A_KT    = 64 * AQ_ST;         // 6656
constexpr int A_VT    = 64 * AV_ST;         // 4608
constexpr int ATTN_SMEM = (2*A_QT + 2*A_KT + 2*A_VT) * (int)sizeof(__nv_bfloat16); // 98304

__global__ __launch_bounds__(256, 2)
void attn_mma_kernel(const float* __restrict__ q, const float* __restrict__ kv,
                     const float* __restrict__ krot, float* __restrict__ out)
{
    extern __shared__ __nv_bfloat16 smb[];
    __nv_bfloat16* Qh = smb;
    __nv_bfloat16* Ql = Qh + A_QT;
    __nv_bfloat16* Kh = Ql + A_QT;
    __nv_bfloat16* Kl = Kh + A_KT;
    __nv_bfloat16* Vh = Kl + A_KT;
    __nv_bfloat16* Vl = Vh + A_VT;
    const uint32_t uQh = smem_u32(Qh);
    const uint32_t uQl = uQh + A_QT * 2;
    const uint32_t uKh = uQl + A_QT * 2;
    const uint32_t uKl = uKh + A_KT * 2;
    const uint32_t uVh = uKl + A_KT * 2;
    const uint32_t uVl = uVh + A_VT * 2;

    const int bh = blockIdx.y;
    const int b  = bh / NHEAD;
    const int h  = bh % NHEAD;
    const int qt = blockIdx.x;
    const int q0 = qt * 128;
    const int tid  = threadIdx.x;
    const int warp = tid >> 5;
    const int lane = tid & 31;
    const int gr   = lane >> 2;
    const int qd   = lane & 3;
    const size_t tok0 = (size_t)b * SEQ;

    // ldmatrix lane addressing
    const int a_row = (lane & 15);
    const int a_col = (lane >> 4) * 8;
    const int b_row = (lane >> 4) * 8 + (lane & 7);
    const int b_col = ((lane >> 3) & 1) * 8;
    const int v_row = (lane & 15);           // key within 16
    const int v_col = (lane >> 4) * 8;       // vd offset

    // ---- load Q tile (128 x 96) hi/lo ----
#pragma unroll
    for (int i = 0; i < 12; i++) {
        const int s  = tid + i * 256;        // 3072 float4
        const int r  = s / 24;
        const int c4 = (s - r * 24) * 4;
        const float4 v = *(const float4*)&q[(tok0 + q0 + r) * (NHEAD * QK_D) + h * QK_D + c4];
        __nv_bfloat16 h0, h1, h2, h3, l0, l1, l2, l3;
        split1(v.x, h0, l0); split1(v.y, h1, l1);
        split1(v.z, h2, l2); split1(v.w, h3, l3);
        *(uint2*)&Qh[r * AQ_ST + c4] = make_uint2(pack2(h0, h1), pack2(h2, h3));
        *(uint2*)&Ql[r * AQ_ST + c4] = make_uint2(pack2(l0, l1), pack2(l2, l3));
    }

    float oacc[8][4];
#pragma unroll
    for (int nf = 0; nf < 8; nf++)
#pragma unroll
        for (int r = 0; r < 4; r++) oacc[nf][r] = 0.f;
    float mA = -1e30f, mB = -1e30f, lA = 0.f, lB = 0.f;

    const int q0w  = q0 + warp * 16;
    const int rowA = q0w + gr;
    const int rowB = rowA + 8;
    const int nkt  = 2 * qt + 2;

    for (int kt = 0; kt < nkt; kt++) {
        const int k0 = kt * 64;
        __syncthreads();
        // ---- load K tile (64 x 96) hi/lo: [key][d] ----
#pragma unroll
        for (int i = 0; i < 6; i++) {
            const int s  = tid + i * 256;    // 1536 float4
            const int r  = s / 24;
            const int c4 = (s - r * 24) * 4;
            float4 v;
            if (c4 < 64)
                v = *(const float4*)&kv[(tok0 + k0 + r) * (NHEAD * KV_D) + h * KV_D + c4];
            else
                v = *(const float4*)&krot[(tok0 + k0 + r) * ROPE_D + (c4 - 64)];
            __nv_bfloat16 h0, h1, h2, h3, l0, l1, l2, l3;
            split1(v.x, h0, l0); split1(v.y, h1, l1);
            split1(v.z, h2, l2); split1(v.w, h3, l3);
            *(uint2*)&Kh[r * AQ_ST + c4] = make_uint2(pack2(h0, h1), pack2(h2, h3));
            *(uint2*)&Kl[r * AQ_ST + c4] = make_uint2(pack2(l0, l1), pack2(l2, l3));
        }
        // ---- load V tile (64 keys x 64 vd) hi/lo: [key][vd] ----
#pragma unroll
        for (int i = 0; i < 4; i++) {
            const int s  = tid + i * 256;    // 1024 float4
            const int r  = s >> 4;           // key
            const int c4 = (s & 15) * 4;     // vd
            const float4 v = *(const float4*)&kv[(tok0 + k0 + r) * (NHEAD * KV_D) + h * KV_D + 64 + c4];
            __nv_bfloat16 h0, h1, h2, h3, l0, l1, l2, l3;
            split1(v.x, h0, l0); split1(v.y, h1, l1);
            split1(v.z, h2, l2); split1(v.w, h3, l3);
            *(uint2*)&Vh[r * AV_ST + c4] = make_uint2(pack2(h0, h1), pack2(h2, h3));
            *(uint2*)&Vl[r * AV_ST + c4] = make_uint2(pack2(l0, l1), pack2(l2, l3));
        }
        __syncthreads();

        // ---- S = Q @ K^T  (warp: 16 rows x 64 cols) ----
        float sa[8][4];
#pragma unroll
        for (int nf = 0; nf < 8; nf++)
#pragma unroll
            for (int r = 0; r < 4; r++) sa[nf][r] = 0.f;

#pragma unroll
        for (int ks = 0; ks < 96; ks += 16) {
            uint32_t ah[4], al[4];
            const uint32_t aoff = ((warp * 16 + a_row) * AQ_ST + ks + a_col) * 2;
            ldmatrix_x4(ah[0], ah[1], ah[2], ah[3], uQh + aoff);
            ldmatrix_x4(al[0], al[1], al[2], al[3], uQl + aoff);
#pragma unroll
            for (int np = 0; np < 4; np++) {
                uint32_t bhf[4], blf[4];
                const uint32_t boff = ((np * 16 + b_row) * AQ_ST + ks + b_col) * 2;
                ldmatrix_x4(bhf[0], bhf[1], bhf[2], bhf[3], uKh + boff);
                ldmatrix_x4(blf[0], blf[1], blf[2], blf[3], uKl + boff);
                mma_bf16(sa[np*2],   ah, bhf + 0);
                mma_bf16(sa[np*2],   ah, blf + 0);
                mma_bf16(sa[np*2],   al, bhf + 0);
                mma_bf16(sa[np*2+1], ah, bhf + 2);
                mma_bf16(sa[np*2+1], ah, blf + 2);
                mma_bf16(sa[np*2+1], al, bhf + 2);
            }
        }

        // ---- scale (log2 domain) + causal mask ----
#pragma unroll
        for (int nf = 0; nf < 8; nf++)
#pragma unroll
            for (int r = 0; r < 4; r++) sa[nf][r] *= SC2;
        if (k0 + 63 > q0w) {
#pragma unroll
            for (int nf = 0; nf < 8; nf++) {
                const int col = k0 + nf * 8 + qd * 2;
                if (col     > rowA) sa[nf][0] = -1e30f;
                if (col + 1 > rowA) sa[nf][1] = -1e30f;
                if (col     > rowB) sa[nf][2] = -1e30f;
                if (col + 1 > rowB) sa[nf][3] = -1e30f;
            }
        }

        // ---- online softmax (rows owned by quads; shfl 1,2) ----
        float mxA = -1e30f, mxB = -1e30f;
#pragma unroll
        for (int nf = 0; nf < 8; nf++) {
            mxA = fmaxf(mxA, fmaxf(sa[nf][0], sa[nf][1]));
            mxB = fmaxf(mxB, fmaxf(sa[nf][2], sa[nf][3]));
        }
        mxA = fmaxf(mxA, __shfl_xor_sync(0xffffffffu, mxA, 1));
        mxA = fmaxf(mxA, __shfl_xor_sync(0xffffffffu, mxA, 2));
        mxB = fmaxf(mxB, __shfl_xor_sync(0xffffffffu, mxB, 1));
        mxB = fmaxf(mxB, __shfl_xor_sync(0xffffffffu, mxB, 2));
        const float mnA = fmaxf(mA, mxA);
        const float mnB = fmaxf(mB, mxB);
        const float alA = fexp2(mA - mnA);
        const float alB = fexp2(mB - mnB);
        mA = mnA; mB = mnB;

        float rsA = 0.f, rsB = 0.f;
#pragma unroll
        for (int nf = 0; nf < 8; nf++) {
            sa[nf][0] = fexp2(sa[nf][0] - mnA); rsA += sa[nf][0];
            sa[nf][1] = fexp2(sa[nf][1] - mnA); rsA += sa[nf][1];
            sa[nf][2] = fexp2(sa[nf][2] - mnB); rsB += sa[nf][2];
            sa[nf][3] = fexp2(sa[nf][3] - mnB); rsB += sa[nf][3];
        }
        rsA += __shfl_xor_sync(0xffffffffu, rsA, 1);
        rsA += __shfl_xor_sync(0xffffffffu, rsA, 2);
        rsB += __shfl_xor_sync(0xffffffffu, rsB, 1);
        rsB += __shfl_xor_sync(0xffffffffu, rsB, 2);
        lA = lA * alA + rsA;
        lB = lB * alB + rsB;
#pragma unroll
        for (int nf = 0; nf < 8; nf++) {
            oacc[nf][0] *= alA; oacc[nf][1] *= alA;
            oacc[nf][2] *= alB; oacc[nf][3] *= alB;
        }

        // ---- O += P @ V  (P from accums, hi/lo split; V via ldmatrix.trans) ----
#pragma unroll
        for (int t = 0; t < 4; t++) {
            uint32_t ph[4], pl[4];
#pragma unroll
            for (int half = 0; half < 2; half++) {
                const int nf = 2 * t + half;
                __nv_bfloat16 h0, h1, h2, h3, l0, l1, l2, l3;
                split1(sa[nf][0], h0, l0); split1(sa[nf][1], h1, l1);
                split1(sa[nf][2], h2, l2); split1(sa[nf][3], h3, l3);
                ph[half*2]   = pack2(h0, h1); pl[half*2]   = pack2(l0, l1);
                ph[half*2+1] = pack2(h2, h3); pl[half*2+1] = pack2(l2, l3);
            }
#pragma unroll
            for (int np = 0; np < 4; np++) {
                uint32_t vhf[4], vlf[4];
                const uint32_t voff = ((t * 16 + v_row) * AV_ST + np * 16 + v_col) * 2;
                ldmatrix_x4_t(vhf[0], vhf[1], vhf[2], vhf[3], uVh + voff);
                ldmatrix_x4_t(vlf[0], vlf[1], vlf[2], vlf[3], uVl + voff);
                mma_bf16(oacc[np*2],   ph, vhf + 0);
                mma_bf16(oacc[np*2],   ph, vlf + 0);
                mma_bf16(oacc[np*2],   pl, vhf + 0);
                mma_bf16(oacc[np*2+1], ph, vhf + 2);
                mma_bf16(oacc[np*2+1], ph, vlf + 2);
                mma_bf16(oacc[np*2+1], pl, vhf + 2);
            }
        }
    }

    // ---- finalize + write ----
    const float invA = 1.f / lA;
    const float invB = 1.f / lB;
#pragma unroll
    for (int nf = 0; nf < 8; nf++) {
        const int col = h * V_D + nf * 8 + qd * 2;
        *(float2*)&out[(tok0 + rowA) * (size_t)(NHEAD * V_D) + col] =
            make_float2(oacc[nf][0] * invA, oacc[nf][1] * invA);
        *(float2*)&out[(tok0 + rowB) * (size_t)(NHEAD * V_D) + col] =
            make_float2(oacc[nf][2] * invB, oacc[nf][3] * invB);
    }
}

// ---------------------------------------------------------------------------
// Launch
// ---------------------------------------------------------------------------
extern "C" void kernel_launch(void* const* d_in, const int* in_sizes, int n_in,
                              void* d_out, int out_size)
{
    const float* hidden = (const float*)d_in[0];
    const float* cosb   = (const float*)d_in[1];
    const float* sinb   = (const float*)d_in[2];
    const float* wq_a   = (const float*)d_in[3];
    const float* q_ln   = (const float*)d_in[4];
    const float* wq_b   = (const float*)d_in[5];
    const float* wkv_a  = (const float*)d_in[6];
    const float* kv_ln  = (const float*)d_in[7];
    const float* wkv_b  = (const float*)d_in[8];
    const float* wo     = (const float*)d_in[9];
    float* out = (float*)d_out;

    float *qa, *qq, *ckv, *kvn, *kvb, *krot, *attn;
    cudaGetSymbolAddress((void**)&qa,   g_qa);
    cudaGetSymbolAddress((void**)&qq,   g_q);
    cudaGetSymbolAddress((void**)&ckv,  g_ckv);
    cudaGetSymbolAddress((void**)&kvn,  g_kvn);
    cudaGetSymbolAddress((void**)&kvb,  g_kv);
    cudaGetSymbolAddress((void**)&krot, g_krot);
    cudaGetSymbolAddress((void**)&attn, g_attn);

    cudaFuncSetAttribute(tgemm_kernel,    cudaFuncAttributeMaxDynamicSharedMemorySize, TG_SMEM);
    cudaFuncSetAttribute(attn_mma_kernel, cudaFuncAttributeMaxDynamicSharedMemorySize, ATTN_SMEM);

    const dim3 blk(256);
    const int mt = NTOK / 128;

    tgemm_kernel<<<dim3(Q_RANK / 64, mt), blk, TG_SMEM>>>(hidden, wq_a, qa, NTOK, Q_RANK, HIDN);
    tgemm_kernel<<<dim3((CKV_D + 63) / 64, mt), blk, TG_SMEM>>>(hidden, wkv_a, ckv, NTOK, CKV_D, HIDN);
    rmsnorm_kernel<<<NTOK, 256>>>(qa, q_ln, qa, Q_RANK, Q_RANK, Q_RANK);
    rmsnorm_kernel<<<NTOK, 256>>>(ckv, kv_ln, kvn, KV_RANK, CKV_D, KV_RANK);
    tgemm_kernel<<<dim3(NHEAD * QK_D / 64, mt), blk, TG_SMEM>>>(qa, wq_b, qq, NTOK, NHEAD * QK_D, Q_RANK);
    tgemm_kernel<<<dim3(NHEAD * KV_D / 64, mt), blk, TG_SMEM>>>(kvn, wkv_b, kvb, NTOK, NHEAD * KV_D, KV_RANK);
    rope_kernel<<<NTOK, 256>>>(qq, ckv, krot, cosb, sinb);
    attn_mma_kernel<<<dim3(SEQ / 128, 2 * NHEAD), blk, ATTN_SMEM>>>(qq, kvb, krot, attn);
    tgemm_kernel<<<dim3(HIDN / 64, mt), blk, TG_SMEM>>>(attn, wo, out, NTOK, HIDN, HIDN);
}

// round 5
// speedup vs baseline: 3.0133x; 1.3746x over previous
#include <cuda_runtime.h>
#include <cuda_bf16.h>
#include <cstdint>

// ---------------------------------------------------------------------------
// Problem constants
// ---------------------------------------------------------------------------
constexpr int SEQ    = 2048;
constexpr int HIDN   = 2560;
constexpr int NHEAD  = 40;
constexpr int NOPE_D = 64;
constexpr int ROPE_D = 32;
constexpr int QK_D   = NOPE_D + ROPE_D;    // 96
constexpr int V_D    = 64;
constexpr int Q_RANK = 768;
constexpr int KV_RANK= 256;
constexpr int CKV_D  = KV_RANK + ROPE_D;   // 288
constexpr int NTOK   = 2 * SEQ;            // 4096
constexpr int QD_ALL = NHEAD * QK_D;       // 3840
constexpr int KVD_ALL= NHEAD * (NOPE_D + V_D); // 5120
constexpr int OD_ALL = NHEAD * V_D;        // 2560
constexpr float SCALE = 0.10206207261596577f;
constexpr float SC2   = SCALE * 1.4426950408889634f;

// ---------------------------------------------------------------------------
// Scratch (static device arrays)
// ---------------------------------------------------------------------------
__device__ __nv_bfloat16 g_hid_h [NTOK * HIDN];
__device__ __nv_bfloat16 g_hid_l [NTOK * HIDN];
__device__ __nv_bfloat16 g_wqa_h [Q_RANK * HIDN];     // transposed [N][K]
__device__ __nv_bfloat16 g_wqa_l [Q_RANK * HIDN];
__device__ __nv_bfloat16 g_wkva_h[CKV_D * HIDN];
__device__ __nv_bfloat16 g_wkva_l[CKV_D * HIDN];
__device__ __nv_bfloat16 g_wqb_h [QD_ALL * Q_RANK];
__device__ __nv_bfloat16 g_wqb_l [QD_ALL * Q_RANK];
__device__ __nv_bfloat16 g_wkvb_h[KVD_ALL * KV_RANK];
__device__ __nv_bfloat16 g_wkvb_l[KVD_ALL * KV_RANK];
__device__ __nv_bfloat16 g_wo_h  [HIDN * OD_ALL];
__device__ __nv_bfloat16 g_wo_l  [HIDN * OD_ALL];
__device__ float         g_qa    [NTOK * Q_RANK];
__device__ float         g_ckv   [NTOK * CKV_D];
__device__ __nv_bfloat16 g_qan_h [NTOK * Q_RANK];
__device__ __nv_bfloat16 g_qan_l [NTOK * Q_RANK];
__device__ __nv_bfloat16 g_kvn_h [NTOK * KV_RANK];
__device__ __nv_bfloat16 g_kvn_l [NTOK * KV_RANK];
__device__ __nv_bfloat16 g_q_h   [NTOK * QD_ALL];
__device__ __nv_bfloat16 g_q_l   [NTOK * QD_ALL];
__device__ __nv_bfloat16 g_kv_h  [NTOK * KVD_ALL];
__device__ __nv_bfloat16 g_kv_l  [NTOK * KVD_ALL];
__device__ __nv_bfloat16 g_kr_h  [NTOK * ROPE_D];
__device__ __nv_bfloat16 g_kr_l  [NTOK * ROPE_D];
__device__ __nv_bfloat16 g_at_h  [NTOK * OD_ALL];
__device__ __nv_bfloat16 g_at_l  [NTOK * OD_ALL];

// ---------------------------------------------------------------------------
// PTX helpers (portable sm_80+ subset)
// ---------------------------------------------------------------------------
__device__ __forceinline__ uint32_t smem_u32(const void* p) {
    uint32_t a;
    asm("{ .reg .u64 t; cvta.to.shared.u64 t, %1; cvt.u32.u64 %0, t; }"
        : "=r"(a) : "l"(p));
    return a;
}
__device__ __forceinline__ void ldmatrix_x4(uint32_t& r0, uint32_t& r1,
                                            uint32_t& r2, uint32_t& r3, uint32_t addr) {
    asm volatile("ldmatrix.sync.aligned.m8n8.x4.shared.b16 {%0,%1,%2,%3}, [%4];"
                 : "=r"(r0), "=r"(r1), "=r"(r2), "=r"(r3) : "r"(addr));
}
__device__ __forceinline__ void ldmatrix_x4_t(uint32_t& r0, uint32_t& r1,
                                              uint32_t& r2, uint32_t& r3, uint32_t addr) {
    asm volatile("ldmatrix.sync.aligned.m8n8.x4.trans.shared.b16 {%0,%1,%2,%3}, [%4];"
                 : "=r"(r0), "=r"(r1), "=r"(r2), "=r"(r3) : "r"(addr));
}
__device__ __forceinline__ void mma_bf16(float* c, const uint32_t* a, const uint32_t* b) {
    asm volatile(
        "mma.sync.aligned.m16n8k16.row.col.f32.bf16.bf16.f32 "
        "{%0,%1,%2,%3}, {%4,%5,%6,%7}, {%8,%9}, {%0,%1,%2,%3};"
        : "+f"(c[0]), "+f"(c[1]), "+f"(c[2]), "+f"(c[3])
        : "r"(a[0]), "r"(a[1]), "r"(a[2]), "r"(a[3]), "r"(b[0]), "r"(b[1]));
}
#define CP16(dst, src) \
    asm volatile("cp.async.cg.shared.global [%0], [%1], 16;" :: "r"(dst), "l"(src))
#define CP16P(dst, src, pred) \
    asm volatile("cp.async.cg.shared.global [%0], [%1], 16, %2;" \
                 :: "r"(dst), "l"(src), "r"((pred) ? 16 : 0))
#define CP_COMMIT() asm volatile("cp.async.commit_group;" ::: "memory")
#define CP_WAIT(n)  asm volatile("cp.async.wait_group %0;" :: "n"(n) : "memory")

__device__ __forceinline__ uint32_t pack2(__nv_bfloat16 a, __nv_bfloat16 b) {
    return ((uint32_t)__bfloat16_as_ushort(b) << 16) | (uint32_t)__bfloat16_as_ushort(a);
}
__device__ __forceinline__ void split1(float x, __nv_bfloat16& h, __nv_bfloat16& l) {
    h = __float2bfloat16(x);
    l = __float2bfloat16(x - __bfloat162float(h));
}
__device__ __forceinline__ float fexp2(float x) {
    x = fmaxf(x, -126.0f);
    int   ni = __float2int_rn(x);
    float f  = x - (float)ni;
    float p  = 1.3333558e-3f;
    p = fmaf(p, f, 9.6181291e-3f);
    p = fmaf(p, f, 5.5504109e-2f);
    p = fmaf(p, f, 2.4022651e-1f);
    p = fmaf(p, f, 6.9314718e-1f);
    p = fmaf(p, f, 1.0f);
    return p * __int_as_float((ni + 127) << 23);
}

// ---------------------------------------------------------------------------
// Elementwise split: fp32 -> bf16 hi/lo planes
// ---------------------------------------------------------------------------
__global__ void split_kernel(const float* __restrict__ in,
                             __nv_bfloat16* __restrict__ oh,
                             __nv_bfloat16* __restrict__ ol, int n4)
{
    const int i = blockIdx.x * blockDim.x + threadIdx.x;
    if (i >= n4) return;
    const float4 v = *(const float4*)&in[(size_t)i * 4];
    __nv_bfloat16 h0, h1, h2, h3, l0, l1, l2, l3;
    split1(v.x, h0, l0); split1(v.y, h1, l1);
    split1(v.z, h2, l2); split1(v.w, h3, l3);
    *(uint2*)&oh[(size_t)i * 4] = make_uint2(pack2(h0, h1), pack2(h2, h3));
    *(uint2*)&ol[(size_t)i * 4] = make_uint2(pack2(l0, l1), pack2(l2, l3));
}

// ---------------------------------------------------------------------------
// Weight transpose+split: W[K][N] fp32 -> Th[N][K], Tl[N][K] bf16
// ---------------------------------------------------------------------------
__global__ void wsplit_kernel(const float* __restrict__ W,
                              __nv_bfloat16* __restrict__ Th,
                              __nv_bfloat16* __restrict__ Tl, int K, int N)
{
    __shared__ float t[32][33];
    const int tx = threadIdx.x & 31;
    const int ty = threadIdx.x >> 5;       // 0..7
    const int n0 = blockIdx.x * 32;
    const int k0 = blockIdx.y * 32;
#pragma unroll
    for (int j = 0; j < 4; j++)
        t[ty + j * 8][tx] = W[(size_t)(k0 + ty + j * 8) * N + n0 + tx];
    __syncthreads();
#pragma unroll
    for (int j = 0; j < 4; j++) {
        const float v = t[tx][ty + j * 8];
        __nv_bfloat16 h, l;
        split1(v, h, l);
        const size_t o = (size_t)(n0 + ty + j * 8) * K + k0 + tx;
        Th[o] = h; Tl[o] = l;
    }
}

// ---------------------------------------------------------------------------
// Tensor GEMM: C[M,N] = A[M,K] @ Bt[N,K]^T  (A, Bt pre-split bf16 planes)
// Tile 128x128, BK=32, 256 threads (8 warps, 4x2), warp tile 32x64.
// cp.async 2-stage pipeline. Out: fp32 C, or bf16 hi/lo planes (SPLIT_OUT).
// ---------------------------------------------------------------------------
constexpr int GST      = 40;                 // smem row stride (bf16)
constexpr int G_OFF_AH = 0;                  // byte offsets within a stage
constexpr int G_OFF_AL = 128 * GST * 2;      // 10240
constexpr int G_OFF_BH = 2 * 128 * GST * 2;  // 20480
constexpr int G_OFF_BL = 3 * 128 * GST * 2;  // 30720
constexpr int G_STAGE  = 4 * 128 * GST * 2;  // 40960 bytes
constexpr int G_SMEM   = 2 * G_STAGE;        // 81920 bytes

template<bool SPLIT_OUT>
__global__ __launch_bounds__(256, 2)
void tgemm_kernel(const __nv_bfloat16* __restrict__ Ah_g,
                  const __nv_bfloat16* __restrict__ Al_g,
                  const __nv_bfloat16* __restrict__ Bh_g,
                  const __nv_bfloat16* __restrict__ Bl_g,
                  float* __restrict__ C,
                  __nv_bfloat16* __restrict__ Ch,
                  __nv_bfloat16* __restrict__ Cl,
                  int M, int N, int K)
{
    extern __shared__ char smc[];
    const uint32_t sb0 = smem_u32(smc);

    const int tid  = threadIdx.x;
    const int warp = tid >> 5;
    const int lane = tid & 31;
    const int wr   = warp >> 1;          // 0..3
    const int wc   = warp & 1;           // 0..1
    const int row0 = blockIdx.y * 128;
    const int col0 = blockIdx.x * 128;

    // copy mapping: 512 16B-chunks per plane; thread covers 2 per plane
    const int cr  = tid >> 2;            // +128*i : row 0..127 over i<2? no: s= tid+i*256
    (void)cr;

    auto issue_chunk = [&](int ch, int st) {
        const int k0 = ch << 5;
        const uint32_t sb = sb0 + st * G_STAGE;
#pragma unroll
        for (int i = 0; i < 2; i++) {
            const int s  = tid + i * 256;      // 0..511
            const int r  = s >> 2;             // 0..127
            const int kc = (s & 3) * 8;        // bf16 offset 0,8,16,24
            const uint32_t d = r * (GST * 2) + kc * 2;
            CP16(sb + G_OFF_AH + d, &Ah_g[(size_t)(row0 + r) * K + k0 + kc]);
            CP16(sb + G_OFF_AL + d, &Al_g[(size_t)(row0 + r) * K + k0 + kc]);
            const int n = col0 + r;
            const bool pr = n < N;
            const size_t bo = (size_t)(pr ? n : 0) * K + k0 + kc;
            CP16P(sb + G_OFF_BH + d, &Bh_g[bo], pr);
            CP16P(sb + G_OFF_BL + d, &Bl_g[bo], pr);
        }
    };

    float acc[2][8][4];
#pragma unroll
    for (int mf = 0; mf < 2; mf++)
#pragma unroll
        for (int nf = 0; nf < 8; nf++)
#pragma unroll
            for (int r = 0; r < 4; r++) acc[mf][nf][r] = 0.f;

    const int a_row = (lane & 15);
    const int a_col = (lane >> 4) * 8;
    const int b_row = (lane >> 4) * 8 + (lane & 7);
    const int b_col = ((lane >> 3) & 1) * 8;

    auto compute_stage = [&](int st) {
        const uint32_t Ah = sb0 + st * G_STAGE + G_OFF_AH;
        const uint32_t Al = sb0 + st * G_STAGE + G_OFF_AL;
        const uint32_t Bh = sb0 + st * G_STAGE + G_OFF_BH;
        const uint32_t Bl = sb0 + st * G_STAGE + G_OFF_BL;
#pragma unroll
        for (int ks = 0; ks < 32; ks += 16) {
            uint32_t ah[2][4], al[2][4];
#pragma unroll
            for (int mf = 0; mf < 2; mf++) {
                const uint32_t off = ((wr * 32 + mf * 16 + a_row) * GST + ks + a_col) * 2;
                ldmatrix_x4(ah[mf][0], ah[mf][1], ah[mf][2], ah[mf][3], Ah + off);
                ldmatrix_x4(al[mf][0], al[mf][1], al[mf][2], al[mf][3], Al + off);
            }
#pragma unroll
            for (int np = 0; np < 4; np++) {
                uint32_t bh[4], bl[4];
                const uint32_t off = ((wc * 64 + np * 16 + b_row) * GST + ks + b_col) * 2;
                ldmatrix_x4(bh[0], bh[1], bh[2], bh[3], Bh + off);
                ldmatrix_x4(bl[0], bl[1], bl[2], bl[3], Bl + off);
#pragma unroll
                for (int mf = 0; mf < 2; mf++) {
                    mma_bf16(acc[mf][np*2],   ah[mf], bh + 0);
                    mma_bf16(acc[mf][np*2],   ah[mf], bl + 0);
                    mma_bf16(acc[mf][np*2],   al[mf], bh + 0);
                    mma_bf16(acc[mf][np*2+1], ah[mf], bh + 2);
                    mma_bf16(acc[mf][np*2+1], ah[mf], bl + 2);
                    mma_bf16(acc[mf][np*2+1], al[mf], bh + 2);
                }
            }
        }
    };

    const int nch = K >> 5;
    issue_chunk(0, 0);
    CP_COMMIT();
    for (int ch = 0; ch < nch; ch++) {
        if (ch + 1 < nch) {
            issue_chunk(ch + 1, (ch + 1) & 1);
            CP_COMMIT();
            CP_WAIT(1);
        } else {
            CP_WAIT(0);
        }
        __syncthreads();
        compute_stage(ch & 1);
        __syncthreads();
    }

    // epilogue
#pragma unroll
    for (int mf = 0; mf < 2; mf++) {
        const int r0 = row0 + wr * 32 + mf * 16 + (lane >> 2);
#pragma unroll
        for (int nf = 0; nf < 8; nf++) {
            const int c = col0 + wc * 64 + nf * 8 + (lane & 3) * 2;
            if (c < N) {
                if (SPLIT_OUT) {
                    __nv_bfloat16 h0, h1, h2, h3, l0, l1, l2, l3;
                    split1(acc[mf][nf][0], h0, l0); split1(acc[mf][nf][1], h1, l1);
                    split1(acc[mf][nf][2], h2, l2); split1(acc[mf][nf][3], h3, l3);
                    *(uint32_t*)&Ch[(size_t)r0 * N + c]       = pack2(h0, h1);
                    *(uint32_t*)&Cl[(size_t)r0 * N + c]       = pack2(l0, l1);
                    *(uint32_t*)&Ch[(size_t)(r0 + 8) * N + c] = pack2(h2, h3);
                    *(uint32_t*)&Cl[(size_t)(r0 + 8) * N + c] = pack2(l2, l3);
                } else {
                    *(float2*)&C[(size_t)r0 * N + c] =
                        make_float2(acc[mf][nf][0], acc[mf][nf][1]);
                    *(float2*)&C[(size_t)(r0 + 8) * N + c] =
                        make_float2(acc[mf][nf][2], acc[mf][nf][3]);
                }
            }
        }
    }
}

// ---------------------------------------------------------------------------
// RMSNorm -> bf16 hi/lo planes
// ---------------------------------------------------------------------------
__global__ void rmsnorm_split_kernel(const float* __restrict__ in,
                                     const float* __restrict__ w,
                                     __nv_bfloat16* __restrict__ oh,
                                     __nv_bfloat16* __restrict__ ol,
                                     int dim, int istride)
{
    const int row = blockIdx.x;
    const float* x = in + (size_t)row * istride;
    float ss = 0.f;
    for (int i = threadIdx.x; i < dim; i += blockDim.x) { float v = x[i]; ss += v * v; }
#pragma unroll
    for (int o = 16; o > 0; o >>= 1) ss += __shfl_xor_sync(0xffffffffu, ss, o);
    __shared__ float sh[8];
    __shared__ float s_inv;
    if ((threadIdx.x & 31) == 0) sh[threadIdx.x >> 5] = ss;
    __syncthreads();
    if (threadIdx.x == 0) {
        float t = 0.f;
        const int nw = blockDim.x >> 5;
        for (int i = 0; i < nw; i++) t += sh[i];
        s_inv = rsqrtf(t / (float)dim + 1e-5f);
    }
    __syncthreads();
    const float inv = s_inv;
    for (int i = threadIdx.x; i < dim; i += blockDim.x) {
        const float y = x[i] * inv * w[i];
        __nv_bfloat16 h, l;
        split1(y, h, l);
        oh[(size_t)row * dim + i] = h;
        ol[(size_t)row * dim + i] = l;
    }
}

// ---------------------------------------------------------------------------
// RoPE on planes: q planes in-place (rope dims), ckv tail -> krot planes
// ---------------------------------------------------------------------------
__global__ void rope_kernel(__nv_bfloat16* __restrict__ qh, __nv_bfloat16* __restrict__ ql,
                            const float* __restrict__ ckv,
                            __nv_bfloat16* __restrict__ krh, __nv_bfloat16* __restrict__ krl,
                            const float* __restrict__ cosb, const float* __restrict__ sinb)
{
    const int token = blockIdx.x;
    const int s = token & (SEQ - 1);
    for (int i = threadIdx.x; i < (NHEAD + 1) * 32; i += blockDim.x) {
        const int h = i >> 5;
        const int d = i & 31;
        const float c  = cosb[s * ROPE_D + d];
        const float sn = sinb[s * ROPE_D + d];
        if (h < NHEAD) {
            const size_t base = (size_t)token * QD_ALL + h * QK_D + NOPE_D;
            const size_t pi   = base + ((d < 16) ? d + 16 : d - 16);
            const float x  = __bfloat162float(qh[base + d]) + __bfloat162float(ql[base + d]);
            float pr = __bfloat162float(qh[pi]) + __bfloat162float(ql[pi]);
            if (d < 16) pr = -pr;
            __syncwarp();
            __nv_bfloat16 hh, ll;
            split1(x * c + pr * sn, hh, ll);
            qh[base + d] = hh;
            ql[base + d] = ll;
        } else {
            const float* kb = ckv + (size_t)token * CKV_D + KV_RANK;
            const float x  = kb[d];
            const float pr = (d < 16) ? -kb[d + 16] : kb[d - 16];
            __nv_bfloat16 hh, ll;
            split1(x * c + pr * sn, hh, ll);
            krh[(size_t)token * ROPE_D + d] = hh;
            krl[(size_t)token * ROPE_D + d] = ll;
        }
    }
}

// ---------------------------------------------------------------------------
// Flash attention on pre-split planes. BQ=128, BK=64, 256 threads, 8 warps.
// ---------------------------------------------------------------------------
constexpr int AQ_ST = 104;
constexpr int AV_ST = 72;
constexpr int A_QT  = 128 * AQ_ST;
constexpr int A_KT  = 64 * AQ_ST;
constexpr int A_VT  = 64 * AV_ST;
constexpr int ATTN_SMEM = (2*A_QT + 2*A_KT + 2*A_VT) * (int)sizeof(__nv_bfloat16);

__global__ __launch_bounds__(256, 2)
void attn_mma_kernel(const __nv_bfloat16* __restrict__ qh, const __nv_bfloat16* __restrict__ ql,
                     const __nv_bfloat16* __restrict__ kvh, const __nv_bfloat16* __restrict__ kvl,
                     const __nv_bfloat16* __restrict__ krh, const __nv_bfloat16* __restrict__ krl,
                     __nv_bfloat16* __restrict__ oh, __nv_bfloat16* __restrict__ ol)
{
    extern __shared__ __nv_bfloat16 smb[];
    const uint32_t uQh = smem_u32(smb);
    const uint32_t uQl = uQh + A_QT * 2;
    const uint32_t uKh = uQl + A_QT * 2;
    const uint32_t uKl = uKh + A_KT * 2;
    const uint32_t uVh = uKl + A_KT * 2;
    const uint32_t uVl = uVh + A_VT * 2;

    const int bh = blockIdx.y;
    const int b  = bh / NHEAD;
    const int h  = bh % NHEAD;
    const int qt = blockIdx.x;
    const int q0 = qt * 128;
    const int tid  = threadIdx.x;
    const int warp = tid >> 5;
    const int lane = tid & 31;
    const int gr   = lane >> 2;
    const int qd   = lane & 3;
    const size_t tok0 = (size_t)b * SEQ;

    const int a_row = (lane & 15);
    const int a_col = (lane >> 4) * 8;
    const int b_row = (lane >> 4) * 8 + (lane & 7);
    const int b_col = ((lane >> 3) & 1) * 8;
    const int v_row = (lane & 15);
    const int v_col = (lane >> 4) * 8;

    // ---- Q tile copy (128 x 96 both planes) via cp.async ----
#pragma unroll
    for (int i = 0; i < 6; i++) {
        const int s  = tid + i * 256;          // 0..1535
        const int r  = s / 12;
        const int c8 = (s - r * 12) * 8;
        const size_t src = (tok0 + q0 + r) * QD_ALL + h * QK_D + c8;
        const uint32_t d = (r * AQ_ST + c8) * 2;
        CP16(uQh + d, &qh[src]);
        CP16(uQl + d, &ql[src]);
    }
    CP_COMMIT();

    float oacc[8][4];
#pragma unroll
    for (int nf = 0; nf < 8; nf++)
#pragma unroll
        for (int r = 0; r < 4; r++) oacc[nf][r] = 0.f;
    float mA = -1e30f, mB = -1e30f, lA = 0.f, lB = 0.f;

    const int q0w  = q0 + warp * 16;
    const int rowA = q0w + gr;
    const int rowB = rowA + 8;
    const int nkt  = 2 * qt + 2;

    for (int kt = 0; kt < nkt; kt++) {
        const int k0 = kt * 64;
        __syncthreads();   // prior compute done reading K/V
        // ---- K tile: 64 x (64 nope + 32 rope), both planes ----
#pragma unroll
        for (int i = 0; i < 3; i++) {
            const int s = tid + i * 256;       // 0..767
            int r, c8;
            size_t srch, srcl;
            if (s < 512) {
                r = s >> 3; c8 = (s & 7) * 8;
                srch = (tok0 + k0 + r) * KVD_ALL + h * 128 + c8;
                CP16(uKh + (r * AQ_ST + c8) * 2, &kvh[srch]);
                CP16(uKl + (r * AQ_ST + c8) * 2, &kvl[srch]);
            } else {
                const int t = s - 512;
                r = t >> 2; c8 = 64 + (t & 3) * 8;
                srcl = (tok0 + k0 + r) * ROPE_D + (c8 - 64);
                CP16(uKh + (r * AQ_ST + c8) * 2, &krh[srcl]);
                CP16(uKl + (r * AQ_ST + c8) * 2, &krl[srcl]);
            }
        }
        // ---- V tile: 64 x 64, both planes ----
#pragma unroll
        for (int i = 0; i < 2; i++) {
            const int s = tid + i * 256;       // 0..511
            const int r = s >> 3;
            const int c8 = (s & 7) * 8;
            const size_t src = (tok0 + k0 + r) * KVD_ALL + h * 128 + 64 + c8;
            CP16(uVh + (r * AV_ST + c8) * 2, &kvh[src]);
            CP16(uVl + (r * AV_ST + c8) * 2, &kvl[src]);
        }
        CP_COMMIT();
        CP_WAIT(0);
        __syncthreads();

        // ---- S = Q @ K^T ----
        float sa[8][4];
#pragma unroll
        for (int nf = 0; nf < 8; nf++)
#pragma unroll
            for (int r = 0; r < 4; r++) sa[nf][r] = 0.f;

#pragma unroll
        for (int ks = 0; ks < 96; ks += 16) {
            uint32_t ah[4], al[4];
            const uint32_t aoff = ((warp * 16 + a_row) * AQ_ST + ks + a_col) * 2;
            ldmatrix_x4(ah[0], ah[1], ah[2], ah[3], uQh + aoff);
            ldmatrix_x4(al[0], al[1], al[2], al[3], uQl + aoff);
#pragma unroll
            for (int np = 0; np < 4; np++) {
                uint32_t bhf[4], blf[4];
                const uint32_t boff = ((np * 16 + b_row) * AQ_ST + ks + b_col) * 2;
                ldmatrix_x4(bhf[0], bhf[1], bhf[2], bhf[3], uKh + boff);
                ldmatrix_x4(blf[0], blf[1], blf[2], blf[3], uKl + boff);
                mma_bf16(sa[np*2],   ah, bhf + 0);
                mma_bf16(sa[np*2],   ah, blf + 0);
                mma_bf16(sa[np*2],   al, bhf + 0);
                mma_bf16(sa[np*2+1], ah, bhf + 2);
                mma_bf16(sa[np*2+1], ah, blf + 2);
                mma_bf16(sa[np*2+1], al, bhf + 2);
            }
        }

#pragma unroll
        for (int nf = 0; nf < 8; nf++)
#pragma unroll
            for (int r = 0; r < 4; r++) sa[nf][r] *= SC2;
        if (k0 + 63 > q0w) {
#pragma unroll
            for (int nf = 0; nf < 8; nf++) {
                const int col = k0 + nf * 8 + qd * 2;
                if (col     > rowA) sa[nf][0] = -1e30f;
                if (col + 1 > rowA) sa[nf][1] = -1e30f;
                if (col     > rowB) sa[nf][2] = -1e30f;
                if (col + 1 > rowB) sa[nf][3] = -1e30f;
            }
        }

        float mxA = -1e30f, mxB = -1e30f;
#pragma unroll
        for (int nf = 0; nf < 8; nf++) {
            mxA = fmaxf(mxA, fmaxf(sa[nf][0], sa[nf][1]));
            mxB = fmaxf(mxB, fmaxf(sa[nf][2], sa[nf][3]));
        }
        mxA = fmaxf(mxA, __shfl_xor_sync(0xffffffffu, mxA, 1));
        mxA = fmaxf(mxA, __shfl_xor_sync(0xffffffffu, mxA, 2));
        mxB = fmaxf(mxB, __shfl_xor_sync(0xffffffffu, mxB, 1));
        mxB = fmaxf(mxB, __shfl_xor_sync(0xffffffffu, mxB, 2));
        const float mnA = fmaxf(mA, mxA);
        const float mnB = fmaxf(mB, mxB);
        const float alA = fexp2(mA - mnA);
        const float alB = fexp2(mB - mnB);
        mA = mnA; mB = mnB;

        float rsA = 0.f, rsB = 0.f;
#pragma unroll
        for (int nf = 0; nf < 8; nf++) {
            sa[nf][0] = fexp2(sa[nf][0] - mnA); rsA += sa[nf][0];
            sa[nf][1] = fexp2(sa[nf][1] - mnA); rsA += sa[nf][1];
            sa[nf][2] = fexp2(sa[nf][2] - mnB); rsB += sa[nf][2];
            sa[nf][3] = fexp2(sa[nf][3] - mnB); rsB += sa[nf][3];
        }
        rsA += __shfl_xor_sync(0xffffffffu, rsA, 1);
        rsA += __shfl_xor_sync(0xffffffffu, rsA, 2);
        rsB += __shfl_xor_sync(0xffffffffu, rsB, 1);
        rsB += __shfl_xor_sync(0xffffffffu, rsB, 2);
        lA = lA * alA + rsA;
        lB = lB * alB + rsB;
#pragma unroll
        for (int nf = 0; nf < 8; nf++) {
            oacc[nf][0] *= alA; oacc[nf][1] *= alA;
            oacc[nf][2] *= alB; oacc[nf][3] *= alB;
        }

        // ---- O += P @ V ----
#pragma unroll
        for (int t = 0; t < 4; t++) {
            uint32_t ph[4], pl[4];
#pragma unroll
            for (int half = 0; half < 2; half++) {
                const int nf = 2 * t + half;
                __nv_bfloat16 h0, h1, h2, h3, l0, l1, l2, l3;
                split1(sa[nf][0], h0, l0); split1(sa[nf][1], h1, l1);
                split1(sa[nf][2], h2, l2); split1(sa[nf][3], h3, l3);
                ph[half*2]   = pack2(h0, h1); pl[half*2]   = pack2(l0, l1);
                ph[half*2+1] = pack2(h2, h3); pl[half*2+1] = pack2(l2, l3);
            }
#pragma unroll
            for (int np = 0; np < 4; np++) {
                uint32_t vhf[4], vlf[4];
                const uint32_t voff = ((t * 16 + v_row) * AV_ST + np * 16 + v_col) * 2;
                ldmatrix_x4_t(vhf[0], vhf[1], vhf[2], vhf[3], uVh + voff);
                ldmatrix_x4_t(vlf[0], vlf[1], vlf[2], vlf[3], uVl + voff);
                mma_bf16(oacc[np*2],   ph, vhf + 0);
                mma_bf16(oacc[np*2],   ph, vlf + 0);
                mma_bf16(oacc[np*2],   pl, vhf + 0);
                mma_bf16(oacc[np*2+1], ph, vhf + 2);
                mma_bf16(oacc[np*2+1], ph, vlf + 2);
                mma_bf16(oacc[np*2+1], pl, vhf + 2);
            }
        }
    }

    // ---- finalize + write split planes ----
    const float invA = 1.f / lA;
    const float invB = 1.f / lB;
#pragma unroll
    for (int nf = 0; nf < 8; nf++) {
        const int col = h * V_D + nf * 8 + qd * 2;
        __nv_bfloat16 h0, h1, l0, l1;
        split1(oacc[nf][0] * invA, h0, l0);
        split1(oacc[nf][1] * invA, h1, l1);
        *(uint32_t*)&oh[(tok0 + rowA) * (size_t)OD_ALL + col] = pack2(h0, h1);
        *(uint32_t*)&ol[(tok0 + rowA) * (size_t)OD_ALL + col] = pack2(l0, l1);
        split1(oacc[nf][2] * invB, h0, l0);
        split1(oacc[nf][3] * invB, h1, l1);
        *(uint32_t*)&oh[(tok0 + rowB) * (size_t)OD_ALL + col] = pack2(h0, h1);
        *(uint32_t*)&ol[(tok0 + rowB) * (size_t)OD_ALL + col] = pack2(l0, l1);
    }
}

// ---------------------------------------------------------------------------
// Launch
// ---------------------------------------------------------------------------
extern "C" void kernel_launch(void* const* d_in, const int* in_sizes, int n_in,
                              void* d_out, int out_size)
{
    const float* hidden = (const float*)d_in[0];
    const float* cosb   = (const float*)d_in[1];
    const float* sinb   = (const float*)d_in[2];
    const float* wq_a   = (const float*)d_in[3];
    const float* q_ln   = (const float*)d_in[4];
    const float* wq_b   = (const float*)d_in[5];
    const float* wkv_a  = (const float*)d_in[6];
    const float* kv_ln  = (const float*)d_in[7];
    const float* wkv_b  = (const float*)d_in[8];
    const float* wo     = (const float*)d_in[9];
    float* out = (float*)d_out;

    __nv_bfloat16 *hidh, *hidl, *wqah, *wqal, *wkvah, *wkval, *wqbh, *wqbl,
                  *wkvbh, *wkvbl, *woh, *wol, *qanh, *qanl, *kvnh, *kvnl,
                  *qhp, *qlp, *kvhp, *kvlp, *krhp, *krlp, *ath, *atl;
    float *qa, *ckv;
    cudaGetSymbolAddress((void**)&hidh,  g_hid_h);  cudaGetSymbolAddress((void**)&hidl,  g_hid_l);
    cudaGetSymbolAddress((void**)&wqah,  g_wqa_h);  cudaGetSymbolAddress((void**)&wqal,  g_wqa_l);
    cudaGetSymbolAddress((void**)&wkvah, g_wkva_h); cudaGetSymbolAddress((void**)&wkval, g_wkva_l);
    cudaGetSymbolAddress((void**)&wqbh,  g_wqb_h);  cudaGetSymbolAddress((void**)&wqbl,  g_wqb_l);
    cudaGetSymbolAddress((void**)&wkvbh, g_wkvb_h); cudaGetSymbolAddress((void**)&wkvbl, g_wkvb_l);
    cudaGetSymbolAddress((void**)&woh,   g_wo_h);   cudaGetSymbolAddress((void**)&wol,   g_wo_l);
    cudaGetSymbolAddress((void**)&qa,    g_qa);     cudaGetSymbolAddress((void**)&ckv,   g_ckv);
    cudaGetSymbolAddress((void**)&qanh,  g_qan_h);  cudaGetSymbolAddress((void**)&qanl,  g_qan_l);
    cudaGetSymbolAddress((void**)&kvnh,  g_kvn_h);  cudaGetSymbolAddress((void**)&kvnl,  g_kvn_l);
    cudaGetSymbolAddress((void**)&qhp,   g_q_h);    cudaGetSymbolAddress((void**)&qlp,   g_q_l);
    cudaGetSymbolAddress((void**)&kvhp,  g_kv_h);   cudaGetSymbolAddress((void**)&kvlp,  g_kv_l);
    cudaGetSymbolAddress((void**)&krhp,  g_kr_h);   cudaGetSymbolAddress((void**)&krlp,  g_kr_l);
    cudaGetSymbolAddress((void**)&ath,   g_at_h);   cudaGetSymbolAddress((void**)&atl,   g_at_l);

    cudaFuncSetAttribute(tgemm_kernel<false>, cudaFuncAttributeMaxDynamicSharedMemorySize, G_SMEM);
    cudaFuncSetAttribute(tgemm_kernel<true>,  cudaFuncAttributeMaxDynamicSharedMemorySize, G_SMEM);
    cudaFuncSetAttribute(attn_mma_kernel,     cudaFuncAttributeMaxDynamicSharedMemorySize, ATTN_SMEM);

    const dim3 blk(256);
    const int mt = NTOK / 128;

    // presplit hidden + weights
    split_kernel<<<(NTOK * HIDN / 4 + 255) / 256, 256>>>(hidden, hidh, hidl, NTOK * HIDN / 4);
    wsplit_kernel<<<dim3(Q_RANK / 32,  HIDN / 32),  blk>>>(wq_a,  wqah,  wqal,  HIDN,  Q_RANK);
    wsplit_kernel<<<dim3(CKV_D / 32,   HIDN / 32),  blk>>>(wkv_a, wkvah, wkval, HIDN,  CKV_D);
    wsplit_kernel<<<dim3(QD_ALL / 32,  Q_RANK / 32),blk>>>(wq_b,  wqbh,  wqbl,  Q_RANK, QD_ALL);
    wsplit_kernel<<<dim3(KVD_ALL / 32, KV_RANK / 32),blk>>>(wkv_b, wkvbh, wkvbl, KV_RANK, KVD_ALL);
    wsplit_kernel<<<dim3(OD_ALL / 32,  HIDN / 32),  blk>>>(wo,    woh,   wol,   HIDN,  OD_ALL);

    // qa = hidden @ wq_a ; ckv = hidden @ wkv_a
    tgemm_kernel<false><<<dim3(Q_RANK / 128, mt), blk, G_SMEM>>>(
        hidh, hidl, wqah, wqal, qa, nullptr, nullptr, NTOK, Q_RANK, HIDN);
    tgemm_kernel<false><<<dim3((CKV_D + 127) / 128, mt), blk, G_SMEM>>>(
        hidh, hidl, wkvah, wkval, ckv, nullptr, nullptr, NTOK, CKV_D, HIDN);
    // rmsnorms -> planes
    rmsnorm_split_kernel<<<NTOK, 256>>>(qa, q_ln, qanh, qanl, Q_RANK, Q_RANK);
    rmsnorm_split_kernel<<<NTOK, 256>>>(ckv, kv_ln, kvnh, kvnl, KV_RANK, CKV_D);
    // q = qan @ wq_b (split out), kv = kvn @ wkv_b (split out)
    tgemm_kernel<true><<<dim3(QD_ALL / 128, mt), blk, G_SMEM>>>(
        qanh, qanl, wqbh, wqbl, nullptr, qhp, qlp, NTOK, QD_ALL, Q_RANK);
    tgemm_kernel<true><<<dim3(KVD_ALL / 128, mt), blk, G_SMEM>>>(
        kvnh, kvnl, wkvbh, wkvbl, nullptr, kvhp, kvlp, NTOK, KVD_ALL, KV_RANK);
    // rope (q planes in place, krot planes)
    rope_kernel<<<NTOK, 256>>>(qhp, qlp, ckv, krhp, krlp, cosb, sinb);
    // attention -> planes
    attn_mma_kernel<<<dim3(SEQ / 128, 2 * NHEAD), blk, ATTN_SMEM>>>(
        qhp, qlp, kvhp, kvlp, krhp, krlp, ath, atl);
    // out = attn @ wo
    tgemm_kernel<false><<<dim3(HIDN / 128, mt), blk, G_SMEM>>>(
        ath, atl, woh, wol, out, nullptr, nullptr, NTOK, HIDN, OD_ALL);
}

// round 6
// speedup vs baseline: 3.1757x; 1.0539x over previous
#include <cuda_runtime.h>
#include <cuda_bf16.h>
#include <cstdint>

// ---------------------------------------------------------------------------
// Problem constants
// ---------------------------------------------------------------------------
constexpr int SEQ    = 2048;
constexpr int HIDN   = 2560;
constexpr int NHEAD  = 40;
constexpr int NOPE_D = 64;
constexpr int ROPE_D = 32;
constexpr int QK_D   = NOPE_D + ROPE_D;    // 96
constexpr int V_D    = 64;
constexpr int Q_RANK = 768;
constexpr int KV_RANK= 256;
constexpr int CKV_D  = KV_RANK + ROPE_D;   // 288
constexpr int NTOK   = 2 * SEQ;            // 4096
constexpr int QD_ALL = NHEAD * QK_D;       // 3840
constexpr int KVD_ALL= NHEAD * (NOPE_D + V_D); // 5120
constexpr int OD_ALL = NHEAD * V_D;        // 2560
constexpr float SCALE = 0.10206207261596577f;
constexpr float SC2   = SCALE * 1.4426950408889634f;

// ---------------------------------------------------------------------------
// Scratch (static device arrays)
// ---------------------------------------------------------------------------
__device__ __nv_bfloat16 g_hid_h [NTOK * HIDN];
__device__ __nv_bfloat16 g_hid_l [NTOK * HIDN];
__device__ __nv_bfloat16 g_wqa_h [Q_RANK * HIDN];     // transposed [N][K]
__device__ __nv_bfloat16 g_wqa_l [Q_RANK * HIDN];
__device__ __nv_bfloat16 g_wkva_h[CKV_D * HIDN];
__device__ __nv_bfloat16 g_wkva_l[CKV_D * HIDN];
__device__ __nv_bfloat16 g_wqb_h [QD_ALL * Q_RANK];
__device__ __nv_bfloat16 g_wqb_l [QD_ALL * Q_RANK];
__device__ __nv_bfloat16 g_wkvb_h[KVD_ALL * KV_RANK];
__device__ __nv_bfloat16 g_wkvb_l[KVD_ALL * KV_RANK];
__device__ __nv_bfloat16 g_wo_h  [HIDN * OD_ALL];
__device__ __nv_bfloat16 g_wo_l  [HIDN * OD_ALL];
__device__ float         g_qa    [NTOK * Q_RANK];
__device__ float         g_ckv   [NTOK * CKV_D];
__device__ __nv_bfloat16 g_qan_h [NTOK * Q_RANK];
__device__ __nv_bfloat16 g_qan_l [NTOK * Q_RANK];
__device__ __nv_bfloat16 g_kvn_h [NTOK * KV_RANK];
__device__ __nv_bfloat16 g_kvn_l [NTOK * KV_RANK];
__device__ __nv_bfloat16 g_q_h   [NTOK * QD_ALL];
__device__ __nv_bfloat16 g_q_l   [NTOK * QD_ALL];
__device__ __nv_bfloat16 g_kv_h  [NTOK * KVD_ALL];
__device__ __nv_bfloat16 g_kv_l  [NTOK * KVD_ALL];
__device__ __nv_bfloat16 g_kr_h  [NTOK * ROPE_D];
__device__ __nv_bfloat16 g_kr_l  [NTOK * ROPE_D];
__device__ __nv_bfloat16 g_at_h  [NTOK * OD_ALL];
__device__ __nv_bfloat16 g_at_l  [NTOK * OD_ALL];

// ---------------------------------------------------------------------------
// PTX helpers (portable sm_80+ subset)
// ---------------------------------------------------------------------------
__device__ __forceinline__ uint32_t smem_u32(const void* p) {
    uint32_t a;
    asm("{ .reg .u64 t; cvta.to.shared.u64 t, %1; cvt.u32.u64 %0, t; }"
        : "=r"(a) : "l"(p));
    return a;
}
__device__ __forceinline__ void ldmatrix_x4(uint32_t& r0, uint32_t& r1,
                                            uint32_t& r2, uint32_t& r3, uint32_t addr) {
    asm volatile("ldmatrix.sync.aligned.m8n8.x4.shared.b16 {%0,%1,%2,%3}, [%4];"
                 : "=r"(r0), "=r"(r1), "=r"(r2), "=r"(r3) : "r"(addr));
}
__device__ __forceinline__ void ldmatrix_x4_t(uint32_t& r0, uint32_t& r1,
                                              uint32_t& r2, uint32_t& r3, uint32_t addr) {
    asm volatile("ldmatrix.sync.aligned.m8n8.x4.trans.shared.b16 {%0,%1,%2,%3}, [%4];"
                 : "=r"(r0), "=r"(r1), "=r"(r2), "=r"(r3) : "r"(addr));
}
__device__ __forceinline__ void mma_bf16(float* c, const uint32_t* a, const uint32_t* b) {
    asm volatile(
        "mma.sync.aligned.m16n8k16.row.col.f32.bf16.bf16.f32 "
        "{%0,%1,%2,%3}, {%4,%5,%6,%7}, {%8,%9}, {%0,%1,%2,%3};"
        : "+f"(c[0]), "+f"(c[1]), "+f"(c[2]), "+f"(c[3])
        : "r"(a[0]), "r"(a[1]), "r"(a[2]), "r"(a[3]), "r"(b[0]), "r"(b[1]));
}
#define CP16(dst, src) \
    asm volatile("cp.async.cg.shared.global [%0], [%1], 16;" :: "r"(dst), "l"(src))
#define CP16P(dst, src, pred) \
    asm volatile("cp.async.cg.shared.global [%0], [%1], 16, %2;" \
                 :: "r"(dst), "l"(src), "r"((pred) ? 16 : 0))
#define CP_COMMIT() asm volatile("cp.async.commit_group;" ::: "memory")
#define CP_WAIT(n)  asm volatile("cp.async.wait_group %0;" :: "n"(n) : "memory")

__device__ __forceinline__ uint32_t pack2(__nv_bfloat16 a, __nv_bfloat16 b) {
    return ((uint32_t)__bfloat16_as_ushort(b) << 16) | (uint32_t)__bfloat16_as_ushort(a);
}
__device__ __forceinline__ void split1(float x, __nv_bfloat16& h, __nv_bfloat16& l) {
    h = __float2bfloat16(x);
    l = __float2bfloat16(x - __bfloat162float(h));
}
// Fast pair split: hi = truncate-to-bf16 (bit mask), lo = rounded remainder.
// hp = packed hi pair, lp = packed lo pair. Captures 16 mantissa bits.
__device__ __forceinline__ void split2(float x0, float x1, uint32_t& hp, uint32_t& lp) {
    const uint32_t b0 = __float_as_uint(x0), b1 = __float_as_uint(x1);
    hp = __byte_perm(b0, b1, 0x7632);
    const float l0 = x0 - __uint_as_float(b0 & 0xFFFF0000u);
    const float l1 = x1 - __uint_as_float(b1 & 0xFFFF0000u);
    asm("cvt.rn.bf16x2.f32 %0, %1, %2;" : "=r"(lp) : "f"(l1), "f"(l0));
}
// exp2 via MUFU (masked scores -1e30 underflow to 0 naturally)
__device__ __forceinline__ float fexp2(float x) {
    float r;
    asm("ex2.approx.ftz.f32 %0, %1;" : "=f"(r) : "f"(x));
    return r;
}

// ---------------------------------------------------------------------------
// Elementwise split: fp32 -> bf16 hi/lo planes
// ---------------------------------------------------------------------------
__global__ void split_kernel(const float* __restrict__ in,
                             __nv_bfloat16* __restrict__ oh,
                             __nv_bfloat16* __restrict__ ol, int n4)
{
    const int i = blockIdx.x * blockDim.x + threadIdx.x;
    if (i >= n4) return;
    const float4 v = *(const float4*)&in[(size_t)i * 4];
    uint2 hp, lp;
    split2(v.x, v.y, hp.x, lp.x);
    split2(v.z, v.w, hp.y, lp.y);
    *(uint2*)&oh[(size_t)i * 4] = hp;
    *(uint2*)&ol[(size_t)i * 4] = lp;
}

// ---------------------------------------------------------------------------
// All-weights transpose+split in ONE launch: W[K][N] fp32 -> Th/Tl[N][K] bf16
// ---------------------------------------------------------------------------
__global__ void wsplit_all_kernel(const float* __restrict__ wqa,
                                  const float* __restrict__ wkva,
                                  const float* __restrict__ wqb,
                                  const float* __restrict__ wkvb,
                                  const float* __restrict__ wo)
{
    const int bid = blockIdx.x;
    const float* W; __nv_bfloat16 *Th, *Tl; int K, N, nx, t;
    if (bid < 1920)      { t = bid;        W=wqa;  Th=g_wqa_h;  Tl=g_wqa_l;  K=HIDN;    N=Q_RANK;  nx=24; }
    else if (bid < 2640) { t = bid-1920;   W=wkva; Th=g_wkva_h; Tl=g_wkva_l; K=HIDN;    N=CKV_D;   nx=9; }
    else if (bid < 5520) { t = bid-2640;   W=wqb;  Th=g_wqb_h;  Tl=g_wqb_l;  K=Q_RANK;  N=QD_ALL;  nx=120; }
    else if (bid < 6800) { t = bid-5520;   W=wkvb; Th=g_wkvb_h; Tl=g_wkvb_l; K=KV_RANK; N=KVD_ALL; nx=160; }
    else                 { t = bid-6800;   W=wo;   Th=g_wo_h;   Tl=g_wo_l;   K=HIDN;    N=OD_ALL;  nx=80; }
    const int n0 = (t % nx) * 32;
    const int k0 = (t / nx) * 32;

    __shared__ float tt[32][33];
    const int tx = threadIdx.x & 31;
    const int ty = threadIdx.x >> 5;       // 0..7
#pragma unroll
    for (int j = 0; j < 4; j++)
        tt[ty + j * 8][tx] = W[(size_t)(k0 + ty + j * 8) * N + n0 + tx];
    __syncthreads();
#pragma unroll
    for (int j = 0; j < 4; j++) {
        const float v = tt[tx][ty + j * 8];
        __nv_bfloat16 h, l;
        split1(v, h, l);
        const size_t o = (size_t)(n0 + ty + j * 8) * K + k0 + tx;
        Th[o] = h; Tl[o] = l;
    }
}

// ---------------------------------------------------------------------------
// Tensor GEMM: C[M,N] = A[M,K] @ Bt[N,K]^T  (A, Bt pre-split bf16 planes)
// Tile 128x128, BK=32, 256 threads (8 warps, 4x2), warp tile 32x64.
// cp.async 2-stage pipeline. Out: fp32 C, or bf16 hi/lo planes (SPLIT_OUT).
// ---------------------------------------------------------------------------
constexpr int GST      = 40;
constexpr int G_OFF_AH = 0;
constexpr int G_OFF_AL = 128 * GST * 2;
constexpr int G_OFF_BH = 2 * 128 * GST * 2;
constexpr int G_OFF_BL = 3 * 128 * GST * 2;
constexpr int G_STAGE  = 4 * 128 * GST * 2;
constexpr int G_SMEM   = 2 * G_STAGE;

template<bool SPLIT_OUT>
__global__ __launch_bounds__(256, 2)
void tgemm_kernel(const __nv_bfloat16* __restrict__ Ah_g,
                  const __nv_bfloat16* __restrict__ Al_g,
                  const __nv_bfloat16* __restrict__ Bh_g,
                  const __nv_bfloat16* __restrict__ Bl_g,
                  float* __restrict__ C,
                  __nv_bfloat16* __restrict__ Ch,
                  __nv_bfloat16* __restrict__ Cl,
                  int M, int N, int K)
{
    extern __shared__ char smc[];
    const uint32_t sb0 = smem_u32(smc);

    const int tid  = threadIdx.x;
    const int warp = tid >> 5;
    const int lane = tid & 31;
    const int wr   = warp >> 1;
    const int wc   = warp & 1;
    const int row0 = blockIdx.y * 128;
    const int col0 = blockIdx.x * 128;

    auto issue_chunk = [&](int ch, int st) {
        const int k0 = ch << 5;
        const uint32_t sb = sb0 + st * G_STAGE;
#pragma unroll
        for (int i = 0; i < 2; i++) {
            const int s  = tid + i * 256;
            const int r  = s >> 2;
            const int kc = (s & 3) * 8;
            const uint32_t d = r * (GST * 2) + kc * 2;
            CP16(sb + G_OFF_AH + d, &Ah_g[(size_t)(row0 + r) * K + k0 + kc]);
            CP16(sb + G_OFF_AL + d, &Al_g[(size_t)(row0 + r) * K + k0 + kc]);
            const int n = col0 + r;
            const bool pr = n < N;
            const size_t bo = (size_t)(pr ? n : 0) * K + k0 + kc;
            CP16P(sb + G_OFF_BH + d, &Bh_g[bo], pr);
            CP16P(sb + G_OFF_BL + d, &Bl_g[bo], pr);
        }
    };

    float acc[2][8][4];
#pragma unroll
    for (int mf = 0; mf < 2; mf++)
#pragma unroll
        for (int nf = 0; nf < 8; nf++)
#pragma unroll
            for (int r = 0; r < 4; r++) acc[mf][nf][r] = 0.f;

    const int a_row = (lane & 15);
    const int a_col = (lane >> 4) * 8;
    const int b_row = (lane >> 4) * 8 + (lane & 7);
    const int b_col = ((lane >> 3) & 1) * 8;

    auto compute_stage = [&](int st) {
        const uint32_t Ah = sb0 + st * G_STAGE + G_OFF_AH;
        const uint32_t Al = sb0 + st * G_STAGE + G_OFF_AL;
        const uint32_t Bh = sb0 + st * G_STAGE + G_OFF_BH;
        const uint32_t Bl = sb0 + st * G_STAGE + G_OFF_BL;
#pragma unroll
        for (int ks = 0; ks < 32; ks += 16) {
            uint32_t ah[2][4], al[2][4];
#pragma unroll
            for (int mf = 0; mf < 2; mf++) {
                const uint32_t off = ((wr * 32 + mf * 16 + a_row) * GST + ks + a_col) * 2;
                ldmatrix_x4(ah[mf][0], ah[mf][1], ah[mf][2], ah[mf][3], Ah + off);
                ldmatrix_x4(al[mf][0], al[mf][1], al[mf][2], al[mf][3], Al + off);
            }
#pragma unroll
            for (int np = 0; np < 4; np++) {
                uint32_t bh[4], bl[4];
                const uint32_t off = ((wc * 64 + np * 16 + b_row) * GST + ks + b_col) * 2;
                ldmatrix_x4(bh[0], bh[1], bh[2], bh[3], Bh + off);
                ldmatrix_x4(bl[0], bl[1], bl[2], bl[3], Bl + off);
#pragma unroll
                for (int mf = 0; mf < 2; mf++) {
                    mma_bf16(acc[mf][np*2],   ah[mf], bh + 0);
                    mma_bf16(acc[mf][np*2],   ah[mf], bl + 0);
                    mma_bf16(acc[mf][np*2],   al[mf], bh + 0);
                    mma_bf16(acc[mf][np*2+1], ah[mf], bh + 2);
                    mma_bf16(acc[mf][np*2+1], ah[mf], bl + 2);
                    mma_bf16(acc[mf][np*2+1], al[mf], bh + 2);
                }
            }
        }
    };

    const int nch = K >> 5;
    issue_chunk(0, 0);
    CP_COMMIT();
    for (int ch = 0; ch < nch; ch++) {
        if (ch + 1 < nch) {
            issue_chunk(ch + 1, (ch + 1) & 1);
            CP_COMMIT();
            CP_WAIT(1);
        } else {
            CP_WAIT(0);
        }
        __syncthreads();
        compute_stage(ch & 1);
        __syncthreads();
    }

#pragma unroll
    for (int mf = 0; mf < 2; mf++) {
        const int r0 = row0 + wr * 32 + mf * 16 + (lane >> 2);
#pragma unroll
        for (int nf = 0; nf < 8; nf++) {
            const int c = col0 + wc * 64 + nf * 8 + (lane & 3) * 2;
            if (c < N) {
                if (SPLIT_OUT) {
                    uint32_t hp, lp;
                    split2(acc[mf][nf][0], acc[mf][nf][1], hp, lp);
                    *(uint32_t*)&Ch[(size_t)r0 * N + c] = hp;
                    *(uint32_t*)&Cl[(size_t)r0 * N + c] = lp;
                    split2(acc[mf][nf][2], acc[mf][nf][3], hp, lp);
                    *(uint32_t*)&Ch[(size_t)(r0 + 8) * N + c] = hp;
                    *(uint32_t*)&Cl[(size_t)(r0 + 8) * N + c] = lp;
                } else {
                    *(float2*)&C[(size_t)r0 * N + c] =
                        make_float2(acc[mf][nf][0], acc[mf][nf][1]);
                    *(float2*)&C[(size_t)(r0 + 8) * N + c] =
                        make_float2(acc[mf][nf][2], acc[mf][nf][3]);
                }
            }
        }
    }
}

// ---------------------------------------------------------------------------
// RMSNorm -> bf16 hi/lo planes
// ---------------------------------------------------------------------------
__global__ void rmsnorm_split_kernel(const float* __restrict__ in,
                                     const float* __restrict__ w,
                                     __nv_bfloat16* __restrict__ oh,
                                     __nv_bfloat16* __restrict__ ol,
                                     int dim, int istride)
{
    const int row = blockIdx.x;
    const float* x = in + (size_t)row * istride;
    float ss = 0.f;
    for (int i = threadIdx.x; i < dim; i += blockDim.x) { float v = x[i]; ss += v * v; }
#pragma unroll
    for (int o = 16; o > 0; o >>= 1) ss += __shfl_xor_sync(0xffffffffu, ss, o);
    __shared__ float sh[8];
    __shared__ float s_inv;
    if ((threadIdx.x & 31) == 0) sh[threadIdx.x >> 5] = ss;
    __syncthreads();
    if (threadIdx.x == 0) {
        float t = 0.f;
        const int nw = blockDim.x >> 5;
        for (int i = 0; i < nw; i++) t += sh[i];
        s_inv = rsqrtf(t / (float)dim + 1e-5f);
    }
    __syncthreads();
    const float inv = s_inv;
    for (int i = threadIdx.x; i < dim; i += blockDim.x) {
        const float y = x[i] * inv * w[i];
        __nv_bfloat16 h, l;
        split1(y, h, l);
        oh[(size_t)row * dim + i] = h;
        ol[(size_t)row * dim + i] = l;
    }
}

// ---------------------------------------------------------------------------
// RoPE on planes: q planes in-place (rope dims), ckv tail -> krot planes
// ---------------------------------------------------------------------------
__global__ void rope_kernel(__nv_bfloat16* __restrict__ qh, __nv_bfloat16* __restrict__ ql,
                            const float* __restrict__ ckv,
                            __nv_bfloat16* __restrict__ krh, __nv_bfloat16* __restrict__ krl,
                            const float* __restrict__ cosb, const float* __restrict__ sinb)
{
    const int token = blockIdx.x;
    const int s = token & (SEQ - 1);
    for (int i = threadIdx.x; i < (NHEAD + 1) * 32; i += blockDim.x) {
        const int h = i >> 5;
        const int d = i & 31;
        const float c  = cosb[s * ROPE_D + d];
        const float sn = sinb[s * ROPE_D + d];
        if (h < NHEAD) {
            const size_t base = (size_t)token * QD_ALL + h * QK_D + NOPE_D;
            const size_t pi   = base + ((d < 16) ? d + 16 : d - 16);
            const float x  = __bfloat162float(qh[base + d]) + __bfloat162float(ql[base + d]);
            float pr = __bfloat162float(qh[pi]) + __bfloat162float(ql[pi]);
            if (d < 16) pr = -pr;
            __syncwarp();
            __nv_bfloat16 hh, ll;
            split1(x * c + pr * sn, hh, ll);
            qh[base + d] = hh;
            ql[base + d] = ll;
        } else {
            const float* kb = ckv + (size_t)token * CKV_D + KV_RANK;
            const float x  = kb[d];
            const float pr = (d < 16) ? -kb[d + 16] : kb[d - 16];
            __nv_bfloat16 hh, ll;
            split1(x * c + pr * sn, hh, ll);
            krh[(size_t)token * ROPE_D + d] = hh;
            krl[(size_t)token * ROPE_D + d] = ll;
        }
    }
}

// ---------------------------------------------------------------------------
// Flash attention on pre-split planes. BQ=128, BK=64, 256 threads, 8 warps.
// Software pipelined: K(t+1) prefetched during softmax, V(t+1) during next S.
// ---------------------------------------------------------------------------
constexpr int AQ_ST = 104;
constexpr int AV_ST = 72;
constexpr int A_QT  = 128 * AQ_ST;
constexpr int A_KT  = 64 * AQ_ST;
constexpr int A_VT  = 64 * AV_ST;
constexpr int ATTN_SMEM = (2*A_QT + 2*A_KT + 2*A_VT) * (int)sizeof(__nv_bfloat16);

__global__ __launch_bounds__(256, 2)
void attn_mma_kernel(const __nv_bfloat16* __restrict__ qh, const __nv_bfloat16* __restrict__ ql,
                     const __nv_bfloat16* __restrict__ kvh, const __nv_bfloat16* __restrict__ kvl,
                     const __nv_bfloat16* __restrict__ krh, const __nv_bfloat16* __restrict__ krl,
                     __nv_bfloat16* __restrict__ oh, __nv_bfloat16* __restrict__ ol)
{
    extern __shared__ __nv_bfloat16 smb[];
    const uint32_t uQh = smem_u32(smb);
    const uint32_t uQl = uQh + A_QT * 2;
    const uint32_t uKh = uQl + A_QT * 2;
    const uint32_t uKl = uKh + A_KT * 2;
    const uint32_t uVh = uKl + A_KT * 2;
    const uint32_t uVl = uVh + A_VT * 2;

    const int bh = blockIdx.y;
    const int b  = bh / NHEAD;
    const int h  = bh % NHEAD;
    const int qt = blockIdx.x;
    const int q0 = qt * 128;
    const int tid  = threadIdx.x;
    const int warp = tid >> 5;
    const int lane = tid & 31;
    const int gr   = lane >> 2;
    const int qd   = lane & 3;
    const size_t tok0 = (size_t)b * SEQ;

    const int a_row = (lane & 15);
    const int a_col = (lane >> 4) * 8;
    const int b_row = (lane >> 4) * 8 + (lane & 7);
    const int b_col = ((lane >> 3) & 1) * 8;
    const int v_row = (lane & 15);
    const int v_col = (lane >> 4) * 8;

    auto issue_k = [&](int kt) {
        const int k0 = kt * 64;
#pragma unroll
        for (int i = 0; i < 3; i++) {
            const int s = tid + i * 256;
            if (s < 512) {
                const int r = s >> 3, c8 = (s & 7) * 8;
                const size_t src = (tok0 + k0 + r) * KVD_ALL + h * 128 + c8;
                CP16(uKh + (r * AQ_ST + c8) * 2, &kvh[src]);
                CP16(uKl + (r * AQ_ST + c8) * 2, &kvl[src]);
            } else {
                const int t = s - 512;
                const int r = t >> 2, c8 = 64 + (t & 3) * 8;
                const size_t src = (tok0 + k0 + r) * ROPE_D + (c8 - 64);
                CP16(uKh + (r * AQ_ST + c8) * 2, &krh[src]);
                CP16(uKl + (r * AQ_ST + c8) * 2, &krl[src]);
            }
        }
    };
    auto issue_v = [&](int kt) {
        const int k0 = kt * 64;
#pragma unroll
        for (int i = 0; i < 2; i++) {
            const int s = tid + i * 256;
            const int r = s >> 3;
            const int c8 = (s & 7) * 8;
            const size_t src = (tok0 + k0 + r) * KVD_ALL + h * 128 + 64 + c8;
            CP16(uVh + (r * AV_ST + c8) * 2, &kvh[src]);
            CP16(uVl + (r * AV_ST + c8) * 2, &kvl[src]);
        }
    };

    // ---- Q tile copy (128 x 96 both planes) ----
#pragma unroll
    for (int i = 0; i < 6; i++) {
        const int s  = tid + i * 256;
        const int r  = s / 12;
        const int c8 = (s - r * 12) * 8;
        const size_t src = (tok0 + q0 + r) * QD_ALL + h * QK_D + c8;
        const uint32_t d = (r * AQ_ST + c8) * 2;
        CP16(uQh + d, &qh[src]);
        CP16(uQl + d, &ql[src]);
    }
    CP_COMMIT();          // group: Q
    issue_k(0);
    CP_COMMIT();          // group: K0
    issue_v(0);
    CP_COMMIT();          // group: V0

    float oacc[8][4];
#pragma unroll
    for (int nf = 0; nf < 8; nf++)
#pragma unroll
        for (int r = 0; r < 4; r++) oacc[nf][r] = 0.f;
    float mA = -1e30f, mB = -1e30f, lA = 0.f, lB = 0.f;

    const int q0w  = q0 + warp * 16;
    const int rowA = q0w + gr;
    const int rowB = rowA + 8;
    const int nkt  = 2 * qt + 2;

    for (int kt = 0; kt < nkt; kt++) {
        const int k0 = kt * 64;

        CP_WAIT(1);            // K_t (and Q) landed; V_t may be in flight
        __syncthreads();

        // ---- S = Q @ K^T ----
        float sa[8][4];
#pragma unroll
        for (int nf = 0; nf < 8; nf++)
#pragma unroll
            for (int r = 0; r < 4; r++) sa[nf][r] = 0.f;

#pragma unroll
        for (int ks = 0; ks < 96; ks += 16) {
            uint32_t ah[4], al[4];
            const uint32_t aoff = ((warp * 16 + a_row) * AQ_ST + ks + a_col) * 2;
            ldmatrix_x4(ah[0], ah[1], ah[2], ah[3], uQh + aoff);
            ldmatrix_x4(al[0], al[1], al[2], al[3], uQl + aoff);
#pragma unroll
            for (int np = 0; np < 4; np++) {
                uint32_t bhf[4], blf[4];
                const uint32_t boff = ((np * 16 + b_row) * AQ_ST + ks + b_col) * 2;
                ldmatrix_x4(bhf[0], bhf[1], bhf[2], bhf[3], uKh + boff);
                ldmatrix_x4(blf[0], blf[1], blf[2], blf[3], uKl + boff);
                mma_bf16(sa[np*2],   ah, bhf + 0);
                mma_bf16(sa[np*2],   ah, blf + 0);
                mma_bf16(sa[np*2],   al, bhf + 0);
                mma_bf16(sa[np*2+1], ah, bhf + 2);
                mma_bf16(sa[np*2+1], ah, blf + 2);
                mma_bf16(sa[np*2+1], al, bhf + 2);
            }
        }
        __syncthreads();       // all warps done reading Ks
        if (kt + 1 < nkt) issue_k(kt + 1);
        CP_COMMIT();           // group K_{t+1} (possibly empty)

        // ---- scale + mask ----
#pragma unroll
        for (int nf = 0; nf < 8; nf++)
#pragma unroll
            for (int r = 0; r < 4; r++) sa[nf][r] *= SC2;
        if (k0 + 63 > q0w) {
#pragma unroll
            for (int nf = 0; nf < 8; nf++) {
                const int col = k0 + nf * 8 + qd * 2;
                if (col     > rowA) sa[nf][0] = -1e30f;
                if (col + 1 > rowA) sa[nf][1] = -1e30f;
                if (col     > rowB) sa[nf][2] = -1e30f;
                if (col + 1 > rowB) sa[nf][3] = -1e30f;
            }
        }

        // ---- online softmax ----
        float mxA = -1e30f, mxB = -1e30f;
#pragma unroll
        for (int nf = 0; nf < 8; nf++) {
            mxA = fmaxf(mxA, fmaxf(sa[nf][0], sa[nf][1]));
            mxB = fmaxf(mxB, fmaxf(sa[nf][2], sa[nf][3]));
        }
        mxA = fmaxf(mxA, __shfl_xor_sync(0xffffffffu, mxA, 1));
        mxA = fmaxf(mxA, __shfl_xor_sync(0xffffffffu, mxA, 2));
        mxB = fmaxf(mxB, __shfl_xor_sync(0xffffffffu, mxB, 1));
        mxB = fmaxf(mxB, __shfl_xor_sync(0xffffffffu, mxB, 2));
        const float mnA = fmaxf(mA, mxA);
        const float mnB = fmaxf(mB, mxB);
        const float alA = fexp2(mA - mnA);
        const float alB = fexp2(mB - mnB);
        mA = mnA; mB = mnB;

        float rsA = 0.f, rsB = 0.f;
#pragma unroll
        for (int nf = 0; nf < 8; nf++) {
            sa[nf][0] = fexp2(sa[nf][0] - mnA); rsA += sa[nf][0];
            sa[nf][1] = fexp2(sa[nf][1] - mnA); rsA += sa[nf][1];
            sa[nf][2] = fexp2(sa[nf][2] - mnB); rsB += sa[nf][2];
            sa[nf][3] = fexp2(sa[nf][3] - mnB); rsB += sa[nf][3];
        }
        rsA += __shfl_xor_sync(0xffffffffu, rsA, 1);
        rsA += __shfl_xor_sync(0xffffffffu, rsA, 2);
        rsB += __shfl_xor_sync(0xffffffffu, rsB, 1);
        rsB += __shfl_xor_sync(0xffffffffu, rsB, 2);
        lA = lA * alA + rsA;
        lB = lB * alB + rsB;
#pragma unroll
        for (int nf = 0; nf < 8; nf++) {
            oacc[nf][0] *= alA; oacc[nf][1] *= alA;
            oacc[nf][2] *= alB; oacc[nf][3] *= alB;
        }

        CP_WAIT(1);            // V_t landed; K_{t+1} may be in flight
        __syncthreads();

        // ---- O += P @ V ----
#pragma unroll
        for (int t = 0; t < 4; t++) {
            uint32_t ph[4], pl[4];
#pragma unroll
            for (int half = 0; half < 2; half++) {
                const int nf = 2 * t + half;
                split2(sa[nf][0], sa[nf][1], ph[half*2],   pl[half*2]);
                split2(sa[nf][2], sa[nf][3], ph[half*2+1], pl[half*2+1]);
            }
#pragma unroll
            for (int np = 0; np < 4; np++) {
                uint32_t vhf[4], vlf[4];
                const uint32_t voff = ((t * 16 + v_row) * AV_ST + np * 16 + v_col) * 2;
                ldmatrix_x4_t(vhf[0], vhf[1], vhf[2], vhf[3], uVh + voff);
                ldmatrix_x4_t(vlf[0], vlf[1], vlf[2], vlf[3], uVl + voff);
                mma_bf16(oacc[np*2],   ph, vhf + 0);
                mma_bf16(oacc[np*2],   ph, vlf + 0);
                mma_bf16(oacc[np*2],   pl, vhf + 0);
                mma_bf16(oacc[np*2+1], ph, vhf + 2);
                mma_bf16(oacc[np*2+1], ph, vlf + 2);
                mma_bf16(oacc[np*2+1], pl, vhf + 2);
            }
        }
        __syncthreads();       // all warps done reading Vs
        if (kt + 1 < nkt) issue_v(kt + 1);
        CP_COMMIT();           // group V_{t+1} (possibly empty)
    }

    // ---- finalize + write split planes ----
    const float invA = 1.f / lA;
    const float invB = 1.f / lB;
#pragma unroll
    for (int nf = 0; nf < 8; nf++) {
        const int col = h * V_D + nf * 8 + qd * 2;
        uint32_t hp, lp;
        split2(oacc[nf][0] * invA, oacc[nf][1] * invA, hp, lp);
        *(uint32_t*)&oh[(tok0 + rowA) * (size_t)OD_ALL + col] = hp;
        *(uint32_t*)&ol[(tok0 + rowA) * (size_t)OD_ALL + col] = lp;
        split2(oacc[nf][2] * invB, oacc[nf][3] * invB, hp, lp);
        *(uint32_t*)&oh[(tok0 + rowB) * (size_t)OD_ALL + col] = hp;
        *(uint32_t*)&ol[(tok0 + rowB) * (size_t)OD_ALL + col] = lp;
    }
}

// ---------------------------------------------------------------------------
// Launch (ordered so ncu -s 5 profiles the wq_b GEMM)
// ---------------------------------------------------------------------------
extern "C" void kernel_launch(void* const* d_in, const int* in_sizes, int n_in,
                              void* d_out, int out_size)
{
    const float* hidden = (const float*)d_in[0];
    const float* cosb   = (const float*)d_in[1];
    const float* sinb   = (const float*)d_in[2];
    const float* wq_a   = (const float*)d_in[3];
    const float* q_ln   = (const float*)d_in[4];
    const float* wq_b   = (const float*)d_in[5];
    const float* wkv_a  = (const float*)d_in[6];
    const float* kv_ln  = (const float*)d_in[7];
    const float* wkv_b  = (const float*)d_in[8];
    const float* wo     = (const float*)d_in[9];
    float* out = (float*)d_out;

    __nv_bfloat16 *hidh, *hidl, *wqah, *wqal, *wkvah, *wkval, *wqbh, *wqbl,
                  *wkvbh, *wkvbl, *woh, *wol, *qanh, *qanl, *kvnh, *kvnl,
                  *qhp, *qlp, *kvhp, *kvlp, *krhp, *krlp, *ath, *atl;
    float *qa, *ckv;
    cudaGetSymbolAddress((void**)&hidh,  g_hid_h);  cudaGetSymbolAddress((void**)&hidl,  g_hid_l);
    cudaGetSymbolAddress((void**)&wqah,  g_wqa_h);  cudaGetSymbolAddress((void**)&wqal,  g_wqa_l);
    cudaGetSymbolAddress((void**)&wkvah, g_wkva_h); cudaGetSymbolAddress((void**)&wkval, g_wkva_l);
    cudaGetSymbolAddress((void**)&wqbh,  g_wqb_h);  cudaGetSymbolAddress((void**)&wqbl,  g_wqb_l);
    cudaGetSymbolAddress((void**)&wkvbh, g_wkvb_h); cudaGetSymbolAddress((void**)&wkvbl, g_wkvb_l);
    cudaGetSymbolAddress((void**)&woh,   g_wo_h);   cudaGetSymbolAddress((void**)&wol,   g_wo_l);
    cudaGetSymbolAddress((void**)&qa,    g_qa);     cudaGetSymbolAddress((void**)&ckv,   g_ckv);
    cudaGetSymbolAddress((void**)&qanh,  g_qan_h);  cudaGetSymbolAddress((void**)&qanl,  g_qan_l);
    cudaGetSymbolAddress((void**)&kvnh,  g_kvn_h);  cudaGetSymbolAddress((void**)&kvnl,  g_kvn_l);
    cudaGetSymbolAddress((void**)&qhp,   g_q_h);    cudaGetSymbolAddress((void**)&qlp,   g_q_l);
    cudaGetSymbolAddress((void**)&kvhp,  g_kv_h);   cudaGetSymbolAddress((void**)&kvlp,  g_kv_l);
    cudaGetSymbolAddress((void**)&krhp,  g_kr_h);   cudaGetSymbolAddress((void**)&krlp,  g_kr_l);
    cudaGetSymbolAddress((void**)&ath,   g_at_h);   cudaGetSymbolAddress((void**)&atl,   g_at_l);

    cudaFuncSetAttribute(tgemm_kernel<false>, cudaFuncAttributeMaxDynamicSharedMemorySize, G_SMEM);
    cudaFuncSetAttribute(tgemm_kernel<true>,  cudaFuncAttributeMaxDynamicSharedMemorySize, G_SMEM);
    cudaFuncSetAttribute(attn_mma_kernel,     cudaFuncAttributeMaxDynamicSharedMemorySize, ATTN_SMEM);

    const dim3 blk(256);
    const int mt = NTOK / 128;

    // 0: presplit hidden
    split_kernel<<<(NTOK * HIDN / 4 + 255) / 256, 256>>>(hidden, hidh, hidl, NTOK * HIDN / 4);
    // 1: all weight transpose+splits
    wsplit_all_kernel<<<13200, 256>>>(wq_a, wkv_a, wq_b, wkv_b, wo);
    // 2: qa = hidden @ wq_a
    tgemm_kernel<false><<<dim3(Q_RANK / 128, mt), blk, G_SMEM>>>(
        hidh, hidl, wqah, wqal, qa, nullptr, nullptr, NTOK, Q_RANK, HIDN);
    // 3: rmsnorm qa -> planes
    rmsnorm_split_kernel<<<NTOK, 256>>>(qa, q_ln, qanh, qanl, Q_RANK, Q_RANK);
    // 4: ckv = hidden @ wkv_a
    tgemm_kernel<false><<<dim3((CKV_D + 127) / 128, mt), blk, G_SMEM>>>(
        hidh, hidl, wkvah, wkval, ckv, nullptr, nullptr, NTOK, CKV_D, HIDN);
    // 5: q = qan @ wq_b  (split out)  <-- ncu profile target
    tgemm_kernel<true><<<dim3(QD_ALL / 128, mt), blk, G_SMEM>>>(
        qanh, qanl, wqbh, wqbl, nullptr, qhp, qlp, NTOK, QD_ALL, Q_RANK);
    // 6: rmsnorm ckv -> planes
    rmsnorm_split_kernel<<<NTOK, 256>>>(ckv, kv_ln, kvnh, kvnl, KV_RANK, CKV_D);
    // 7: kv = kvn @ wkv_b (split out)
    tgemm_kernel<true><<<dim3(KVD_ALL / 128, mt), blk, G_SMEM>>>(
        kvnh, kvnl, wkvbh, wkvbl, nullptr, kvhp, kvlp, NTOK, KVD_ALL, KV_RANK);
    // 8: rope
    rope_kernel<<<NTOK, 256>>>(qhp, qlp, ckv, krhp, krlp, cosb, sinb);
    // 9: attention
    attn_mma_kernel<<<dim3(SEQ / 128, 2 * NHEAD), blk, ATTN_SMEM>>>(
        qhp, qlp, kvhp, kvlp, krhp, krlp, ath, atl);
    // 10: out = attn @ wo
    tgemm_kernel<false><<<dim3(HIDN / 128, mt), blk, G_SMEM>>>(
        ath, atl, woh, wol, out, nullptr, nullptr, NTOK, HIDN, OD_ALL);
}

// round 7
// speedup vs baseline: 3.3957x; 1.0693x over previous
#include <cuda_runtime.h>
#include <cuda_bf16.h>
#include <cstdint>

// ---------------------------------------------------------------------------
// Problem constants
// ---------------------------------------------------------------------------
constexpr int SEQ    = 2048;
constexpr int HIDN   = 2560;
constexpr int NHEAD  = 40;
constexpr int NOPE_D = 64;
constexpr int ROPE_D = 32;
constexpr int QK_D   = NOPE_D + ROPE_D;    // 96
constexpr int V_D    = 64;
constexpr int Q_RANK = 768;
constexpr int KV_RANK= 256;
constexpr int CKV_D  = KV_RANK + ROPE_D;   // 288
constexpr int NTOK   = 2 * SEQ;            // 4096
constexpr int QD_ALL = NHEAD * QK_D;       // 3840
constexpr int KVD_ALL= NHEAD * (NOPE_D + V_D); // 5120
constexpr int OD_ALL = NHEAD * V_D;        // 2560
constexpr float SCALE = 0.10206207261596577f;
constexpr float SC2   = SCALE * 1.4426950408889634f;

// ---------------------------------------------------------------------------
// Scratch (static device arrays)
// ---------------------------------------------------------------------------
__device__ __nv_bfloat16 g_hid_h [NTOK * HIDN];
__device__ __nv_bfloat16 g_hid_l [NTOK * HIDN];
__device__ __nv_bfloat16 g_wqa_h [Q_RANK * HIDN];     // transposed [N][K]
__device__ __nv_bfloat16 g_wqa_l [Q_RANK * HIDN];
__device__ __nv_bfloat16 g_wkva_h[CKV_D * HIDN];
__device__ __nv_bfloat16 g_wkva_l[CKV_D * HIDN];
__device__ __nv_bfloat16 g_wqb_h [QD_ALL * Q_RANK];
__device__ __nv_bfloat16 g_wqb_l [QD_ALL * Q_RANK];
__device__ __nv_bfloat16 g_wkvb_h[KVD_ALL * KV_RANK];
__device__ __nv_bfloat16 g_wkvb_l[KVD_ALL * KV_RANK];
__device__ __nv_bfloat16 g_wo_h  [HIDN * OD_ALL];
__device__ __nv_bfloat16 g_wo_l  [HIDN * OD_ALL];
__device__ float         g_qa    [NTOK * Q_RANK];
__device__ float         g_ckv   [NTOK * CKV_D];
__device__ __nv_bfloat16 g_qan_h [NTOK * Q_RANK];
__device__ __nv_bfloat16 g_qan_l [NTOK * Q_RANK];
__device__ __nv_bfloat16 g_kvn_h [NTOK * KV_RANK];
__device__ __nv_bfloat16 g_kvn_l [NTOK * KV_RANK];
__device__ __nv_bfloat16 g_q_h   [NTOK * QD_ALL];
__device__ __nv_bfloat16 g_q_l   [NTOK * QD_ALL];
__device__ __nv_bfloat16 g_kv_h  [NTOK * KVD_ALL];
__device__ __nv_bfloat16 g_kv_l  [NTOK * KVD_ALL];
__device__ __nv_bfloat16 g_kr_h  [NTOK * ROPE_D];
__device__ __nv_bfloat16 g_kr_l  [NTOK * ROPE_D];
__device__ __nv_bfloat16 g_at_h  [NTOK * OD_ALL];
__device__ __nv_bfloat16 g_at_l  [NTOK * OD_ALL];

// ---------------------------------------------------------------------------
// PTX helpers (portable sm_80+ subset)
// ---------------------------------------------------------------------------
__device__ __forceinline__ uint32_t smem_u32(const void* p) {
    uint32_t a;
    asm("{ .reg .u64 t; cvta.to.shared.u64 t, %1; cvt.u32.u64 %0, t; }"
        : "=r"(a) : "l"(p));
    return a;
}
__device__ __forceinline__ void ldmatrix_x4(uint32_t& r0, uint32_t& r1,
                                            uint32_t& r2, uint32_t& r3, uint32_t addr) {
    asm volatile("ldmatrix.sync.aligned.m8n8.x4.shared.b16 {%0,%1,%2,%3}, [%4];"
                 : "=r"(r0), "=r"(r1), "=r"(r2), "=r"(r3) : "r"(addr));
}
__device__ __forceinline__ void ldmatrix_x4_t(uint32_t& r0, uint32_t& r1,
                                              uint32_t& r2, uint32_t& r3, uint32_t addr) {
    asm volatile("ldmatrix.sync.aligned.m8n8.x4.trans.shared.b16 {%0,%1,%2,%3}, [%4];"
                 : "=r"(r0), "=r"(r1), "=r"(r2), "=r"(r3) : "r"(addr));
}
__device__ __forceinline__ void mma_bf16(float* c, const uint32_t* a, const uint32_t* b) {
    asm volatile(
        "mma.sync.aligned.m16n8k16.row.col.f32.bf16.bf16.f32 "
        "{%0,%1,%2,%3}, {%4,%5,%6,%7}, {%8,%9}, {%0,%1,%2,%3};"
        : "+f"(c[0]), "+f"(c[1]), "+f"(c[2]), "+f"(c[3])
        : "r"(a[0]), "r"(a[1]), "r"(a[2]), "r"(a[3]), "r"(b[0]), "r"(b[1]));
}
#define CP16(dst, src) \
    asm volatile("cp.async.cg.shared.global [%0], [%1], 16;" :: "r"(dst), "l"(src))
#define CP16P(dst, src, pred) \
    asm volatile("cp.async.cg.shared.global [%0], [%1], 16, %2;" \
                 :: "r"(dst), "l"(src), "r"((pred) ? 16 : 0))
#define CP_COMMIT() asm volatile("cp.async.commit_group;" ::: "memory")
#define CP_WAIT(n)  asm volatile("cp.async.wait_group %0;" :: "n"(n) : "memory")

__device__ __forceinline__ uint32_t pack2(__nv_bfloat16 a, __nv_bfloat16 b) {
    return ((uint32_t)__bfloat16_as_ushort(b) << 16) | (uint32_t)__bfloat16_as_ushort(a);
}
__device__ __forceinline__ void split1(float x, __nv_bfloat16& h, __nv_bfloat16& l) {
    h = __float2bfloat16(x);
    l = __float2bfloat16(x - __bfloat162float(h));
}
// Fast pair split: hi = truncate-to-bf16 (bit mask), lo = rounded remainder.
__device__ __forceinline__ void split2(float x0, float x1, uint32_t& hp, uint32_t& lp) {
    const uint32_t b0 = __float_as_uint(x0), b1 = __float_as_uint(x1);
    hp = __byte_perm(b0, b1, 0x7632);
    const float l0 = x0 - __uint_as_float(b0 & 0xFFFF0000u);
    const float l1 = x1 - __uint_as_float(b1 & 0xFFFF0000u);
    asm("cvt.rn.bf16x2.f32 %0, %1, %2;" : "=r"(lp) : "f"(l1), "f"(l0));
}
__device__ __forceinline__ float fexp2(float x) {
    float r;
    asm("ex2.approx.ftz.f32 %0, %1;" : "=f"(r) : "f"(x));
    return r;
}

// ---------------------------------------------------------------------------
// Prep: hidden split (bid < 10240) + all weight transpose+splits (one launch)
// ---------------------------------------------------------------------------
constexpr int PREP_SPLIT_BLOCKS = NTOK * HIDN / 4 / 256;  // 10240
constexpr int PREP_TOTAL_BLOCKS = PREP_SPLIT_BLOCKS + 13200;

__global__ void prep_kernel(const float* __restrict__ hidden,
                            const float* __restrict__ wqa,
                            const float* __restrict__ wkva,
                            const float* __restrict__ wqb,
                            const float* __restrict__ wkvb,
                            const float* __restrict__ wo)
{
    __shared__ float tt[32][33];
    if (blockIdx.x < PREP_SPLIT_BLOCKS) {
        const int i = blockIdx.x * 256 + threadIdx.x;
        const float4 v = *(const float4*)&hidden[(size_t)i * 4];
        uint2 hp, lp;
        split2(v.x, v.y, hp.x, lp.x);
        split2(v.z, v.w, hp.y, lp.y);
        *(uint2*)&g_hid_h[(size_t)i * 4] = hp;
        *(uint2*)&g_hid_l[(size_t)i * 4] = lp;
        return;
    }
    const int bid = blockIdx.x - PREP_SPLIT_BLOCKS;
    const float* W; __nv_bfloat16 *Th, *Tl; int K, N, nx, t;
    if (bid < 1920)      { t = bid;        W=wqa;  Th=g_wqa_h;  Tl=g_wqa_l;  K=HIDN;    N=Q_RANK;  nx=24; }
    else if (bid < 2640) { t = bid-1920;   W=wkva; Th=g_wkva_h; Tl=g_wkva_l; K=HIDN;    N=CKV_D;   nx=9; }
    else if (bid < 5520) { t = bid-2640;   W=wqb;  Th=g_wqb_h;  Tl=g_wqb_l;  K=Q_RANK;  N=QD_ALL;  nx=120; }
    else if (bid < 6800) { t = bid-5520;   W=wkvb; Th=g_wkvb_h; Tl=g_wkvb_l; K=KV_RANK; N=KVD_ALL; nx=160; }
    else                 { t = bid-6800;   W=wo;   Th=g_wo_h;   Tl=g_wo_l;   K=HIDN;    N=OD_ALL;  nx=80; }
    const int n0 = (t % nx) * 32;
    const int k0 = (t / nx) * 32;

    const int tx = threadIdx.x & 31;
    const int ty = threadIdx.x >> 5;       // 0..7
#pragma unroll
    for (int j = 0; j < 4; j++)
        tt[ty + j * 8][tx] = W[(size_t)(k0 + ty + j * 8) * N + n0 + tx];
    __syncthreads();
#pragma unroll
    for (int j = 0; j < 4; j++) {
        const float v = tt[tx][ty + j * 8];
        __nv_bfloat16 h, l;
        split1(v, h, l);
        const size_t o = (size_t)(n0 + ty + j * 8) * K + k0 + tx;
        Th[o] = h; Tl[o] = l;
    }
}

// ---------------------------------------------------------------------------
// Fused tensor GEMM: two sub-GEMMs in one launch, selected by blockIdx.x.
// C[M,N] = A[M,K] @ Bt[N,K]^T on pre-split bf16 planes.
// Tile 128x128, BK=32, 256 threads (8 warps, 4x2), warp tile 32x64.
// ---------------------------------------------------------------------------
struct GemmDesc {
    const __nv_bfloat16 *Ah, *Al, *Bh, *Bl;
    float* C;
    __nv_bfloat16 *Ch, *Cl;
    int N, K;
};

constexpr int GST      = 40;
constexpr int G_OFF_AH = 0;
constexpr int G_OFF_AL = 128 * GST * 2;
constexpr int G_OFF_BH = 2 * 128 * GST * 2;
constexpr int G_OFF_BL = 3 * 128 * GST * 2;
constexpr int G_STAGE  = 4 * 128 * GST * 2;
constexpr int G_SMEM   = 2 * G_STAGE;

template<bool SPLIT_OUT>
__global__ __launch_bounds__(256, 2)
void tgemm2_kernel(GemmDesc d0, GemmDesc d1, int xsplit)
{
    extern __shared__ char smc[];
    const uint32_t sb0 = smem_u32(smc);

    const bool second = blockIdx.x >= (unsigned)xsplit;
    const GemmDesc d = second ? d1 : d0;
    const int bx = second ? (blockIdx.x - xsplit) : blockIdx.x;
    const int N = d.N, K = d.K;

    const int tid  = threadIdx.x;
    const int warp = tid >> 5;
    const int lane = tid & 31;
    const int wr   = warp >> 1;
    const int wc   = warp & 1;
    const int row0 = blockIdx.y * 128;
    const int col0 = bx * 128;

    auto issue_chunk = [&](int ch, int st) {
        const int k0 = ch << 5;
        const uint32_t sb = sb0 + st * G_STAGE;
#pragma unroll
        for (int i = 0; i < 2; i++) {
            const int s  = tid + i * 256;
            const int r  = s >> 2;
            const int kc = (s & 3) * 8;
            const uint32_t dd = r * (GST * 2) + kc * 2;
            CP16(sb + G_OFF_AH + dd, &d.Ah[(size_t)(row0 + r) * K + k0 + kc]);
            CP16(sb + G_OFF_AL + dd, &d.Al[(size_t)(row0 + r) * K + k0 + kc]);
            const int n = col0 + r;
            const bool pr = n < N;
            const size_t bo = (size_t)(pr ? n : 0) * K + k0 + kc;
            CP16P(sb + G_OFF_BH + dd, &d.Bh[bo], pr);
            CP16P(sb + G_OFF_BL + dd, &d.Bl[bo], pr);
        }
    };

    float acc[2][8][4];
#pragma unroll
    for (int mf = 0; mf < 2; mf++)
#pragma unroll
        for (int nf = 0; nf < 8; nf++)
#pragma unroll
            for (int r = 0; r < 4; r++) acc[mf][nf][r] = 0.f;

    const int a_row = (lane & 15);
    const int a_col = (lane >> 4) * 8;
    const int b_row = (lane >> 4) * 8 + (lane & 7);
    const int b_col = ((lane >> 3) & 1) * 8;

    auto compute_stage = [&](int st) {
        const uint32_t Ah = sb0 + st * G_STAGE + G_OFF_AH;
        const uint32_t Al = sb0 + st * G_STAGE + G_OFF_AL;
        const uint32_t Bh = sb0 + st * G_STAGE + G_OFF_BH;
        const uint32_t Bl = sb0 + st * G_STAGE + G_OFF_BL;
#pragma unroll
        for (int ks = 0; ks < 32; ks += 16) {
            uint32_t ah[2][4], al[2][4];
#pragma unroll
            for (int mf = 0; mf < 2; mf++) {
                const uint32_t off = ((wr * 32 + mf * 16 + a_row) * GST + ks + a_col) * 2;
                ldmatrix_x4(ah[mf][0], ah[mf][1], ah[mf][2], ah[mf][3], Ah + off);
                ldmatrix_x4(al[mf][0], al[mf][1], al[mf][2], al[mf][3], Al + off);
            }
#pragma unroll
            for (int np = 0; np < 4; np++) {
                uint32_t bh[4], bl[4];
                const uint32_t off = ((wc * 64 + np * 16 + b_row) * GST + ks + b_col) * 2;
                ldmatrix_x4(bh[0], bh[1], bh[2], bh[3], Bh + off);
                ldmatrix_x4(bl[0], bl[1], bl[2], bl[3], Bl + off);
#pragma unroll
                for (int mf = 0; mf < 2; mf++) {
                    mma_bf16(acc[mf][np*2],   ah[mf], bh + 0);
                    mma_bf16(acc[mf][np*2],   ah[mf], bl + 0);
                    mma_bf16(acc[mf][np*2],   al[mf], bh + 0);
                    mma_bf16(acc[mf][np*2+1], ah[mf], bh + 2);
                    mma_bf16(acc[mf][np*2+1], ah[mf], bl + 2);
                    mma_bf16(acc[mf][np*2+1], al[mf], bh + 2);
                }
            }
        }
    };

    const int nch = K >> 5;
    issue_chunk(0, 0);
    CP_COMMIT();
    for (int ch = 0; ch < nch; ch++) {
        if (ch + 1 < nch) {
            issue_chunk(ch + 1, (ch + 1) & 1);
            CP_COMMIT();
            CP_WAIT(1);
        } else {
            CP_WAIT(0);
        }
        __syncthreads();
        compute_stage(ch & 1);
        __syncthreads();
    }

#pragma unroll
    for (int mf = 0; mf < 2; mf++) {
        const int r0 = row0 + wr * 32 + mf * 16 + (lane >> 2);
#pragma unroll
        for (int nf = 0; nf < 8; nf++) {
            const int c = col0 + wc * 64 + nf * 8 + (lane & 3) * 2;
            if (c < N) {
                if (SPLIT_OUT) {
                    uint32_t hp, lp;
                    split2(acc[mf][nf][0], acc[mf][nf][1], hp, lp);
                    *(uint32_t*)&d.Ch[(size_t)r0 * N + c] = hp;
                    *(uint32_t*)&d.Cl[(size_t)r0 * N + c] = lp;
                    split2(acc[mf][nf][2], acc[mf][nf][3], hp, lp);
                    *(uint32_t*)&d.Ch[(size_t)(r0 + 8) * N + c] = hp;
                    *(uint32_t*)&d.Cl[(size_t)(r0 + 8) * N + c] = lp;
                } else {
                    *(float2*)&d.C[(size_t)r0 * N + c] =
                        make_float2(acc[mf][nf][0], acc[mf][nf][1]);
                    *(float2*)&d.C[(size_t)(r0 + 8) * N + c] =
                        make_float2(acc[mf][nf][2], acc[mf][nf][3]);
                }
            }
        }
    }
}

// ---------------------------------------------------------------------------
// Both RMSNorms in one launch -> bf16 hi/lo planes
// ---------------------------------------------------------------------------
__global__ void rmsnorm2_kernel(const float* __restrict__ qln,
                                const float* __restrict__ kvln)
{
    const float* in; const float* w; __nv_bfloat16 *oh, *ol;
    int dim, istride, row;
    if (blockIdx.x < NTOK) {
        row = blockIdx.x;
        in = g_qa; w = qln; oh = g_qan_h; ol = g_qan_l;
        dim = Q_RANK; istride = Q_RANK;
    } else {
        row = blockIdx.x - NTOK;
        in = g_ckv; w = kvln; oh = g_kvn_h; ol = g_kvn_l;
        dim = KV_RANK; istride = CKV_D;
    }
    const float* x = in + (size_t)row * istride;
    float ss = 0.f;
    for (int i = threadIdx.x; i < dim; i += blockDim.x) { float v = x[i]; ss += v * v; }
#pragma unroll
    for (int o = 16; o > 0; o >>= 1) ss += __shfl_xor_sync(0xffffffffu, ss, o);
    __shared__ float sh[8];
    __shared__ float s_inv;
    if ((threadIdx.x & 31) == 0) sh[threadIdx.x >> 5] = ss;
    __syncthreads();
    if (threadIdx.x == 0) {
        float t = 0.f;
        const int nw = blockDim.x >> 5;
        for (int i = 0; i < nw; i++) t += sh[i];
        s_inv = rsqrtf(t / (float)dim + 1e-5f);
    }
    __syncthreads();
    const float inv = s_inv;
    for (int i = threadIdx.x; i < dim; i += blockDim.x) {
        const float y = x[i] * inv * w[i];
        __nv_bfloat16 h, l;
        split1(y, h, l);
        oh[(size_t)row * dim + i] = h;
        ol[(size_t)row * dim + i] = l;
    }
}

// ---------------------------------------------------------------------------
// RoPE on planes: q planes in-place (rope dims), ckv tail -> krot planes
// ---------------------------------------------------------------------------
__global__ void rope_kernel(__nv_bfloat16* __restrict__ qh, __nv_bfloat16* __restrict__ ql,
                            const float* __restrict__ ckv,
                            __nv_bfloat16* __restrict__ krh, __nv_bfloat16* __restrict__ krl,
                            const float* __restrict__ cosb, const float* __restrict__ sinb)
{
    const int token = blockIdx.x;
    const int s = token & (SEQ - 1);
    for (int i = threadIdx.x; i < (NHEAD + 1) * 32; i += blockDim.x) {
        const int h = i >> 5;
        const int d = i & 31;
        const float c  = cosb[s * ROPE_D + d];
        const float sn = sinb[s * ROPE_D + d];
        if (h < NHEAD) {
            const size_t base = (size_t)token * QD_ALL + h * QK_D + NOPE_D;
            const size_t pi   = base + ((d < 16) ? d + 16 : d - 16);
            const float x  = __bfloat162float(qh[base + d]) + __bfloat162float(ql[base + d]);
            float pr = __bfloat162float(qh[pi]) + __bfloat162float(ql[pi]);
            if (d < 16) pr = -pr;
            __syncwarp();
            __nv_bfloat16 hh, ll;
            split1(x * c + pr * sn, hh, ll);
            qh[base + d] = hh;
            ql[base + d] = ll;
        } else {
            const float* kb = ckv + (size_t)token * CKV_D + KV_RANK;
            const float x  = kb[d];
            const float pr = (d < 16) ? -kb[d + 16] : kb[d - 16];
            __nv_bfloat16 hh, ll;
            split1(x * c + pr * sn, hh, ll);
            krh[(size_t)token * ROPE_D + d] = hh;
            krl[(size_t)token * ROPE_D + d] = ll;
        }
    }
}

// ---------------------------------------------------------------------------
// Flash attention on pre-split planes. BQ=128, BK=64, 256 threads, 8 warps.
// Largest-qt-first ordering; K(t+1)/V(t+1) prefetch pipeline.
// ---------------------------------------------------------------------------
constexpr int AQ_ST = 104;
constexpr int AV_ST = 72;
constexpr int A_QT  = 128 * AQ_ST;
constexpr int A_KT  = 64 * AQ_ST;
constexpr int A_VT  = 64 * AV_ST;
constexpr int ATTN_SMEM = (2*A_QT + 2*A_KT + 2*A_VT) * (int)sizeof(__nv_bfloat16);

__global__ __launch_bounds__(256, 2)
void attn_mma_kernel(const __nv_bfloat16* __restrict__ qh, const __nv_bfloat16* __restrict__ ql,
                     const __nv_bfloat16* __restrict__ kvh, const __nv_bfloat16* __restrict__ kvl,
                     const __nv_bfloat16* __restrict__ krh, const __nv_bfloat16* __restrict__ krl,
                     __nv_bfloat16* __restrict__ oh, __nv_bfloat16* __restrict__ ol)
{
    extern __shared__ __nv_bfloat16 smb[];
    const uint32_t uQh = smem_u32(smb);
    const uint32_t uQl = uQh + A_QT * 2;
    const uint32_t uKh = uQl + A_QT * 2;
    const uint32_t uKl = uKh + A_KT * 2;
    const uint32_t uVh = uKl + A_KT * 2;
    const uint32_t uVl = uVh + A_VT * 2;

    const int bh = blockIdx.y;
    const int b  = bh / NHEAD;
    const int h  = bh % NHEAD;
    const int qt = (SEQ / 128 - 1) - blockIdx.x;   // largest work first
    const int q0 = qt * 128;
    const int tid  = threadIdx.x;
    const int warp = tid >> 5;
    const int lane = tid & 31;
    const int gr   = lane >> 2;
    const int qd   = lane & 3;
    const size_t tok0 = (size_t)b * SEQ;

    const int a_row = (lane & 15);
    const int a_col = (lane >> 4) * 8;
    const int b_row = (lane >> 4) * 8 + (lane & 7);
    const int b_col = ((lane >> 3) & 1) * 8;
    const int v_row = (lane & 15);
    const int v_col = (lane >> 4) * 8;

    auto issue_k = [&](int kt) {
        const int k0 = kt * 64;
#pragma unroll
        for (int i = 0; i < 3; i++) {
            const int s = tid + i * 256;
            if (s < 512) {
                const int r = s >> 3, c8 = (s & 7) * 8;
                const size_t src = (tok0 + k0 + r) * KVD_ALL + h * 128 + c8;
                CP16(uKh + (r * AQ_ST + c8) * 2, &kvh[src]);
                CP16(uKl + (r * AQ_ST + c8) * 2, &kvl[src]);
            } else {
                const int t = s - 512;
                const int r = t >> 2, c8 = 64 + (t & 3) * 8;
                const size_t src = (tok0 + k0 + r) * ROPE_D + (c8 - 64);
                CP16(uKh + (r * AQ_ST + c8) * 2, &krh[src]);
                CP16(uKl + (r * AQ_ST + c8) * 2, &krl[src]);
            }
        }
    };
    auto issue_v = [&](int kt) {
        const int k0 = kt * 64;
#pragma unroll
        for (int i = 0; i < 2; i++) {
            const int s = tid + i * 256;
            const int r = s >> 3;
            const int c8 = (s & 7) * 8;
            const size_t src = (tok0 + k0 + r) * KVD_ALL + h * 128 + 64 + c8;
            CP16(uVh + (r * AV_ST + c8) * 2, &kvh[src]);
            CP16(uVl + (r * AV_ST + c8) * 2, &kvl[src]);
        }
    };

    // ---- Q tile copy (128 x 96 both planes) ----
#pragma unroll
    for (int i = 0; i < 6; i++) {
        const int s  = tid + i * 256;
        const int r  = s / 12;
        const int c8 = (s - r * 12) * 8;
        const size_t src = (tok0 + q0 + r) * QD_ALL + h * QK_D + c8;
        const uint32_t d = (r * AQ_ST + c8) * 2;
        CP16(uQh + d, &qh[src]);
        CP16(uQl + d, &ql[src]);
    }
    CP_COMMIT();          // group: Q
    issue_k(0);
    CP_COMMIT();          // group: K0
    issue_v(0);
    CP_COMMIT();          // group: V0

    float oacc[8][4];
#pragma unroll
    for (int nf = 0; nf < 8; nf++)
#pragma unroll
        for (int r = 0; r < 4; r++) oacc[nf][r] = 0.f;
    float mA = -1e30f, mB = -1e30f, lA = 0.f, lB = 0.f;

    const int q0w  = q0 + warp * 16;
    const int rowA = q0w + gr;
    const int rowB = rowA + 8;
    const int nkt  = 2 * qt + 2;

    for (int kt = 0; kt < nkt; kt++) {
        const int k0 = kt * 64;

        CP_WAIT(1);            // K_t (and Q) landed; V_t may be in flight
        __syncthreads();

        // ---- S = Q @ K^T ----
        float sa[8][4];
#pragma unroll
        for (int nf = 0; nf < 8; nf++)
#pragma unroll
            for (int r = 0; r < 4; r++) sa[nf][r] = 0.f;

#pragma unroll
        for (int ks = 0; ks < 96; ks += 16) {
            uint32_t ah[4], al[4];
            const uint32_t aoff = ((warp * 16 + a_row) * AQ_ST + ks + a_col) * 2;
            ldmatrix_x4(ah[0], ah[1], ah[2], ah[3], uQh + aoff);
            ldmatrix_x4(al[0], al[1], al[2], al[3], uQl + aoff);
#pragma unroll
            for (int np = 0; np < 4; np++) {
                uint32_t bhf[4], blf[4];
                const uint32_t boff = ((np * 16 + b_row) * AQ_ST + ks + b_col) * 2;
                ldmatrix_x4(bhf[0], bhf[1], bhf[2], bhf[3], uKh + boff);
                ldmatrix_x4(blf[0], blf[1], blf[2], blf[3], uKl + boff);
                mma_bf16(sa[np*2],   ah, bhf + 0);
                mma_bf16(sa[np*2],   ah, blf + 0);
                mma_bf16(sa[np*2],   al, bhf + 0);
                mma_bf16(sa[np*2+1], ah, bhf + 2);
                mma_bf16(sa[np*2+1], ah, blf + 2);
                mma_bf16(sa[np*2+1], al, bhf + 2);
            }
        }
        __syncthreads();       // all warps done reading Ks
        if (kt + 1 < nkt) issue_k(kt + 1);
        CP_COMMIT();           // group K_{t+1} (possibly empty)

        // ---- scale + mask ----
#pragma unroll
        for (int nf = 0; nf < 8; nf++)
#pragma unroll
            for (int r = 0; r < 4; r++) sa[nf][r] *= SC2;
        if (k0 + 63 > q0w) {
#pragma unroll
            for (int nf = 0; nf < 8; nf++) {
                const int col = k0 + nf * 8 + qd * 2;
                if (col     > rowA) sa[nf][0] = -1e30f;
                if (col + 1 > rowA) sa[nf][1] = -1e30f;
                if (col     > rowB) sa[nf][2] = -1e30f;
                if (col + 1 > rowB) sa[nf][3] = -1e30f;
            }
        }

        // ---- online softmax ----
        float mxA = -1e30f, mxB = -1e30f;
#pragma unroll
        for (int nf = 0; nf < 8; nf++) {
            mxA = fmaxf(mxA, fmaxf(sa[nf][0], sa[nf][1]));
            mxB = fmaxf(mxB, fmaxf(sa[nf][2], sa[nf][3]));
        }
        mxA = fmaxf(mxA, __shfl_xor_sync(0xffffffffu, mxA, 1));
        mxA = fmaxf(mxA, __shfl_xor_sync(0xffffffffu, mxA, 2));
        mxB = fmaxf(mxB, __shfl_xor_sync(0xffffffffu, mxB, 1));
        mxB = fmaxf(mxB, __shfl_xor_sync(0xffffffffu, mxB, 2));
        const float mnA = fmaxf(mA, mxA);
        const float mnB = fmaxf(mB, mxB);
        const float alA = fexp2(mA - mnA);
        const float alB = fexp2(mB - mnB);
        mA = mnA; mB = mnB;

        float rsA = 0.f, rsB = 0.f;
#pragma unroll
        for (int nf = 0; nf < 8; nf++) {
            sa[nf][0] = fexp2(sa[nf][0] - mnA); rsA += sa[nf][0];
            sa[nf][1] = fexp2(sa[nf][1] - mnA); rsA += sa[nf][1];
            sa[nf][2] = fexp2(sa[nf][2] - mnB); rsB += sa[nf][2];
            sa[nf][3] = fexp2(sa[nf][3] - mnB); rsB += sa[nf][3];
        }
        rsA += __shfl_xor_sync(0xffffffffu, rsA, 1);
        rsA += __shfl_xor_sync(0xffffffffu, rsA, 2);
        rsB += __shfl_xor_sync(0xffffffffu, rsB, 1);
        rsB += __shfl_xor_sync(0xffffffffu, rsB, 2);
        lA = lA * alA + rsA;
        lB = lB * alB + rsB;
#pragma unroll
        for (int nf = 0; nf < 8; nf++) {
            oacc[nf][0] *= alA; oacc[nf][1] *= alA;
            oacc[nf][2] *= alB; oacc[nf][3] *= alB;
        }

        CP_WAIT(1);            // V_t landed; K_{t+1} may be in flight
        __syncthreads();

        // ---- O += P @ V ----
#pragma unroll
        for (int t = 0; t < 4; t++) {
            uint32_t ph[4], pl[4];
#pragma unroll
            for (int half = 0; half < 2; half++) {
                const int nf = 2 * t + half;
                split2(sa[nf][0], sa[nf][1], ph[half*2],   pl[half*2]);
                split2(sa[nf][2], sa[nf][3], ph[half*2+1], pl[half*2+1]);
            }
#pragma unroll
            for (int np = 0; np < 4; np++) {
                uint32_t vhf[4], vlf[4];
                const uint32_t voff = ((t * 16 + v_row) * AV_ST + np * 16 + v_col) * 2;
                ldmatrix_x4_t(vhf[0], vhf[1], vhf[2], vhf[3], uVh + voff);
                ldmatrix_x4_t(vlf[0], vlf[1], vlf[2], vlf[3], uVl + voff);
                mma_bf16(oacc[np*2],   ph, vhf + 0);
                mma_bf16(oacc[np*2],   ph, vlf + 0);
                mma_bf16(oacc[np*2],   pl, vhf + 0);
                mma_bf16(oacc[np*2+1], ph, vhf + 2);
                mma_bf16(oacc[np*2+1], ph, vlf + 2);
                mma_bf16(oacc[np*2+1], pl, vhf + 2);
            }
        }
        __syncthreads();       // all warps done reading Vs
        if (kt + 1 < nkt) issue_v(kt + 1);
        CP_COMMIT();           // group V_{t+1} (possibly empty)
    }

    // ---- finalize + write split planes ----
    const float invA = 1.f / lA;
    const float invB = 1.f / lB;
#pragma unroll
    for (int nf = 0; nf < 8; nf++) {
        const int col = h * V_D + nf * 8 + qd * 2;
        uint32_t hp, lp;
        split2(oacc[nf][0] * invA, oacc[nf][1] * invA, hp, lp);
        *(uint32_t*)&oh[(tok0 + rowA) * (size_t)OD_ALL + col] = hp;
        *(uint32_t*)&ol[(tok0 + rowA) * (size_t)OD_ALL + col] = lp;
        split2(oacc[nf][2] * invB, oacc[nf][3] * invB, hp, lp);
        *(uint32_t*)&oh[(tok0 + rowB) * (size_t)OD_ALL + col] = hp;
        *(uint32_t*)&ol[(tok0 + rowB) * (size_t)OD_ALL + col] = lp;
    }
}

// ---------------------------------------------------------------------------
// Launch
// ---------------------------------------------------------------------------
extern "C" void kernel_launch(void* const* d_in, const int* in_sizes, int n_in,
                              void* d_out, int out_size)
{
    const float* hidden = (const float*)d_in[0];
    const float* cosb   = (const float*)d_in[1];
    const float* sinb   = (const float*)d_in[2];
    const float* wq_a   = (const float*)d_in[3];
    const float* q_ln   = (const float*)d_in[4];
    const float* wq_b   = (const float*)d_in[5];
    const float* wkv_a  = (const float*)d_in[6];
    const float* kv_ln  = (const float*)d_in[7];
    const float* wkv_b  = (const float*)d_in[8];
    const float* wo     = (const float*)d_in[9];
    float* out = (float*)d_out;

    __nv_bfloat16 *hidh, *hidl, *wqah, *wqal, *wkvah, *wkval, *wqbh, *wqbl,
                  *wkvbh, *wkvbl, *woh, *wol, *qanh, *qanl, *kvnh, *kvnl,
                  *qhp, *qlp, *kvhp, *kvlp, *krhp, *krlp, *ath, *atl;
    float *qa, *ckv;
    cudaGetSymbolAddress((void**)&hidh,  g_hid_h);  cudaGetSymbolAddress((void**)&hidl,  g_hid_l);
    cudaGetSymbolAddress((void**)&wqah,  g_wqa_h);  cudaGetSymbolAddress((void**)&wqal,  g_wqa_l);
    cudaGetSymbolAddress((void**)&wkvah, g_wkva_h); cudaGetSymbolAddress((void**)&wkval, g_wkva_l);
    cudaGetSymbolAddress((void**)&wqbh,  g_wqb_h);  cudaGetSymbolAddress((void**)&wqbl,  g_wqb_l);
    cudaGetSymbolAddress((void**)&wkvbh, g_wkvb_h); cudaGetSymbolAddress((void**)&wkvbl, g_wkvb_l);
    cudaGetSymbolAddress((void**)&woh,   g_wo_h);   cudaGetSymbolAddress((void**)&wol,   g_wo_l);
    cudaGetSymbolAddress((void**)&qa,    g_qa);     cudaGetSymbolAddress((void**)&ckv,   g_ckv);
    cudaGetSymbolAddress((void**)&qanh,  g_qan_h);  cudaGetSymbolAddress((void**)&qanl,  g_qan_l);
    cudaGetSymbolAddress((void**)&kvnh,  g_kvn_h);  cudaGetSymbolAddress((void**)&kvnl,  g_kvn_l);
    cudaGetSymbolAddress((void**)&qhp,   g_q_h);    cudaGetSymbolAddress((void**)&qlp,   g_q_l);
    cudaGetSymbolAddress((void**)&kvhp,  g_kv_h);   cudaGetSymbolAddress((void**)&kvlp,  g_kv_l);
    cudaGetSymbolAddress((void**)&krhp,  g_kr_h);   cudaGetSymbolAddress((void**)&krlp,  g_kr_l);
    cudaGetSymbolAddress((void**)&ath,   g_at_h);   cudaGetSymbolAddress((void**)&atl,   g_at_l);

    cudaFuncSetAttribute(tgemm2_kernel<false>, cudaFuncAttributeMaxDynamicSharedMemorySize, G_SMEM);
    cudaFuncSetAttribute(tgemm2_kernel<true>,  cudaFuncAttributeMaxDynamicSharedMemorySize, G_SMEM);
    cudaFuncSetAttribute(attn_mma_kernel,      cudaFuncAttributeMaxDynamicSharedMemorySize, ATTN_SMEM);

    const dim3 blk(256);
    const int mt = NTOK / 128;

    // 0: prep (hidden split + all weight transpose/splits)
    prep_kernel<<<PREP_TOTAL_BLOCKS, 256>>>(hidden, wq_a, wkv_a, wq_b, wkv_b, wo);

    // 1: fused GEMM pair: qa = hid@wqa  |  ckv = hid@wkva
    {
        GemmDesc d0 = { hidh, hidl, wqah,  wqal,  qa,  nullptr, nullptr, Q_RANK, HIDN };
        GemmDesc d1 = { hidh, hidl, wkvah, wkval, ckv, nullptr, nullptr, CKV_D,  HIDN };
        tgemm2_kernel<false><<<dim3(6 + 3, mt), blk, G_SMEM>>>(d0, d1, 6);
    }
    // 2: both rmsnorms
    rmsnorm2_kernel<<<2 * NTOK, 256>>>(q_ln, kv_ln);
    // 3: fused GEMM pair: q = qan@wqb (split out) | kv = kvn@wkvb (split out)
    {
        GemmDesc d0 = { qanh, qanl, wqbh,  wqbl,  nullptr, qhp,  qlp,  QD_ALL,  Q_RANK };
        GemmDesc d1 = { kvnh, kvnl, wkvbh, wkvbl, nullptr, kvhp, kvlp, KVD_ALL, KV_RANK };
        tgemm2_kernel<true><<<dim3(30 + 40, mt), blk, G_SMEM>>>(d0, d1, 30);
    }
    // 4: rope
    rope_kernel<<<NTOK, 256>>>(qhp, qlp, ckv, krhp, krlp, cosb, sinb);
    // 5: attention (largest qt first)
    attn_mma_kernel<<<dim3(SEQ / 128, 2 * NHEAD), blk, ATTN_SMEM>>>(
        qhp, qlp, kvhp, kvlp, krhp, krlp, ath, atl);
    // 6: out = attn @ wo
    {
        GemmDesc d0 = { ath, atl, woh, wol, out, nullptr, nullptr, HIDN, OD_ALL };
        tgemm2_kernel<false><<<dim3(HIDN / 128, mt), blk, G_SMEM>>>(d0, d0, HIDN / 128);
    }
}

// round 9
// speedup vs baseline: 4.7199x; 1.3900x over previous
#include <cuda_runtime.h>
#include <cuda_fp16.h>
#include <cstdint>

// ---------------------------------------------------------------------------
// Problem constants
// ---------------------------------------------------------------------------
constexpr int SEQ    = 2048;
constexpr int HIDN   = 2560;
constexpr int NHEAD  = 40;
constexpr int NOPE_D = 64;
constexpr int ROPE_D = 32;
constexpr int QK_D   = NOPE_D + ROPE_D;    // 96
constexpr int V_D    = 64;
constexpr int Q_RANK = 768;
constexpr int KV_RANK= 256;
constexpr int CKV_D  = KV_RANK + ROPE_D;   // 288
constexpr int NTOK   = 2 * SEQ;            // 4096
constexpr int QD_ALL = NHEAD * QK_D;       // 3840
constexpr int KVD_ALL= NHEAD * (NOPE_D + V_D); // 5120
constexpr int OD_ALL = NHEAD * V_D;        // 2560
constexpr float SCALE = 0.10206207261596577f;
constexpr float SC2   = SCALE * 1.4426950408889634f;

// ---------------------------------------------------------------------------
// Scratch (static device arrays). Activations: fp16 hi only.
// Weights and K/V-side tensors: fp16 hi + lo planes.
// ---------------------------------------------------------------------------
__device__ __half g_hid_h [NTOK * HIDN];
__device__ __half g_wqa_h [Q_RANK * HIDN];     // transposed [N][K]
__device__ __half g_wqa_l [Q_RANK * HIDN];
__device__ __half g_wkva_h[CKV_D * HIDN];
__device__ __half g_wkva_l[CKV_D * HIDN];
__device__ __half g_wqb_h [QD_ALL * Q_RANK];
__device__ __half g_wqb_l [QD_ALL * Q_RANK];
__device__ __half g_wkvb_h[KVD_ALL * KV_RANK];
__device__ __half g_wkvb_l[KVD_ALL * KV_RANK];
__device__ __half g_wo_h  [HIDN * OD_ALL];
__device__ __half g_wo_l  [HIDN * OD_ALL];
__device__ float  g_qa    [NTOK * Q_RANK];
__device__ float  g_ckv   [NTOK * CKV_D];
__device__ __half g_qan_h [NTOK * Q_RANK];
__device__ __half g_kvn_h [NTOK * KV_RANK];
__device__ __half g_q_h   [NTOK * QD_ALL];
__device__ __half g_kv_h  [NTOK * KVD_ALL];
__device__ __half g_kv_l  [NTOK * KVD_ALL];
__device__ __half g_kr_h  [NTOK * ROPE_D];
__device__ __half g_kr_l  [NTOK * ROPE_D];
__device__ __half g_at_h  [NTOK * OD_ALL];

// ---------------------------------------------------------------------------
// PTX helpers (portable sm_80+ subset)
// ---------------------------------------------------------------------------
__device__ __forceinline__ uint32_t smem_u32(const void* p) {
    uint32_t a;
    asm("{ .reg .u64 t; cvta.to.shared.u64 t, %1; cvt.u32.u64 %0, t; }"
        : "=r"(a) : "l"(p));
    return a;
}
__device__ __forceinline__ void ldmatrix_x4(uint32_t& r0, uint32_t& r1,
                                            uint32_t& r2, uint32_t& r3, uint32_t addr) {
    asm volatile("ldmatrix.sync.aligned.m8n8.x4.shared.b16 {%0,%1,%2,%3}, [%4];"
                 : "=r"(r0), "=r"(r1), "=r"(r2), "=r"(r3) : "r"(addr));
}
__device__ __forceinline__ void ldmatrix_x4_t(uint32_t& r0, uint32_t& r1,
                                              uint32_t& r2, uint32_t& r3, uint32_t addr) {
    asm volatile("ldmatrix.sync.aligned.m8n8.x4.trans.shared.b16 {%0,%1,%2,%3}, [%4];"
                 : "=r"(r0), "=r"(r1), "=r"(r2), "=r"(r3) : "r"(addr));
}
__device__ __forceinline__ void mma_f16(float* c, const uint32_t* a, const uint32_t* b) {
    asm volatile(
        "mma.sync.aligned.m16n8k16.row.col.f32.f16.f16.f32 "
        "{%0,%1,%2,%3}, {%4,%5,%6,%7}, {%8,%9}, {%0,%1,%2,%3};"
        : "+f"(c[0]), "+f"(c[1]), "+f"(c[2]), "+f"(c[3])
        : "r"(a[0]), "r"(a[1]), "r"(a[2]), "r"(a[3]), "r"(b[0]), "r"(b[1]));
}
#define CP16(dst, src) \
    asm volatile("cp.async.cg.shared.global [%0], [%1], 16;" :: "r"(dst), "l"(src))
#define CP16P(dst, src, pred) \
    asm volatile("cp.async.cg.shared.global [%0], [%1], 16, %2;" \
                 :: "r"(dst), "l"(src), "r"((pred) ? 16 : 0))
#define CP_COMMIT() asm volatile("cp.async.commit_group;" ::: "memory")
#define CP_WAIT(n)  asm volatile("cp.async.wait_group %0;" :: "n"(n) : "memory")

// pack two fp32 -> f16x2 (low = x0)
__device__ __forceinline__ uint32_t packh2(float x0, float x1) {
    uint32_t p;
    asm("cvt.rn.f16x2.f32 %0, %1, %2;" : "=r"(p) : "f"(x1), "f"(x0));
    return p;
}
// exact fp16 split of one value
__device__ __forceinline__ void splith1(float x, __half& h, __half& l) {
    h = __float2half_rn(x);
    l = __float2half_rn(x - __half2float(h));
}
// pair split -> packed hi / lo
__device__ __forceinline__ void splith2(float x0, float x1, uint32_t& hp, uint32_t& lp) {
    const __half h0 = __float2half_rn(x0), h1 = __float2half_rn(x1);
    hp = ((uint32_t)__half_as_ushort(h1) << 16) | (uint32_t)__half_as_ushort(h0);
    lp = packh2(x0 - __half2float(h0), x1 - __half2float(h1));
}
__device__ __forceinline__ float fexp2(float x) {
    float r;
    asm("ex2.approx.ftz.f32 %0, %1;" : "=f"(r) : "f"(x));
    return r;
}

// ---------------------------------------------------------------------------
// Prep: hidden fp32->fp16 (hi only) + all weight transpose+splits, one launch
// ---------------------------------------------------------------------------
constexpr int PREP_SPLIT_BLOCKS = NTOK * HIDN / 4 / 256;  // 10240
constexpr int PREP_TOTAL_BLOCKS = PREP_SPLIT_BLOCKS + 13200;

__global__ void prep_kernel(const float* __restrict__ hidden,
                            const float* __restrict__ wqa,
                            const float* __restrict__ wkva,
                            const float* __restrict__ wqb,
                            const float* __restrict__ wkvb,
                            const float* __restrict__ wo)
{
    __shared__ float tt[32][33];
    if (blockIdx.x < PREP_SPLIT_BLOCKS) {
        const int i = blockIdx.x * 256 + threadIdx.x;
        const float4 v = *(const float4*)&hidden[(size_t)i * 4];
        *(uint2*)&g_hid_h[(size_t)i * 4] =
            make_uint2(packh2(v.x, v.y), packh2(v.z, v.w));
        return;
    }
    const int bid = blockIdx.x - PREP_SPLIT_BLOCKS;
    const float* W; __half *Th, *Tl; int K, N, nx, t;
    if (bid < 1920)      { t = bid;        W=wqa;  Th=g_wqa_h;  Tl=g_wqa_l;  K=HIDN;    N=Q_RANK;  nx=24; }
    else if (bid < 2640) { t = bid-1920;   W=wkva; Th=g_wkva_h; Tl=g_wkva_l; K=HIDN;    N=CKV_D;   nx=9; }
    else if (bid < 5520) { t = bid-2640;   W=wqb;  Th=g_wqb_h;  Tl=g_wqb_l;  K=Q_RANK;  N=QD_ALL;  nx=120; }
    else if (bid < 6800) { t = bid-5520;   W=wkvb; Th=g_wkvb_h; Tl=g_wkvb_l; K=KV_RANK; N=KVD_ALL; nx=160; }
    else                 { t = bid-6800;   W=wo;   Th=g_wo_h;   Tl=g_wo_l;   K=HIDN;    N=OD_ALL;  nx=80; }
    const int n0 = (t % nx) * 32;
    const int k0 = (t / nx) * 32;

    const int tx = threadIdx.x & 31;
    const int ty = threadIdx.x >> 5;       // 0..7
#pragma unroll
    for (int j = 0; j < 4; j++)
        tt[ty + j * 8][tx] = W[(size_t)(k0 + ty + j * 8) * N + n0 + tx];
    __syncthreads();
#pragma unroll
    for (int j = 0; j < 4; j++) {
        const float v = tt[tx][ty + j * 8];
        __half h, l;
        splith1(v, h, l);
        const size_t o = (size_t)(n0 + ty + j * 8) * K + k0 + tx;
        Th[o] = h; Tl[o] = l;
    }
}

// ---------------------------------------------------------------------------
// Fused tensor GEMM (fp16, 2-product): C = A(hi) @ [Bt(hi)+Bt(lo)]^T
// Tile 128x128, BK=32, 256 threads (8 warps, 4x2), warp tile 32x64.
// ---------------------------------------------------------------------------
struct GemmDesc {
    const __half *Ah, *Bh, *Bl;
    float* C;
    __half *Ch, *Cl;     // Cl may be null (hi-only output)
    int N, K;
};

constexpr int GST      = 40;
constexpr int G_OFF_A  = 0;
constexpr int G_OFF_BH = 128 * GST * 2;      // 10240
constexpr int G_OFF_BL = 2 * 128 * GST * 2;  // 20480
constexpr int G_STAGE  = 3 * 128 * GST * 2;  // 30720
constexpr int G_SMEM   = 2 * G_STAGE;        // 61440

template<bool SPLIT_OUT>
__global__ __launch_bounds__(256, 2)
void tgemm2_kernel(GemmDesc d0, GemmDesc d1, int xsplit)
{
    extern __shared__ char smc[];
    const uint32_t sb0 = smem_u32(smc);

    const bool second = blockIdx.x >= (unsigned)xsplit;
    const GemmDesc d = second ? d1 : d0;
    const int bx = second ? (blockIdx.x - xsplit) : blockIdx.x;
    const int N = d.N, K = d.K;

    const int tid  = threadIdx.x;
    const int warp = tid >> 5;
    const int lane = tid & 31;
    const int wr   = warp >> 1;
    const int wc   = warp & 1;
    const int row0 = blockIdx.y * 128;
    const int col0 = bx * 128;

    auto issue_chunk = [&](int ch, int st) {
        const int k0 = ch << 5;
        const uint32_t sb = sb0 + st * G_STAGE;
#pragma unroll
        for (int i = 0; i < 2; i++) {
            const int s  = tid + i * 256;
            const int r  = s >> 2;
            const int kc = (s & 3) * 8;
            const uint32_t dd = r * (GST * 2) + kc * 2;
            CP16(sb + G_OFF_A + dd, &d.Ah[(size_t)(row0 + r) * K + k0 + kc]);
            const int n = col0 + r;
            const bool pr = n < N;
            const size_t bo = (size_t)(pr ? n : 0) * K + k0 + kc;
            CP16P(sb + G_OFF_BH + dd, &d.Bh[bo], pr);
            CP16P(sb + G_OFF_BL + dd, &d.Bl[bo], pr);
        }
    };

    float acc[2][8][4];
#pragma unroll
    for (int mf = 0; mf < 2; mf++)
#pragma unroll
        for (int nf = 0; nf < 8; nf++)
#pragma unroll
            for (int r = 0; r < 4; r++) acc[mf][nf][r] = 0.f;

    const int a_row = (lane & 15);
    const int a_col = (lane >> 4) * 8;
    const int b_row = (lane >> 4) * 8 + (lane & 7);
    const int b_col = ((lane >> 3) & 1) * 8;

    auto compute_stage = [&](int st) {
        const uint32_t Ah = sb0 + st * G_STAGE + G_OFF_A;
        const uint32_t Bh = sb0 + st * G_STAGE + G_OFF_BH;
        const uint32_t Bl = sb0 + st * G_STAGE + G_OFF_BL;
#pragma unroll
        for (int ks = 0; ks < 32; ks += 16) {
            uint32_t ah[2][4];
#pragma unroll
            for (int mf = 0; mf < 2; mf++) {
                const uint32_t off = ((wr * 32 + mf * 16 + a_row) * GST + ks + a_col) * 2;
                ldmatrix_x4(ah[mf][0], ah[mf][1], ah[mf][2], ah[mf][3], Ah + off);
            }
#pragma unroll
            for (int np = 0; np < 4; np++) {
                uint32_t bh[4], bl[4];
                const uint32_t off = ((wc * 64 + np * 16 + b_row) * GST + ks + b_col) * 2;
                ldmatrix_x4(bh[0], bh[1], bh[2], bh[3], Bh + off);
                ldmatrix_x4(bl[0], bl[1], bl[2], bl[3], Bl + off);
#pragma unroll
                for (int mf = 0; mf < 2; mf++) {
                    mma_f16(acc[mf][np*2],   ah[mf], bh + 0);
                    mma_f16(acc[mf][np*2],   ah[mf], bl + 0);
                    mma_f16(acc[mf][np*2+1], ah[mf], bh + 2);
                    mma_f16(acc[mf][np*2+1], ah[mf], bl + 2);
                }
            }
        }
    };

    const int nch = K >> 5;
    issue_chunk(0, 0);
    CP_COMMIT();
    for (int ch = 0; ch < nch; ch++) {
        if (ch + 1 < nch) {
            issue_chunk(ch + 1, (ch + 1) & 1);
            CP_COMMIT();
            CP_WAIT(1);
        } else {
            CP_WAIT(0);
        }
        __syncthreads();
        compute_stage(ch & 1);
        __syncthreads();
    }

#pragma unroll
    for (int mf = 0; mf < 2; mf++) {
        const int r0 = row0 + wr * 32 + mf * 16 + (lane >> 2);
#pragma unroll
        for (int nf = 0; nf < 8; nf++) {
            const int c = col0 + wc * 64 + nf * 8 + (lane & 3) * 2;
            if (c < N) {
                if (SPLIT_OUT) {
                    if (d.Cl) {
                        uint32_t hp, lp;
                        splith2(acc[mf][nf][0], acc[mf][nf][1], hp, lp);
                        *(uint32_t*)&d.Ch[(size_t)r0 * N + c] = hp;
                        *(uint32_t*)&d.Cl[(size_t)r0 * N + c] = lp;
                        splith2(acc[mf][nf][2], acc[mf][nf][3], hp, lp);
                        *(uint32_t*)&d.Ch[(size_t)(r0 + 8) * N + c] = hp;
                        *(uint32_t*)&d.Cl[(size_t)(r0 + 8) * N + c] = lp;
                    } else {
                        *(uint32_t*)&d.Ch[(size_t)r0 * N + c] =
                            packh2(acc[mf][nf][0], acc[mf][nf][1]);
                        *(uint32_t*)&d.Ch[(size_t)(r0 + 8) * N + c] =
                            packh2(acc[mf][nf][2], acc[mf][nf][3]);
                    }
                } else {
                    *(float2*)&d.C[(size_t)r0 * N + c] =
                        make_float2(acc[mf][nf][0], acc[mf][nf][1]);
                    *(float2*)&d.C[(size_t)(r0 + 8) * N + c] =
                        make_float2(acc[mf][nf][2], acc[mf][nf][3]);
                }
            }
        }
    }
}

// ---------------------------------------------------------------------------
// Both RMSNorms in one launch -> fp16 hi plane
// ---------------------------------------------------------------------------
__global__ void rmsnorm2_kernel(const float* __restrict__ qln,
                                const float* __restrict__ kvln)
{
    const float* in; const float* w; __half* oh;
    int dim, istride, row;
    if (blockIdx.x < NTOK) {
        row = blockIdx.x;
        in = g_qa; w = qln; oh = g_qan_h;
        dim = Q_RANK; istride = Q_RANK;
    } else {
        row = blockIdx.x - NTOK;
        in = g_ckv; w = kvln; oh = g_kvn_h;
        dim = KV_RANK; istride = CKV_D;
    }
    const float* x = in + (size_t)row * istride;
    float ss = 0.f;
    for (int i = threadIdx.x; i < dim; i += blockDim.x) { float v = x[i]; ss += v * v; }
#pragma unroll
    for (int o = 16; o > 0; o >>= 1) ss += __shfl_xor_sync(0xffffffffu, ss, o);
    __shared__ float sh[8];
    __shared__ float s_inv;
    if ((threadIdx.x & 31) == 0) sh[threadIdx.x >> 5] = ss;
    __syncthreads();
    if (threadIdx.x == 0) {
        float t = 0.f;
        const int nw = blockDim.x >> 5;
        for (int i = 0; i < nw; i++) t += sh[i];
        s_inv = rsqrtf(t / (float)dim + 1e-5f);
    }
    __syncthreads();
    const float inv = s_inv;
    for (int i = threadIdx.x; i < dim; i += blockDim.x)
        oh[(size_t)row * dim + i] = __float2half_rn(x[i] * inv * w[i]);
}

// ---------------------------------------------------------------------------
// RoPE: q hi plane in-place (rope dims), ckv tail -> krot hi/lo planes
// ---------------------------------------------------------------------------
__global__ void rope_kernel(__half* __restrict__ qh,
                            const float* __restrict__ ckv,
                            __half* __restrict__ krh, __half* __restrict__ krl,
                            const float* __restrict__ cosb, const float* __restrict__ sinb)
{
    const int token = blockIdx.x;
    const int s = token & (SEQ - 1);
    for (int i = threadIdx.x; i < (NHEAD + 1) * 32; i += blockDim.x) {
        const int h = i >> 5;
        const int d = i & 31;
        const float c  = cosb[s * ROPE_D + d];
        const float sn = sinb[s * ROPE_D + d];
        if (h < NHEAD) {
            const size_t base = (size_t)token * QD_ALL + h * QK_D + NOPE_D;
            const size_t pi   = base + ((d < 16) ? d + 16 : d - 16);
            const float x  = __half2float(qh[base + d]);
            float pr = __half2float(qh[pi]);
            if (d < 16) pr = -pr;
            __syncwarp();
            qh[base + d] = __float2half_rn(x * c + pr * sn);
        } else {
            const float* kb = ckv + (size_t)token * CKV_D + KV_RANK;
            const float x  = kb[d];
            const float pr = (d < 16) ? -kb[d + 16] : kb[d - 16];
            __half hh, ll;
            splith1(x * c + pr * sn, hh, ll);
            krh[(size_t)token * ROPE_D + d] = hh;
            krl[(size_t)token * ROPE_D + d] = ll;
        }
    }
}

// ---------------------------------------------------------------------------
// Flash attention, fp16 2-product. BQ=128, BK=64, 256 threads, 8 warps.
// Q: hi only. K/V: hi+lo. P: fp16 (no split). Largest-qt-first; K/V prefetch.
// ---------------------------------------------------------------------------
constexpr int AQ_ST = 104;
constexpr int AV_ST = 72;
constexpr int A_QT  = 128 * AQ_ST;
constexpr int A_KT  = 64 * AQ_ST;
constexpr int A_VT  = 64 * AV_ST;
constexpr int ATTN_SMEM = (A_QT + 2*A_KT + 2*A_VT) * (int)sizeof(__half);  // 71680

__global__ __launch_bounds__(256, 2)
void attn_mma_kernel(const __half* __restrict__ qh,
                     const __half* __restrict__ kvh, const __half* __restrict__ kvl,
                     const __half* __restrict__ krh, const __half* __restrict__ krl,
                     __half* __restrict__ oh)
{
    extern __shared__ __half smh[];
    const uint32_t uQ  = smem_u32(smh);
    const uint32_t uKh = uQ  + A_QT * 2;
    const uint32_t uKl = uKh + A_KT * 2;
    const uint32_t uVh = uKl + A_KT * 2;
    const uint32_t uVl = uVh + A_VT * 2;

    const int bh = blockIdx.y;
    const int b  = bh / NHEAD;
    const int h  = bh % NHEAD;
    const int qt = (SEQ / 128 - 1) - blockIdx.x;   // largest work first
    const int q0 = qt * 128;
    const int tid  = threadIdx.x;
    const int warp = tid >> 5;
    const int lane = tid & 31;
    const int gr   = lane >> 2;
    const int qd   = lane & 3;
    const size_t tok0 = (size_t)b * SEQ;

    const int a_row = (lane & 15);
    const int a_col = (lane >> 4) * 8;
    const int b_row = (lane >> 4) * 8 + (lane & 7);
    const int b_col = ((lane >> 3) & 1) * 8;
    const int v_row = (lane & 15);
    const int v_col = (lane >> 4) * 8;

    auto issue_k = [&](int kt) {
        const int k0 = kt * 64;
#pragma unroll
        for (int i = 0; i < 3; i++) {
            const int s = tid + i * 256;
            if (s < 512) {
                const int r = s >> 3, c8 = (s & 7) * 8;
                const size_t src = (tok0 + k0 + r) * KVD_ALL + h * 128 + c8;
                CP16(uKh + (r * AQ_ST + c8) * 2, &kvh[src]);
                CP16(uKl + (r * AQ_ST + c8) * 2, &kvl[src]);
            } else {
                const int t = s - 512;
                const int r = t >> 2, c8 = 64 + (t & 3) * 8;
                const size_t src = (tok0 + k0 + r) * ROPE_D + (c8 - 64);
                CP16(uKh + (r * AQ_ST + c8) * 2, &krh[src]);
                CP16(uKl + (r * AQ_ST + c8) * 2, &krl[src]);
            }
        }
    };
    auto issue_v = [&](int kt) {
        const int k0 = kt * 64;
#pragma unroll
        for (int i = 0; i < 2; i++) {
            const int s = tid + i * 256;
            const int r = s >> 3;
            const int c8 = (s & 7) * 8;
            const size_t src = (tok0 + k0 + r) * KVD_ALL + h * 128 + 64 + c8;
            CP16(uVh + (r * AV_ST + c8) * 2, &kvh[src]);
            CP16(uVl + (r * AV_ST + c8) * 2, &kvl[src]);
        }
    };

    // ---- Q tile copy (128 x 96, hi plane) ----
#pragma unroll
    for (int i = 0; i < 6; i++) {
        const int s  = tid + i * 256;        // 0..1535
        const int r  = s / 12;
        const int c8 = (s - r * 12) * 8;
        CP16(uQ + (r * AQ_ST + c8) * 2, &qh[(tok0 + q0 + r) * QD_ALL + h * QK_D + c8]);
    }
    CP_COMMIT();          // group: Q
    issue_k(0);
    CP_COMMIT();          // group: K0
    issue_v(0);
    CP_COMMIT();          // group: V0

    float oacc[8][4];
#pragma unroll
    for (int nf = 0; nf < 8; nf++)
#pragma unroll
        for (int r = 0; r < 4; r++) oacc[nf][r] = 0.f;
    float mA = -1e30f, mB = -1e30f, lA = 0.f, lB = 0.f;

    const int q0w  = q0 + warp * 16;
    const int rowA = q0w + gr;
    const int rowB = rowA + 8;
    const int nkt  = 2 * qt + 2;

    for (int kt = 0; kt < nkt; kt++) {
        const int k0 = kt * 64;

        CP_WAIT(1);            // K_t (and Q) landed; V_t may be in flight
        __syncthreads();

        // ---- S = Q @ K^T (2-product) ----
        float sa[8][4];
#pragma unroll
        for (int nf = 0; nf < 8; nf++)
#pragma unroll
            for (int r = 0; r < 4; r++) sa[nf][r] = 0.f;

#pragma unroll
        for (int ks = 0; ks < 96; ks += 16) {
            uint32_t ah[4];
            const uint32_t aoff = ((warp * 16 + a_row) * AQ_ST + ks + a_col) * 2;
            ldmatrix_x4(ah[0], ah[1], ah[2], ah[3], uQ + aoff);
#pragma unroll
            for (int np = 0; np < 4; np++) {
                uint32_t bhf[4], blf[4];
                const uint32_t boff = ((np * 16 + b_row) * AQ_ST + ks + b_col) * 2;
                ldmatrix_x4(bhf[0], bhf[1], bhf[2], bhf[3], uKh + boff);
                ldmatrix_x4(blf[0], blf[1], blf[2], blf[3], uKl + boff);
                mma_f16(sa[np*2],   ah, bhf + 0);
                mma_f16(sa[np*2],   ah, blf + 0);
                mma_f16(sa[np*2+1], ah, bhf + 2);
                mma_f16(sa[np*2+1], ah, blf + 2);
            }
        }
        __syncthreads();       // all warps done reading K smem
        if (kt + 1 < nkt) issue_k(kt + 1);
        CP_COMMIT();           // group K_{t+1} (possibly empty)

        // ---- scale + mask ----
#pragma unroll
        for (int nf = 0; nf < 8; nf++)
#pragma unroll
            for (int r = 0; r < 4; r++) sa[nf][r] *= SC2;
        if (k0 + 63 > q0w) {
#pragma unroll
            for (int nf = 0; nf < 8; nf++) {
                const int col = k0 + nf * 8 + qd * 2;
                if (col     > rowA) sa[nf][0] = -1e30f;
                if (col + 1 > rowA) sa[nf][1] = -1e30f;
                if (col     > rowB) sa[nf][2] = -1e30f;
                if (col + 1 > rowB) sa[nf][3] = -1e30f;
            }
        }

        // ---- online softmax ----
        float mxA = -1e30f, mxB = -1e30f;
#pragma unroll
        for (int nf = 0; nf < 8; nf++) {
            mxA = fmaxf(mxA, fmaxf(sa[nf][0], sa[nf][1]));
            mxB = fmaxf(mxB, fmaxf(sa[nf][2], sa[nf][3]));
        }
        mxA = fmaxf(mxA, __shfl_xor_sync(0xffffffffu, mxA, 1));
        mxA = fmaxf(mxA, __shfl_xor_sync(0xffffffffu, mxA, 2));
        mxB = fmaxf(mxB, __shfl_xor_sync(0xffffffffu, mxB, 1));
        mxB = fmaxf(mxB, __shfl_xor_sync(0xffffffffu, mxB, 2));
        const float mnA = fmaxf(mA, mxA);
        const float mnB = fmaxf(mB, mxB);
        const float alA = fexp2(mA - mnA);
        const float alB = fexp2(mB - mnB);
        mA = mnA; mB = mnB;

        float rsA = 0.f, rsB = 0.f;
#pragma unroll
        for (int nf = 0; nf < 8; nf++) {
            sa[nf][0] = fexp2(sa[nf][0] - mnA); rsA += sa[nf][0];
            sa[nf][1] = fexp2(sa[nf][1] - mnA); rsA += sa[nf][1];
            sa[nf][2] = fexp2(sa[nf][2] - mnB); rsB += sa[nf][2];
            sa[nf][3] = fexp2(sa[nf][3] - mnB); rsB += sa[nf][3];
        }
        rsA += __shfl_xor_sync(0xffffffffu, rsA, 1);
        rsA += __shfl_xor_sync(0xffffffffu, rsA, 2);
        rsB += __shfl_xor_sync(0xffffffffu, rsB, 1);
        rsB += __shfl_xor_sync(0xffffffffu, rsB, 2);
        lA = lA * alA + rsA;
        lB = lB * alB + rsB;
#pragma unroll
        for (int nf = 0; nf < 8; nf++) {
            oacc[nf][0] *= alA; oacc[nf][1] *= alA;
            oacc[nf][2] *= alB; oacc[nf][3] *= alB;
        }

        CP_WAIT(1);            // V_t landed; K_{t+1} may be in flight
        __syncthreads();

        // ---- O += P @ V  (P fp16, no split; V hi+lo) ----
#pragma unroll
        for (int t = 0; t < 4; t++) {
            uint32_t ph[4];
            ph[0] = packh2(sa[2*t][0],   sa[2*t][1]);
            ph[1] = packh2(sa[2*t][2],   sa[2*t][3]);
            ph[2] = packh2(sa[2*t+1][0], sa[2*t+1][1]);
            ph[3] = packh2(sa[2*t+1][2], sa[2*t+1][3]);
#pragma unroll
            for (int np = 0; np < 4; np++) {
                uint32_t vhf[4], vlf[4];
                const uint32_t voff = ((t * 16 + v_row) * AV_ST + np * 16 + v_col) * 2;
                ldmatrix_x4_t(vhf[0], vhf[1], vhf[2], vhf[3], uVh + voff);
                ldmatrix_x4_t(vlf[0], vlf[1], vlf[2], vlf[3], uVl + voff);
                mma_f16(oacc[np*2],   ph, vhf + 0);
                mma_f16(oacc[np*2],   ph, vlf + 0);
                mma_f16(oacc[np*2+1], ph, vhf + 2);
                mma_f16(oacc[np*2+1], ph, vlf + 2);
            }
        }
        __syncthreads();       // all warps done reading V smem
        if (kt + 1 < nkt) issue_v(kt + 1);
        CP_COMMIT();           // group V_{t+1} (possibly empty)
    }

    // ---- finalize + write hi plane ----
    const float invA = 1.f / lA;
    const float invB = 1.f / lB;
#pragma unroll
    for (int nf = 0; nf < 8; nf++) {
        const int col = h * V_D + nf * 8 + qd * 2;
        *(uint32_t*)&oh[(tok0 + rowA) * (size_t)OD_ALL + col] =
            packh2(oacc[nf][0] * invA, oacc[nf][1] * invA);
        *(uint32_t*)&oh[(tok0 + rowB) * (size_t)OD_ALL + col] =
            packh2(oacc[nf][2] * invB, oacc[nf][3] * invB);
    }
}

// ---------------------------------------------------------------------------
// Launch
// ---------------------------------------------------------------------------
extern "C" void kernel_launch(void* const* d_in, const int* in_sizes, int n_in,
                              void* d_out, int out_size)
{
    const float* hidden = (const float*)d_in[0];
    const float* cosb   = (const float*)d_in[1];
    const float* sinb   = (const float*)d_in[2];
    const float* wq_a   = (const float*)d_in[3];
    const float* q_ln   = (const float*)d_in[4];
    const float* wq_b   = (const float*)d_in[5];
    const float* wkv_a  = (const float*)d_in[6];
    const float* kv_ln  = (const float*)d_in[7];
    const float* wkv_b  = (const float*)d_in[8];
    const float* wo     = (const float*)d_in[9];
    float* out = (float*)d_out;

    __half *hidh, *wqah, *wqal, *wkvah, *wkval, *wqbh, *wqbl,
           *wkvbh, *wkvbl, *woh, *wol, *qanh, *kvnh,
           *qhp, *kvhp, *kvlp, *krhp, *krlp, *ath;
    float *qa, *ckv;
    cudaGetSymbolAddress((void**)&hidh,  g_hid_h);
    cudaGetSymbolAddress((void**)&wqah,  g_wqa_h);  cudaGetSymbolAddress((void**)&wqal,  g_wqa_l);
    cudaGetSymbolAddress((void**)&wkvah, g_wkva_h); cudaGetSymbolAddress((void**)&wkval, g_wkva_l);
    cudaGetSymbolAddress((void**)&wqbh,  g_wqb_h);  cudaGetSymbolAddress((void**)&wqbl,  g_wqb_l);
    cudaGetSymbolAddress((void**)&wkvbh, g_wkvb_h); cudaGetSymbolAddress((void**)&wkvbl, g_wkvb_l);
    cudaGetSymbolAddress((void**)&woh,   g_wo_h);   cudaGetSymbolAddress((void**)&wol,   g_wo_l);
    cudaGetSymbolAddress((void**)&qa,    g_qa);     cudaGetSymbolAddress((void**)&ckv,   g_ckv);
    cudaGetSymbolAddress((void**)&qanh,  g_qan_h);  cudaGetSymbolAddress((void**)&kvnh,  g_kvn_h);
    cudaGetSymbolAddress((void**)&qhp,   g_q_h);
    cudaGetSymbolAddress((void**)&kvhp,  g_kv_h);   cudaGetSymbolAddress((void**)&kvlp,  g_kv_l);
    cudaGetSymbolAddress((void**)&krhp,  g_kr_h);   cudaGetSymbolAddress((void**)&krlp,  g_kr_l);
    cudaGetSymbolAddress((void**)&ath,   g_at_h);

    cudaFuncSetAttribute(tgemm2_kernel<false>, cudaFuncAttributeMaxDynamicSharedMemorySize, G_SMEM);
    cudaFuncSetAttribute(tgemm2_kernel<true>,  cudaFuncAttributeMaxDynamicSharedMemorySize, G_SMEM);
    cudaFuncSetAttribute(attn_mma_kernel,      cudaFuncAttributeMaxDynamicSharedMemorySize, ATTN_SMEM);

    const dim3 blk(256);
    const int mt = NTOK / 128;

    // 0: prep (hidden convert + all weight transpose/splits)
    prep_kernel<<<PREP_TOTAL_BLOCKS, 256>>>(hidden, wq_a, wkv_a, wq_b, wkv_b, wo);

    // 1: fused GEMM pair: qa = hid@wqa  |  ckv = hid@wkva   (fp32 out)
    {
        GemmDesc d0 = { hidh, wqah,  wqal,  qa,  nullptr, nullptr, Q_RANK, HIDN };
        GemmDesc d1 = { hidh, wkvah, wkval, ckv, nullptr, nullptr, CKV_D,  HIDN };
        tgemm2_kernel<false><<<dim3(6 + 3, mt), blk, G_SMEM>>>(d0, d1, 6);
    }
    // 2: both rmsnorms -> fp16 hi planes
    rmsnorm2_kernel<<<2 * NTOK, 256>>>(q_ln, kv_ln);
    // 3: fused GEMM pair: q = qan@wqb (hi out) | kv = kvn@wkvb (hi+lo out)
    {
        GemmDesc d0 = { qanh, wqbh,  wqbl,  nullptr, qhp,  nullptr, QD_ALL,  Q_RANK };
        GemmDesc d1 = { kvnh, wkvbh, wkvbl, nullptr, kvhp, kvlp,    KVD_ALL, KV_RANK };
        tgemm2_kernel<true><<<dim3(30 + 40, mt), blk, G_SMEM>>>(d0, d1, 30);
    }
    // 4: rope
    rope_kernel<<<NTOK, 256>>>(qhp, ckv, krhp, krlp, cosb, sinb);
    // 5: attention (largest qt first)
    attn_mma_kernel<<<dim3(SEQ / 128, 2 * NHEAD), blk, ATTN_SMEM>>>(
        qhp, kvhp, kvlp, krhp, krlp, ath);
    // 6: out = attn @ wo
    {
        GemmDesc d0 = { ath, woh, wol, out, nullptr, nullptr, HIDN, OD_ALL };
        tgemm2_kernel<false><<<dim3(HIDN / 128, mt), blk, G_SMEM>>>(d0, d0, HIDN / 128);
    }
}